// round 1
// baseline (speedup 1.0000x reference)
#include <cuda_runtime.h>
#include <cuda_bf16.h>
#include <cstdint>

// Problem constants
#define Bz 2
#define Tz 2048
#define Cz 768
#define Hz 12
#define Dz 64
#define BHz (Bz*Hz)        // 24
#define Mz (Bz*Tz)         // 4096

// Scratch (static device allocs — no cudaMalloc allowed)
__device__ float g_tmp[(size_t)Mz * 1536];        // [4096,1536] k-chunk | v-chunk
__device__ float g_K[(size_t)BHz * Tz * Dz];      // [24,2048,64]
__device__ float g_Q[(size_t)BHz * Tz * Dz];
__device__ float g_V[(size_t)BHz * Tz * Dz];
__device__ float g_att[(size_t)Mz * Cz];          // [4096,768] attention out (B,T,C layout)

// ---------------------------------------------------------------------------
// SGEMM: C[M,N] = A[M,K] @ Bmat[K, ldb] (logical col n -> physical col n (+768 if n>=nsplit))
// 128x128 tile, BK=16, 256 threads, 8x8 per thread. All dims divisible.
// ---------------------------------------------------------------------------
#define GBM 128
#define GBN 128
#define GBK 16

__global__ __launch_bounds__(256) void sgemm_kernel(
    const float* __restrict__ A, const float* __restrict__ Bmat,
    float* __restrict__ Cmat, const float* __restrict__ bias,
    int M, int N, int K, int ldb, int nsplit)
{
    __shared__ float As[GBK][GBM + 1];
    __shared__ float Bs[GBK][GBN];

    int tid  = threadIdx.x;
    int bcol = blockIdx.x;
    int brow = blockIdx.y;
    int tx = tid & 15;   // col group
    int ty = tid >> 4;   // row group

    float acc[8][8];
    #pragma unroll
    for (int i = 0; i < 8; i++)
        #pragma unroll
        for (int j = 0; j < 8; j++) acc[i][j] = 0.f;

    const float* Ablk = A + (size_t)brow * GBM * K;
    int ncolbase = bcol * GBN;
    int physbase = (ncolbase >= nsplit) ? ncolbase + 768 : ncolbase;

    for (int kt = 0; kt < K; kt += GBK) {
        // Load A tile (128 rows x 16 k), transposed into As
        #pragma unroll
        for (int it = 0; it < 2; it++) {
            int idx = tid + it * 256;            // 0..511
            int r  = idx >> 2;                   // 0..127
            int c4 = (idx & 3) * 4;              // 0,4,8,12
            float4 v = *reinterpret_cast<const float4*>(Ablk + (size_t)r * K + kt + c4);
            As[c4 + 0][r] = v.x;
            As[c4 + 1][r] = v.y;
            As[c4 + 2][r] = v.z;
            As[c4 + 3][r] = v.w;
        }
        // Load B tile (16 k x 128 cols)
        #pragma unroll
        for (int it = 0; it < 2; it++) {
            int idx = tid + it * 256;
            int r  = idx >> 5;                   // 0..15
            int c4 = (idx & 31) * 4;             // 0..124
            float4 v = *reinterpret_cast<const float4*>(
                Bmat + (size_t)(kt + r) * ldb + physbase + c4);
            *reinterpret_cast<float4*>(&Bs[r][c4]) = v;
        }
        __syncthreads();

        #pragma unroll
        for (int k = 0; k < GBK; k++) {
            float ra[8], rb[8];
            #pragma unroll
            for (int i = 0; i < 8; i++) ra[i] = As[k][ty * 8 + i];
            #pragma unroll
            for (int j = 0; j < 8; j++) rb[j] = Bs[k][tx * 8 + j];
            #pragma unroll
            for (int i = 0; i < 8; i++)
                #pragma unroll
                for (int j = 0; j < 8; j++)
                    acc[i][j] += ra[i] * rb[j];
        }
        __syncthreads();
    }

    #pragma unroll
    for (int i = 0; i < 8; i++) {
        int row = brow * GBM + ty * 8 + i;
        #pragma unroll
        for (int j = 0; j < 8; j++) {
            int col = ncolbase + tx * 8 + j;
            float v = acc[i][j];
            if (bias) v += bias[col];
            Cmat[(size_t)row * N + col] = v;
        }
    }
}

// ---------------------------------------------------------------------------
// RoPE + transpose to head layout.
// tmp: [4096,1536], cols [0:768)=k chunk, [768:1536)=v chunk.
// K = rope(k), Q = rope(v)  (faithful to the reference bug), V = v.
// Output layout [BH, T, D].
// ---------------------------------------------------------------------------
__global__ __launch_bounds__(256) void rope_kernel(
    const float* __restrict__ tmp,
    const float* __restrict__ cosb, const float* __restrict__ sinb,
    float* __restrict__ Ko, float* __restrict__ Qo, float* __restrict__ Vo)
{
    int idx = blockIdx.x * blockDim.x + threadIdx.x;  // over 4096*12*32
    if (idx >= Mz * Hz * (Dz / 2)) return;
    int i = idx & 31;                // rotation pair index 0..31
    int h = (idx >> 5) % Hz;
    int m = idx / (Hz * 32);         // b*T + t
    int b = m >> 11;
    int t = m & (Tz - 1);

    const float* row = tmp + (size_t)m * 1536;
    float kr = row[h * Dz + 2 * i];
    float ki = row[h * Dz + 2 * i + 1];
    float vr = row[768 + h * Dz + 2 * i];
    float vi = row[768 + h * Dz + 2 * i + 1];

    float c = cosb[t * 32 + i];
    float s = sinb[t * 32 + i];

    size_t o = ((size_t)(b * Hz + h) * Tz + t) * Dz + 2 * i;
    Ko[o]     = kr * c - ki * s;
    Ko[o + 1] = kr * s + ki * c;
    Qo[o]     = vr * c - vi * s;
    Qo[o + 1] = vr * s + vi * c;
    Vo[o]     = vr;
    Vo[o + 1] = vi;
}

// ---------------------------------------------------------------------------
// Causal flash attention, fp32, online softmax with deferred rescale.
// grid: (T/64, BH). block: 256 threads. Each row handled by 4 threads
// (16 dims each); scores reduced across the 4 lanes with shfl.
// Writes output already in [B,T,C] layout (g_att) for the proj GEMM.
// ---------------------------------------------------------------------------
__global__ __launch_bounds__(256) void flash_kernel(
    const float* __restrict__ Q, const float* __restrict__ K,
    const float* __restrict__ V, float* __restrict__ O)
{
    __shared__ float Ks[64][64];
    __shared__ float Vs[64][64];

    int tid  = threadIdx.x;
    int qt   = blockIdx.x;
    int bh   = blockIdx.y;
    int row  = tid >> 2;       // 0..63
    int part = tid & 3;        // 16-dim slice

    const float* Qb = Q + (size_t)bh * Tz * Dz;
    const float* Kb = K + (size_t)bh * Tz * Dz;
    const float* Vb = V + (size_t)bh * Tz * Dz;

    int qi = qt * 64 + row;

    float qf[16];
    {
        const float4* qsrc = reinterpret_cast<const float4*>(
            Qb + (size_t)qi * Dz + part * 16);
        const float scale = 0.125f;  // D^-0.5
        #pragma unroll
        for (int i = 0; i < 4; i++) {
            float4 v = qsrc[i];
            qf[4 * i + 0] = v.x * scale;
            qf[4 * i + 1] = v.y * scale;
            qf[4 * i + 2] = v.z * scale;
            qf[4 * i + 3] = v.w * scale;
        }
    }

    float acc[16];
    #pragma unroll
    for (int i = 0; i < 16; i++) acc[i] = 0.f;
    float m = -1e30f, l = 0.f;

    for (int jt = 0; jt <= qt; jt++) {
        #pragma unroll
        for (int it = 0; it < 4; it++) {
            int idx = tid + it * 256;     // 0..1023
            int r  = idx >> 4;            // 0..63
            int c4 = (idx & 15) * 4;      // 0..60
            size_t goff = (size_t)(jt * 64 + r) * Dz + c4;
            *reinterpret_cast<float4*>(&Ks[r][c4]) =
                *reinterpret_cast<const float4*>(Kb + goff);
            *reinterpret_cast<float4*>(&Vs[r][c4]) =
                *reinterpret_cast<const float4*>(Vb + goff);
        }
        __syncthreads();

        bool diag = (jt == qt);
        #pragma unroll 2
        for (int j = 0; j < 64; j++) {
            float s = 0.f;
            const float* krow = &Ks[j][part * 16];
            #pragma unroll
            for (int i = 0; i < 16; i++) s += qf[i] * krow[i];
            s += __shfl_xor_sync(0xffffffffu, s, 1);
            s += __shfl_xor_sync(0xffffffffu, s, 2);
            if (diag && j > row) s = -1e30f;

            if (s > m) {  // rare: rescale only on new max
                float corr = __expf(m - s);
                m = s;
                l *= corr;
                #pragma unroll
                for (int i = 0; i < 16; i++) acc[i] *= corr;
            }
            float p = __expf(s - m);
            l += p;
            const float* vrow = &Vs[j][part * 16];
            #pragma unroll
            for (int i = 0; i < 16; i++) acc[i] += p * vrow[i];
        }
        __syncthreads();
    }

    float inv = 1.f / l;
    int b = bh / Hz, h = bh % Hz;
    float* orow = O + ((size_t)(b * Tz + qi)) * Cz + h * Dz + part * 16;
    #pragma unroll
    for (int i = 0; i < 16; i++) orow[i] = acc[i] * inv;
}

// ---------------------------------------------------------------------------
// kernel_launch
// Inputs: [0]=x [B,T,C] f32, [1]=rope_cos [T,32], [2]=rope_sin [T,32],
//         [3]=W_att [C,3C], [4]=W_proj [C,C], [5]=b_proj [C]
// Output: [B,T,C] f32
// ---------------------------------------------------------------------------
extern "C" void kernel_launch(void* const* d_in, const int* in_sizes, int n_in,
                              void* d_out, int out_size)
{
    const float* x      = (const float*)d_in[0];
    const float* cosb   = (const float*)d_in[1];
    const float* sinb   = (const float*)d_in[2];
    const float* W_att  = (const float*)d_in[3];
    const float* W_proj = (const float*)d_in[4];
    const float* b_proj = (const float*)d_in[5];
    float* out = (float*)d_out;

    float *tmp, *Kp, *Qp, *Vp, *att;
    cudaGetSymbolAddress((void**)&tmp, g_tmp);
    cudaGetSymbolAddress((void**)&Kp,  g_K);
    cudaGetSymbolAddress((void**)&Qp,  g_Q);
    cudaGetSymbolAddress((void**)&Vp,  g_V);
    cudaGetSymbolAddress((void**)&att, g_att);

    // 1) QKV GEMM (only k-chunk and v-chunk; q-chunk of W_att is dead code)
    //    logical N=1536; cols >= 768 map to physical cols +768 (the v chunk).
    sgemm_kernel<<<dim3(1536 / GBN, Mz / GBM), 256>>>(
        x, W_att, tmp, nullptr, Mz, 1536, Cz, 3 * Cz, 768);

    // 2) RoPE + transpose to [BH,T,D]
    {
        int total = Mz * Hz * (Dz / 2);
        rope_kernel<<<(total + 255) / 256, 256>>>(tmp, cosb, sinb, Kp, Qp, Vp);
    }

    // 3) Causal flash attention -> g_att in [B,T,C] layout
    flash_kernel<<<dim3(Tz / 64, BHz), 256>>>(Qp, Kp, Vp, att);

    // 4) Output projection + bias -> d_out
    sgemm_kernel<<<dim3(Cz / GBN, Mz / GBM), 256>>>(
        att, W_proj, out, b_proj, Mz, Cz, Cz, Cz, 1 << 30);
}

// round 2
// speedup vs baseline: 2.3543x; 2.3543x over previous
#include <cuda_runtime.h>
#include <cuda_bf16.h>
#include <cstdint>

// Problem constants
#define Bz 2
#define Tz 2048
#define Cz 768
#define Hz 12
#define Dz 64
#define BHz (Bz*Hz)        // 24
#define Mz (Bz*Tz)         // 4096

// Scratch (static device allocs — no cudaMalloc allowed)
__device__ float g_tmp[(size_t)Mz * 1536];        // [4096,1536] k-chunk | v-chunk
__device__ float g_K[(size_t)BHz * Tz * Dz];      // [24,2048,64]
__device__ float g_Q[(size_t)BHz * Tz * Dz];
__device__ float g_V[(size_t)BHz * Tz * Dz];
__device__ float g_att[(size_t)Mz * Cz];          // [4096,768] attention out (B,T,C layout)

// ---------------------------------------------------------------------------
// SGEMM: C[M,N] = A[M,K] @ Bmat[K, ldb] (logical col n -> physical col n (+768 if n>=nsplit))
// 128x128 tile, BK=16, 256 threads, 8x8 per thread. All dims divisible.
// ---------------------------------------------------------------------------
#define GBM 128
#define GBN 128
#define GBK 16

__global__ __launch_bounds__(256) void sgemm_kernel(
    const float* __restrict__ A, const float* __restrict__ Bmat,
    float* __restrict__ Cmat, const float* __restrict__ bias,
    int M, int N, int K, int ldb, int nsplit)
{
    __shared__ float As[GBK][GBM + 1];
    __shared__ float Bs[GBK][GBN];

    int tid  = threadIdx.x;
    int bcol = blockIdx.x;
    int brow = blockIdx.y;
    int tx = tid & 15;   // col group
    int ty = tid >> 4;   // row group

    float acc[8][8];
    #pragma unroll
    for (int i = 0; i < 8; i++)
        #pragma unroll
        for (int j = 0; j < 8; j++) acc[i][j] = 0.f;

    const float* Ablk = A + (size_t)brow * GBM * K;
    int ncolbase = bcol * GBN;
    int physbase = (ncolbase >= nsplit) ? ncolbase + 768 : ncolbase;

    for (int kt = 0; kt < K; kt += GBK) {
        #pragma unroll
        for (int it = 0; it < 2; it++) {
            int idx = tid + it * 256;            // 0..511
            int r  = idx >> 2;                   // 0..127
            int c4 = (idx & 3) * 4;              // 0,4,8,12
            float4 v = *reinterpret_cast<const float4*>(Ablk + (size_t)r * K + kt + c4);
            As[c4 + 0][r] = v.x;
            As[c4 + 1][r] = v.y;
            As[c4 + 2][r] = v.z;
            As[c4 + 3][r] = v.w;
        }
        #pragma unroll
        for (int it = 0; it < 2; it++) {
            int idx = tid + it * 256;
            int r  = idx >> 5;                   // 0..15
            int c4 = (idx & 31) * 4;             // 0..124
            float4 v = *reinterpret_cast<const float4*>(
                Bmat + (size_t)(kt + r) * ldb + physbase + c4);
            *reinterpret_cast<float4*>(&Bs[r][c4]) = v;
        }
        __syncthreads();

        #pragma unroll
        for (int k = 0; k < GBK; k++) {
            float ra[8], rb[8];
            #pragma unroll
            for (int i = 0; i < 8; i++) ra[i] = As[k][ty * 8 + i];
            #pragma unroll
            for (int j = 0; j < 8; j++) rb[j] = Bs[k][tx * 8 + j];
            #pragma unroll
            for (int i = 0; i < 8; i++)
                #pragma unroll
                for (int j = 0; j < 8; j++)
                    acc[i][j] += ra[i] * rb[j];
        }
        __syncthreads();
    }

    #pragma unroll
    for (int i = 0; i < 8; i++) {
        int row = brow * GBM + ty * 8 + i;
        #pragma unroll
        for (int j = 0; j < 8; j++) {
            int col = ncolbase + tx * 8 + j;
            float v = acc[i][j];
            if (bias) v += bias[col];
            Cmat[(size_t)row * N + col] = v;
        }
    }
}

// ---------------------------------------------------------------------------
// RoPE + transpose to head layout. K = rope(k), Q = rope(v) (faithful bug), V = v.
// ---------------------------------------------------------------------------
__global__ __launch_bounds__(256) void rope_kernel(
    const float* __restrict__ tmp,
    const float* __restrict__ cosb, const float* __restrict__ sinb,
    float* __restrict__ Ko, float* __restrict__ Qo, float* __restrict__ Vo)
{
    int idx = blockIdx.x * blockDim.x + threadIdx.x;
    if (idx >= Mz * Hz * (Dz / 2)) return;
    int i = idx & 31;
    int h = (idx >> 5) % Hz;
    int m = idx / (Hz * 32);
    int b = m >> 11;
    int t = m & (Tz - 1);

    const float* row = tmp + (size_t)m * 1536;
    float kr = row[h * Dz + 2 * i];
    float ki = row[h * Dz + 2 * i + 1];
    float vr = row[768 + h * Dz + 2 * i];
    float vi = row[768 + h * Dz + 2 * i + 1];

    float c = cosb[t * 32 + i];
    float s = sinb[t * 32 + i];

    size_t o = ((size_t)(b * Hz + h) * Tz + t) * Dz + 2 * i;
    Ko[o]     = kr * c - ki * s;
    Ko[o + 1] = kr * s + ki * c;
    Qo[o]     = vr * c - vi * s;
    Qo[o + 1] = vr * s + vi * c;
    Vo[o]     = vr;
    Vo[o + 1] = vi;
}

// ---------------------------------------------------------------------------
// Flash attention v2: GEMM-structured tiles.
// Block: 256 threads. Q-tile = 128 rows, K-tile = 128 keys.
// Phase1: S = Q@K^T via 8x8 register blocking (scores stay in registers).
// Phase2: batched online softmax (shfl over tx half-warp), P -> smem.
// Phase3: O += P@V via 8x4 register blocking; O in registers across tiles.
// ---------------------------------------------------------------------------
#define FTQ 128
#define FTK 128

// smem float offsets
#define OFF_QT 0                      // Qt[64][129]
#define OFF_KT (64*129)               // Kt[64][128]
#define OFF_VS (OFF_KT + 64*128)      // Vs[128][64]
#define OFF_PS (OFF_VS + 128*64)      // Ps[128][130]
#define FL_SMEM_FLOATS (OFF_PS + 128*130)
#define FL_SMEM_BYTES (FL_SMEM_FLOATS * 4)

__global__ __launch_bounds__(256) void flash2_kernel(
    const float* __restrict__ Q, const float* __restrict__ K,
    const float* __restrict__ V, float* __restrict__ O)
{
    extern __shared__ float sm[];
    float* Qt = sm + OFF_QT;   // [64][129] transposed, scale folded
    float* Kt = sm + OFF_KT;   // [64][128] transposed
    float* Vs = sm + OFF_VS;   // [128][64] natural
    float* Ps = sm + OFF_PS;   // [128][130]

    const int tid = threadIdx.x;
    const int qt  = blockIdx.x;       // q tile 0..15
    const int bh  = blockIdx.y;
    const int tx  = tid & 15;         // key group (phase1) / dim group (phase3)
    const int ty  = tid >> 4;         // row group
    const int r0  = ty * 8;
    const int k0  = tx * 8;

    const float* Qb = Q + (size_t)bh * Tz * Dz;
    const float* Kb = K + (size_t)bh * Tz * Dz;
    const float* Vb = V + (size_t)bh * Tz * Dz;

    // ---- Load Q tile transposed into Qt[64][129], scale folded ----
    {
        const float scale = 0.125f;   // D^-0.5
        #pragma unroll
        for (int it = 0; it < 8; it++) {
            int idx = tid + it * 256;          // 0..2047 float4 chunks
            int row = idx & 127;
            int c4  = (idx >> 7) * 4;          // 0..60
            float4 v = *reinterpret_cast<const float4*>(
                Qb + (size_t)(qt * FTQ + row) * Dz + c4);
            Qt[(c4 + 0) * 129 + row] = v.x * scale;
            Qt[(c4 + 1) * 129 + row] = v.y * scale;
            Qt[(c4 + 2) * 129 + row] = v.z * scale;
            Qt[(c4 + 3) * 129 + row] = v.w * scale;
        }
    }

    float o[8][4];
    float mrow[8], lrow[8];
    #pragma unroll
    for (int i = 0; i < 8; i++) {
        mrow[i] = -1e30f; lrow[i] = 0.f;
        #pragma unroll
        for (int d = 0; d < 4; d++) o[i][d] = 0.f;
    }

    for (int jt = 0; jt <= qt; jt++) {
        // ---- Load K tile transposed + V tile natural ----
        #pragma unroll
        for (int it = 0; it < 8; it++) {
            int idx = tid + it * 256;
            int key = idx & 127;
            int c4  = (idx >> 7) * 4;
            float4 v = *reinterpret_cast<const float4*>(
                Kb + (size_t)(jt * FTK + key) * Dz + c4);
            Kt[(c4 + 0) * 128 + key] = v.x;
            Kt[(c4 + 1) * 128 + key] = v.y;
            Kt[(c4 + 2) * 128 + key] = v.z;
            Kt[(c4 + 3) * 128 + key] = v.w;
        }
        #pragma unroll
        for (int it = 0; it < 8; it++) {
            int idx = tid + it * 256;
            int row = idx >> 4;
            int c4  = (idx & 15) * 4;
            *reinterpret_cast<float4*>(&Vs[row * 64 + c4]) =
                *reinterpret_cast<const float4*>(
                    Vb + (size_t)(jt * FTK + row) * Dz + c4);
        }
        __syncthreads();

        // ---- Phase 1: S = Q@K^T, 8x8 per thread ----
        float s[8][8];
        #pragma unroll
        for (int i = 0; i < 8; i++)
            #pragma unroll
            for (int j = 0; j < 8; j++) s[i][j] = 0.f;

        #pragma unroll 4
        for (int d = 0; d < 64; d++) {
            float ra[8], rb[8];
            #pragma unroll
            for (int i = 0; i < 8; i++) ra[i] = Qt[d * 129 + r0 + i];
            #pragma unroll
            for (int j = 0; j < 8; j++) rb[j] = Kt[d * 128 + k0 + j];
            #pragma unroll
            for (int i = 0; i < 8; i++)
                #pragma unroll
                for (int j = 0; j < 8; j++)
                    s[i][j] += ra[i] * rb[j];
        }

        // ---- Causal mask (diagonal tile only) ----
        if (jt == qt) {
            #pragma unroll
            for (int i = 0; i < 8; i++)
                #pragma unroll
                for (int j = 0; j < 8; j++)
                    if (k0 + j > r0 + i) s[i][j] = -1e30f;
        }

        // ---- Phase 2: online softmax, write P ----
        #pragma unroll
        for (int i = 0; i < 8; i++) {
            float tmax = s[i][0];
            #pragma unroll
            for (int j = 1; j < 8; j++) tmax = fmaxf(tmax, s[i][j]);
            #pragma unroll
            for (int off = 1; off < 16; off <<= 1)
                tmax = fmaxf(tmax, __shfl_xor_sync(0xffffffffu, tmax, off));

            float nm = fmaxf(mrow[i], tmax);
            float corr = __expf(mrow[i] - nm);
            mrow[i] = nm;

            float p[8], rs = 0.f;
            #pragma unroll
            for (int j = 0; j < 8; j++) { p[j] = __expf(s[i][j] - nm); rs += p[j]; }
            #pragma unroll
            for (int off = 1; off < 16; off <<= 1)
                rs += __shfl_xor_sync(0xffffffffu, rs, off);

            lrow[i] = lrow[i] * corr + rs;
            #pragma unroll
            for (int d = 0; d < 4; d++) o[i][d] *= corr;

            float* prow = &Ps[(r0 + i) * 130 + k0];
            #pragma unroll
            for (int jj = 0; jj < 4; jj++)
                *reinterpret_cast<float2*>(prow + 2 * jj) =
                    make_float2(p[2 * jj], p[2 * jj + 1]);
        }
        __syncthreads();

        // ---- Phase 3: O += P@V, 8 rows x 4 dims per thread ----
        #pragma unroll 2
        for (int k = 0; k < 128; k++) {
            float4 vb = *reinterpret_cast<const float4*>(&Vs[k * 64 + tx * 4]);
            float pa[8];
            #pragma unroll
            for (int i = 0; i < 8; i++) pa[i] = Ps[(r0 + i) * 130 + k];
            #pragma unroll
            for (int i = 0; i < 8; i++) {
                o[i][0] += pa[i] * vb.x;
                o[i][1] += pa[i] * vb.y;
                o[i][2] += pa[i] * vb.z;
                o[i][3] += pa[i] * vb.w;
            }
        }
        __syncthreads();   // before overwriting K/V/P next tile
    }

    // ---- Normalize + write to [B,T,C] layout ----
    const int b = bh / Hz, h = bh % Hz;
    #pragma unroll
    for (int i = 0; i < 8; i++) {
        float inv = 1.f / lrow[i];
        int grow = b * Tz + qt * FTQ + r0 + i;
        float* orow = O + (size_t)grow * Cz + h * Dz + tx * 4;
        *reinterpret_cast<float4*>(orow) =
            make_float4(o[i][0] * inv, o[i][1] * inv, o[i][2] * inv, o[i][3] * inv);
    }
}

// ---------------------------------------------------------------------------
// kernel_launch
// ---------------------------------------------------------------------------
extern "C" void kernel_launch(void* const* d_in, const int* in_sizes, int n_in,
                              void* d_out, int out_size)
{
    const float* x      = (const float*)d_in[0];
    const float* cosb   = (const float*)d_in[1];
    const float* sinb   = (const float*)d_in[2];
    const float* W_att  = (const float*)d_in[3];
    const float* W_proj = (const float*)d_in[4];
    const float* b_proj = (const float*)d_in[5];
    float* out = (float*)d_out;

    float *tmp, *Kp, *Qp, *Vp, *att;
    cudaGetSymbolAddress((void**)&tmp, g_tmp);
    cudaGetSymbolAddress((void**)&Kp,  g_K);
    cudaGetSymbolAddress((void**)&Qp,  g_Q);
    cudaGetSymbolAddress((void**)&Vp,  g_V);
    cudaGetSymbolAddress((void**)&att, g_att);

    // 1) QKV GEMM (k and v chunks only; q chunk is dead code in the reference)
    sgemm_kernel<<<dim3(1536 / GBN, Mz / GBM), 256>>>(
        x, W_att, tmp, nullptr, Mz, 1536, Cz, 3 * Cz, 768);

    // 2) RoPE + transpose to [BH,T,D]
    {
        int total = Mz * Hz * (Dz / 2);
        rope_kernel<<<(total + 255) / 256, 256>>>(tmp, cosb, sinb, Kp, Qp, Vp);
    }

    // 3) Causal flash attention v2 -> g_att in [B,T,C] layout
    cudaFuncSetAttribute(flash2_kernel,
                         cudaFuncAttributeMaxDynamicSharedMemorySize, FL_SMEM_BYTES);
    flash2_kernel<<<dim3(Tz / FTQ, BHz), 256, FL_SMEM_BYTES>>>(Qp, Kp, Vp, att);

    // 4) Output projection + bias -> d_out
    sgemm_kernel<<<dim3(Cz / GBN, Mz / GBM), 256>>>(
        att, W_proj, out, b_proj, Mz, Cz, Cz, Cz, 1 << 30);
}

// round 4
// speedup vs baseline: 5.9526x; 2.5284x over previous
#include <cuda_runtime.h>
#include <cuda_bf16.h>
#include <cstdint>

// Problem constants
#define Bz 2
#define Tz 2048
#define Cz 768
#define Hz 12
#define Dz 64
#define BHz (Bz*Hz)        // 24
#define Mz (Bz*Tz)         // 4096

typedef __nv_bfloat16 bf16;

// ---------------------------------------------------------------------------
// Scratch (static device arrays — no cudaMalloc allowed)
// ---------------------------------------------------------------------------
__device__ float g_tmp[(size_t)Mz * 1536];        // QKV gemm out: k-chunk | v-chunk
__device__ float g_att[(size_t)Mz * Cz];          // attention out, [B,T,C]

__device__ bf16 g_xhi[(size_t)Mz * Cz],  g_xlo[(size_t)Mz * Cz];
__device__ bf16 g_ahi[(size_t)Mz * Cz],  g_alo[(size_t)Mz * Cz];
__device__ bf16 g_w1hi[(size_t)1536 * Cz], g_w1lo[(size_t)1536 * Cz];
__device__ bf16 g_w2hi[(size_t)Cz * Cz],   g_w2lo[(size_t)Cz * Cz];

// rope outputs, [BH, T, D] bf16 hi/lo
__device__ bf16 g_Kh[(size_t)BHz * Tz * Dz], g_Kl[(size_t)BHz * Tz * Dz];
__device__ bf16 g_Qh[(size_t)BHz * Tz * Dz], g_Ql[(size_t)BHz * Tz * Dz];
__device__ bf16 g_Vh[(size_t)BHz * Tz * Dz], g_Vl[(size_t)BHz * Tz * Dz];

// ---------------------------------------------------------------------------
// Warp-MMA helpers (sm_80-compatible: compile under plain sm_100 target)
// ---------------------------------------------------------------------------
__device__ __forceinline__ uint32_t smem_u32(const void* p) {
    uint32_t a;
    asm("{ .reg .u64 t; cvta.to.shared.u64 t, %1; cvt.u32.u64 %0, t; }"
        : "=r"(a) : "l"(p));
    return a;
}

__device__ __forceinline__ void mma_bf16(float* d, const uint32_t* a,
                                         uint32_t b0, uint32_t b1) {
    asm volatile(
        "mma.sync.aligned.m16n8k16.row.col.f32.bf16.bf16.f32 "
        "{%0,%1,%2,%3}, {%4,%5,%6,%7}, {%8,%9}, {%0,%1,%2,%3};"
        : "+f"(d[0]), "+f"(d[1]), "+f"(d[2]), "+f"(d[3])
        : "r"(a[0]), "r"(a[1]), "r"(a[2]), "r"(a[3]), "r"(b0), "r"(b1));
}
__device__ __forceinline__ void ldmx4(uint32_t* r, uint32_t addr) {
    asm volatile("ldmatrix.sync.aligned.m8n8.x4.shared.b16 {%0,%1,%2,%3}, [%4];"
        : "=r"(r[0]), "=r"(r[1]), "=r"(r[2]), "=r"(r[3]) : "r"(addr));
}
__device__ __forceinline__ void ldmx4t(uint32_t* r, uint32_t addr) {
    asm volatile("ldmatrix.sync.aligned.m8n8.x4.trans.shared.b16 {%0,%1,%2,%3}, [%4];"
        : "=r"(r[0]), "=r"(r[1]), "=r"(r[2]), "=r"(r[3]) : "r"(addr));
}
// pack (low=a, high=b) with bf16 truncation of the f32 bits (exact hi part)
__device__ __forceinline__ uint32_t pack_hi_trunc(float a, float b) {
    return (__float_as_uint(b) & 0xFFFF0000u) | (__float_as_uint(a) >> 16);
}
__device__ __forceinline__ float trunc_bf(float a) {
    return __uint_as_float(__float_as_uint(a) & 0xFFFF0000u);
}
// pack residuals with round-to-nearest: low=a, high=b
__device__ __forceinline__ uint32_t pack_lo_rn(float a, float b) {
    uint32_t u;
    float ra = a - trunc_bf(a), rb = b - trunc_bf(b);
    asm("cvt.rn.bf16x2.f32 %0, %1, %2;" : "=r"(u) : "f"(rb), "f"(ra));
    return u;
}

// ---------------------------------------------------------------------------
// bf16 split prep kernels
// ---------------------------------------------------------------------------
__global__ __launch_bounds__(256) void split_rows_kernel(
    const float* __restrict__ in, bf16* __restrict__ hi, bf16* __restrict__ lo, int n)
{
    int i = blockIdx.x * 256 + threadIdx.x;
    if (i >= n) return;
    float v = in[i];
    bf16 h = __float2bfloat16(v);
    hi[i] = h;
    lo[i] = __float2bfloat16(v - __bfloat162float(h));
}

// Wt[n][k] = W[k][col(n)], split hi/lo. col(n) = n + (n>=nsplit ? 768 : 0)
__global__ __launch_bounds__(256) void splitT_kernel(
    const float* __restrict__ W, bf16* __restrict__ hi, bf16* __restrict__ lo,
    int N, int K, int ldw, int nsplit)
{
    int idx = blockIdx.x * 256 + threadIdx.x;
    if (idx >= N * K) return;
    int k = idx % K;
    int n = idx / K;
    int col = n + (n >= nsplit ? 768 : 0);
    float v = W[(size_t)k * ldw + col];
    bf16 h = __float2bfloat16(v);
    hi[idx] = h;
    lo[idx] = __float2bfloat16(v - __bfloat162float(h));
}

// ---------------------------------------------------------------------------
// Dense GEMM via mma.sync: C[M,N] = A[M,K] @ Bt[N,K]^T, bf16x3 split.
// 128x128x32 CTA tiles, 8 warps (4x2), warptile 32x64.
// ---------------------------------------------------------------------------
#define MG_STRIDE 80            // 32 bf16 = 64B data + 16B pad
#define MG_AH 0
#define MG_AL 10240
#define MG_BH 20480
#define MG_BL 30720

__global__ __launch_bounds__(256) void mm_gemm_kernel(
    const bf16* __restrict__ Ahi, const bf16* __restrict__ Alo,
    const bf16* __restrict__ Bhi, const bf16* __restrict__ Blo,
    float* __restrict__ Cmat, const float* __restrict__ bias,
    int K, int ldc)
{
    __shared__ __align__(16) char gsm[40960];
    const uint32_t smb = smem_u32(gsm);
    const int tid  = threadIdx.x;
    const int w    = tid >> 5;
    const int lane = tid & 31;
    const int n0 = blockIdx.x * 128;
    const int m0 = blockIdx.y * 128;
    const int wm = w & 3;        // m strip (32 rows)
    const int wn = w >> 2;       // n strip (64 cols)

    float acc[2][8][4];
    #pragma unroll
    for (int a = 0; a < 2; a++)
        #pragma unroll
        for (int b = 0; b < 8; b++)
            #pragma unroll
            for (int c = 0; c < 4; c++) acc[a][b][c] = 0.f;

    const int arow = lane & 15, asel = lane >> 4;
    const int brow = lane & 7,  bsel = (lane >> 3) & 3;

    for (int kc = 0; kc < K; kc += 32) {
        if (kc) __syncthreads();
        // fill 4 tiles: each 128 rows x 4x16B units
        #pragma unroll
        for (int it = 0; it < 2; it++) {
            int u   = tid + it * 256;          // 0..511
            int row = u >> 2, c = u & 3;
            const size_t ga = (size_t)(m0 + row) * K + kc + c * 8;
            const size_t gb = (size_t)(n0 + row) * K + kc + c * 8;
            char* d = gsm + row * MG_STRIDE + c * 16;
            *reinterpret_cast<uint4*>(d + MG_AH) = *reinterpret_cast<const uint4*>(Ahi + ga);
            *reinterpret_cast<uint4*>(d + MG_AL) = *reinterpret_cast<const uint4*>(Alo + ga);
            *reinterpret_cast<uint4*>(d + MG_BH) = *reinterpret_cast<const uint4*>(Bhi + gb);
            *reinterpret_cast<uint4*>(d + MG_BL) = *reinterpret_cast<const uint4*>(Blo + gb);
        }
        __syncthreads();

        // A fragments (2 matoms x 2 ksteps, hi+lo)
        uint32_t ah[2][2][4], al[2][2][4];
        #pragma unroll
        for (int ma = 0; ma < 2; ma++)
            #pragma unroll
            for (int ks = 0; ks < 2; ks++) {
                uint32_t off = (uint32_t)((wm * 32 + ma * 16 + arow) * MG_STRIDE
                                          + ks * 32 + asel * 16);
                ldmx4(ah[ma][ks], smb + MG_AH + off);
                ldmx4(al[ma][ks], smb + MG_AL + off);
            }

        #pragma unroll
        for (int na = 0; na < 8; na++) {
            uint32_t boff = (uint32_t)((wn * 64 + na * 8 + brow) * MG_STRIDE + bsel * 16);
            uint32_t bh4[4], bl4[4];
            ldmx4(bh4, smb + MG_BH + boff);
            #pragma unroll
            for (int ma = 0; ma < 2; ma++) {
                mma_bf16(acc[ma][na], ah[ma][0], bh4[0], bh4[1]);
                mma_bf16(acc[ma][na], ah[ma][1], bh4[2], bh4[3]);
                mma_bf16(acc[ma][na], al[ma][0], bh4[0], bh4[1]);
                mma_bf16(acc[ma][na], al[ma][1], bh4[2], bh4[3]);
            }
            ldmx4(bl4, smb + MG_BL + boff);
            #pragma unroll
            for (int ma = 0; ma < 2; ma++) {
                mma_bf16(acc[ma][na], ah[ma][0], bl4[0], bl4[1]);
                mma_bf16(acc[ma][na], ah[ma][1], bl4[2], bl4[3]);
            }
        }
    }

    // epilogue
    const int rg = lane >> 2, cg = lane & 3;
    #pragma unroll
    for (int ma = 0; ma < 2; ma++) {
        int row = m0 + wm * 32 + ma * 16 + rg;
        #pragma unroll
        for (int na = 0; na < 8; na++) {
            int col = n0 + wn * 64 + na * 8 + 2 * cg;
            float b0 = bias ? bias[col] : 0.f;
            float b1 = bias ? bias[col + 1] : 0.f;
            *reinterpret_cast<float2*>(Cmat + (size_t)row * ldc + col) =
                make_float2(acc[ma][na][0] + b0, acc[ma][na][1] + b1);
            *reinterpret_cast<float2*>(Cmat + (size_t)(row + 8) * ldc + col) =
                make_float2(acc[ma][na][2] + b0, acc[ma][na][3] + b1);
        }
    }
}

// ---------------------------------------------------------------------------
// RoPE + transpose + bf16 split. K=rope(k), Q=rope(v)*scale (faithful bug), V=v.
// ---------------------------------------------------------------------------
__device__ __forceinline__ void bsplit(float v, bf16* hp, bf16* lp) {
    bf16 h = __float2bfloat16(v);
    *hp = h;
    *lp = __float2bfloat16(v - __bfloat162float(h));
}

__global__ __launch_bounds__(256) void rope_split_kernel(
    const float* __restrict__ tmp,
    const float* __restrict__ cosb, const float* __restrict__ sinb,
    bf16* __restrict__ Kh, bf16* __restrict__ Kl,
    bf16* __restrict__ Qh, bf16* __restrict__ Ql,
    bf16* __restrict__ Vh, bf16* __restrict__ Vl)
{
    int idx = blockIdx.x * blockDim.x + threadIdx.x;
    if (idx >= Mz * Hz * (Dz / 2)) return;
    int i = idx & 31;
    int h = (idx >> 5) % Hz;
    int m = idx / (Hz * 32);
    int b = m >> 11;
    int t = m & (Tz - 1);

    const float* row = tmp + (size_t)m * 1536;
    float kr = row[h * Dz + 2 * i];
    float ki = row[h * Dz + 2 * i + 1];
    float vr = row[768 + h * Dz + 2 * i];
    float vi = row[768 + h * Dz + 2 * i + 1];

    float c = cosb[t * 32 + i];
    float s = sinb[t * 32 + i];

    size_t o = ((size_t)(b * Hz + h) * Tz + t) * Dz + 2 * i;
    const float scale = 0.125f;   // D^-0.5, folded into Q
    bsplit(kr * c - ki * s, Kh + o,     Kl + o);
    bsplit(kr * s + ki * c, Kh + o + 1, Kl + o + 1);
    bsplit((vr * c - vi * s) * scale, Qh + o,     Ql + o);
    bsplit((vr * s + vi * c) * scale, Qh + o + 1, Ql + o + 1);
    bsplit(vr, Vh + o,     Vl + o);
    bsplit(vi, Vh + o + 1, Vl + o + 1);
}

// ---------------------------------------------------------------------------
// Flash attention via mma.sync (bf16x3 split on S and PV).
// 128 q-rows x 128 keys per tile, 8 warps, warp = 16 q-rows.
// Q frags register-resident; P converted in-register (no smem round trip).
// ---------------------------------------------------------------------------
#define FL_STRIDE 144                // 64 bf16 = 128B + 16B pad
#define FL_TILE   (128 * FL_STRIDE)  // 18432
#define FL_KH 0
#define FL_KL (1 * FL_TILE)
#define FL_VH (2 * FL_TILE)
#define FL_VL (3 * FL_TILE)
#define FL_QH (4 * FL_TILE)
#define FL_QL (5 * FL_TILE)
#define FL3_SMEM (6 * FL_TILE)       // 110592

__device__ __forceinline__ void fl_fill(char* dst, const bf16* g, int tid) {
    #pragma unroll
    for (int it = 0; it < 4; it++) {
        int u = tid + it * 256;      // 0..1023
        int row = u >> 3, c = u & 7;
        *reinterpret_cast<uint4*>(dst + row * FL_STRIDE + c * 16) =
            *reinterpret_cast<const uint4*>(g + row * 64 + c * 8);
    }
}

__global__ __launch_bounds__(256) void flash3_kernel(
    const bf16* __restrict__ Qh, const bf16* __restrict__ Ql,
    const bf16* __restrict__ Kh, const bf16* __restrict__ Kl,
    const bf16* __restrict__ Vh, const bf16* __restrict__ Vl,
    float* __restrict__ O)
{
    extern __shared__ __align__(16) char sm3[];
    const uint32_t smb = smem_u32(sm3);
    const int tid  = threadIdx.x;
    const int w    = tid >> 5;
    const int lane = tid & 31;
    const int qt   = (int)gridDim.x - 1 - (int)blockIdx.x;   // heavy tiles first
    const int bh   = blockIdx.y;
    const size_t hb = (size_t)bh * Tz * Dz;

    // load Q tile (hi/lo) into smem, extract per-warp A-frags, keep in regs
    fl_fill(sm3 + FL_QH, Qh + hb + (size_t)qt * 128 * 64, tid);
    fl_fill(sm3 + FL_QL, Ql + hb + (size_t)qt * 128 * 64, tid);
    __syncthreads();

    uint32_t qfh[16], qfl[16];
    {
        int arow = lane & 15, asel = lane >> 4;
        #pragma unroll
        for (int ka = 0; ka < 4; ka++) {
            uint32_t off = (uint32_t)((16 * w + arow) * FL_STRIDE + ka * 32 + asel * 16);
            ldmx4(qfh + ka * 4, smb + FL_QH + off);
            ldmx4(qfl + ka * 4, smb + FL_QL + off);
        }
    }

    float o[8][4];
    #pragma unroll
    for (int nv = 0; nv < 8; nv++)
        #pragma unroll
        for (int c = 0; c < 4; c++) o[nv][c] = 0.f;
    float mA = -1e30f, mB = -1e30f, lA = 0.f, lB = 0.f;

    const int rg = lane >> 2, cg = lane & 3;
    const int brow = lane & 7, bsel = (lane >> 3) & 3;
    const int vkey = lane & 15, vsel = lane >> 4;

    for (int jt = 0; jt <= qt; jt++) {
        if (jt) __syncthreads();
        const size_t kb = hb + (size_t)jt * 128 * 64;
        fl_fill(sm3 + FL_KH, Kh + kb, tid);
        fl_fill(sm3 + FL_KL, Kl + kb, tid);
        fl_fill(sm3 + FL_VH, Vh + kb, tid);
        fl_fill(sm3 + FL_VL, Vl + kb, tid);
        __syncthreads();

        // ---- S = Q@K^T (bf16x3) ----
        float s[16][4];
        #pragma unroll
        for (int na = 0; na < 16; na++)
            #pragma unroll
            for (int c = 0; c < 4; c++) s[na][c] = 0.f;

        #pragma unroll
        for (int na = 0; na < 16; na++) {
            #pragma unroll
            for (int kp = 0; kp < 2; kp++) {
                uint32_t off = (uint32_t)((na * 8 + brow) * FL_STRIDE + kp * 64 + bsel * 16);
                uint32_t kh4[4], kl4[4];
                ldmx4(kh4, smb + FL_KH + off);
                mma_bf16(s[na], qfh + (2 * kp) * 4,     kh4[0], kh4[1]);
                mma_bf16(s[na], qfh + (2 * kp + 1) * 4, kh4[2], kh4[3]);
                mma_bf16(s[na], qfl + (2 * kp) * 4,     kh4[0], kh4[1]);
                mma_bf16(s[na], qfl + (2 * kp + 1) * 4, kh4[2], kh4[3]);
                ldmx4(kl4, smb + FL_KL + off);
                mma_bf16(s[na], qfh + (2 * kp) * 4,     kl4[0], kl4[1]);
                mma_bf16(s[na], qfh + (2 * kp + 1) * 4, kl4[2], kl4[3]);
            }
        }

        // ---- causal mask (diagonal tile) ----
        if (jt == qt) {
            int rA = 16 * w + rg, rB = rA + 8;
            #pragma unroll
            for (int na = 0; na < 16; na++) {
                int c0 = 8 * na + 2 * cg;
                if (c0 > rA)     s[na][0] = -1e30f;
                if (c0 + 1 > rA) s[na][1] = -1e30f;
                if (c0 > rB)     s[na][2] = -1e30f;
                if (c0 + 1 > rB) s[na][3] = -1e30f;
            }
        }

        // ---- online softmax: row maxes ----
        float xA = -1e30f, xB = -1e30f;
        #pragma unroll
        for (int na = 0; na < 16; na++) {
            xA = fmaxf(xA, fmaxf(s[na][0], s[na][1]));
            xB = fmaxf(xB, fmaxf(s[na][2], s[na][3]));
        }
        xA = fmaxf(xA, __shfl_xor_sync(0xffffffffu, xA, 1));
        xA = fmaxf(xA, __shfl_xor_sync(0xffffffffu, xA, 2));
        xB = fmaxf(xB, __shfl_xor_sync(0xffffffffu, xB, 1));
        xB = fmaxf(xB, __shfl_xor_sync(0xffffffffu, xB, 2));
        float nmA = fmaxf(mA, xA), nmB = fmaxf(mB, xB);
        float cA = __expf(mA - nmA), cB = __expf(mB - nmB);
        mA = nmA; mB = nmB;
        #pragma unroll
        for (int nv = 0; nv < 8; nv++) {
            o[nv][0] *= cA; o[nv][1] *= cA;
            o[nv][2] *= cB; o[nv][3] *= cB;
        }
        float sA = 0.f, sB = 0.f;

        // ---- exp + in-register P conversion + PV mma ----
        #pragma unroll
        for (int ka = 0; ka < 8; ka++) {
            float e00 = __expf(s[2 * ka][0] - nmA);
            float e01 = __expf(s[2 * ka][1] - nmA);
            float e02 = __expf(s[2 * ka][2] - nmB);
            float e03 = __expf(s[2 * ka][3] - nmB);
            float e10 = __expf(s[2 * ka + 1][0] - nmA);
            float e11 = __expf(s[2 * ka + 1][1] - nmA);
            float e12 = __expf(s[2 * ka + 1][2] - nmB);
            float e13 = __expf(s[2 * ka + 1][3] - nmB);
            sA += (e00 + e01) + (e10 + e11);
            sB += (e02 + e03) + (e12 + e13);

            uint32_t pah[4], pal[4];
            pah[0] = pack_hi_trunc(e00, e01);
            pah[1] = pack_hi_trunc(e02, e03);
            pah[2] = pack_hi_trunc(e10, e11);
            pah[3] = pack_hi_trunc(e12, e13);
            pal[0] = pack_lo_rn(e00, e01);
            pal[1] = pack_lo_rn(e02, e03);
            pal[2] = pack_lo_rn(e10, e11);
            pal[3] = pack_lo_rn(e12, e13);

            #pragma unroll
            for (int nv = 0; nv < 4; nv++) {
                uint32_t voff = (uint32_t)((ka * 16 + vkey) * FL_STRIDE
                                           + (nv * 16 + vsel * 8) * 2);
                uint32_t vh4[4], vl4[4];
                ldmx4t(vh4, smb + FL_VH + voff);
                mma_bf16(o[2 * nv],     pah, vh4[0], vh4[1]);
                mma_bf16(o[2 * nv + 1], pah, vh4[2], vh4[3]);
                mma_bf16(o[2 * nv],     pal, vh4[0], vh4[1]);
                mma_bf16(o[2 * nv + 1], pal, vh4[2], vh4[3]);
                ldmx4t(vl4, smb + FL_VL + voff);
                mma_bf16(o[2 * nv],     pah, vl4[0], vl4[1]);
                mma_bf16(o[2 * nv + 1], pah, vl4[2], vl4[3]);
            }
        }
        sA += __shfl_xor_sync(0xffffffffu, sA, 1);
        sA += __shfl_xor_sync(0xffffffffu, sA, 2);
        sB += __shfl_xor_sync(0xffffffffu, sB, 1);
        sB += __shfl_xor_sync(0xffffffffu, sB, 2);
        lA = lA * cA + sA;
        lB = lB * cB + sB;
    }

    // ---- normalize + write [B,T,C] ----
    const int b = bh / Hz, h = bh % Hz;
    const float invA = 1.f / lA, invB = 1.f / lB;
    int rA = qt * 128 + 16 * w + rg;
    #pragma unroll
    for (int nv = 0; nv < 8; nv++) {
        int col = h * 64 + nv * 8 + 2 * cg;
        *reinterpret_cast<float2*>(O + (size_t)(b * Tz + rA) * Cz + col) =
            make_float2(o[nv][0] * invA, o[nv][1] * invA);
        *reinterpret_cast<float2*>(O + (size_t)(b * Tz + rA + 8) * Cz + col) =
            make_float2(o[nv][2] * invB, o[nv][3] * invB);
    }
}

// ---------------------------------------------------------------------------
// kernel_launch
// ---------------------------------------------------------------------------
extern "C" void kernel_launch(void* const* d_in, const int* in_sizes, int n_in,
                              void* d_out, int out_size)
{
    const float* x      = (const float*)d_in[0];
    const float* cosb   = (const float*)d_in[1];
    const float* sinb   = (const float*)d_in[2];
    const float* W_att  = (const float*)d_in[3];
    const float* W_proj = (const float*)d_in[4];
    const float* b_proj = (const float*)d_in[5];
    float* out = (float*)d_out;

    float *tmp, *att;
    cudaGetSymbolAddress((void**)&tmp, g_tmp);
    cudaGetSymbolAddress((void**)&att, g_att);
    bf16 *xhi, *xlo, *ahi, *alo, *w1hi, *w1lo, *w2hi, *w2lo;
    cudaGetSymbolAddress((void**)&xhi, g_xhi);
    cudaGetSymbolAddress((void**)&xlo, g_xlo);
    cudaGetSymbolAddress((void**)&ahi, g_ahi);
    cudaGetSymbolAddress((void**)&alo, g_alo);
    cudaGetSymbolAddress((void**)&w1hi, g_w1hi);
    cudaGetSymbolAddress((void**)&w1lo, g_w1lo);
    cudaGetSymbolAddress((void**)&w2hi, g_w2hi);
    cudaGetSymbolAddress((void**)&w2lo, g_w2lo);
    bf16 *Khp, *Klp, *Qhp, *Qlp, *Vhp, *Vlp;
    cudaGetSymbolAddress((void**)&Khp, g_Kh);
    cudaGetSymbolAddress((void**)&Klp, g_Kl);
    cudaGetSymbolAddress((void**)&Qhp, g_Qh);
    cudaGetSymbolAddress((void**)&Qlp, g_Ql);
    cudaGetSymbolAddress((void**)&Vhp, g_Vh);
    cudaGetSymbolAddress((void**)&Vlp, g_Vl);

    cudaFuncSetAttribute(flash3_kernel,
                         cudaFuncAttributeMaxDynamicSharedMemorySize, FL3_SMEM);

    // prep: bf16 splits
    split_rows_kernel<<<(Mz * Cz + 255) / 256, 256>>>(x, xhi, xlo, Mz * Cz);
    splitT_kernel<<<(1536 * Cz + 255) / 256, 256>>>(W_att, w1hi, w1lo, 1536, Cz, 3 * Cz, 768);
    splitT_kernel<<<(Cz * Cz + 255) / 256, 256>>>(W_proj, w2hi, w2lo, Cz, Cz, Cz, 1 << 30);

    // 1) QKV GEMM (k and v chunks only) -> g_tmp [4096,1536]
    mm_gemm_kernel<<<dim3(1536 / 128, Mz / 128), 256>>>(
        xhi, xlo, w1hi, w1lo, tmp, nullptr, Cz, 1536);

    // 2) RoPE + transpose + split -> [BH,T,D] bf16 hi/lo
    {
        int total = Mz * Hz * (Dz / 2);
        rope_split_kernel<<<(total + 255) / 256, 256>>>(
            tmp, cosb, sinb, Khp, Klp, Qhp, Qlp, Vhp, Vlp);
    }

    // 3) Flash attention (HMMA) -> g_att [B,T,C] fp32
    flash3_kernel<<<dim3(Tz / 128, BHz), 256, FL3_SMEM>>>(
        Qhp, Qlp, Khp, Klp, Vhp, Vlp, att);

    // 4) split attention out, proj GEMM + bias -> d_out
    split_rows_kernel<<<(Mz * Cz + 255) / 256, 256>>>(att, ahi, alo, Mz * Cz);
    mm_gemm_kernel<<<dim3(Cz / 128, Mz / 128), 256>>>(
        ahi, alo, w2hi, w2lo, out, b_proj, Cz, Cz);
}

// round 5
// speedup vs baseline: 6.6087x; 1.1102x over previous
#include <cuda_runtime.h>
#include <cuda_bf16.h>
#include <cstdint>

// Problem constants
#define Bz 2
#define Tz 2048
#define Cz 768
#define Hz 12
#define Dz 64
#define BHz (Bz*Hz)        // 24
#define Mz (Bz*Tz)         // 4096

typedef __nv_bfloat16 bf16;

// ---------------------------------------------------------------------------
// Scratch (static device arrays — no cudaMalloc allowed)
// ---------------------------------------------------------------------------
__device__ float g_tmp[(size_t)Mz * 1536];        // QKV gemm out: k-chunk | v-chunk

__device__ bf16 g_xhi[(size_t)Mz * Cz],  g_xlo[(size_t)Mz * Cz];
__device__ bf16 g_ahi[(size_t)Mz * Cz],  g_alo[(size_t)Mz * Cz];
__device__ bf16 g_w1hi[(size_t)1536 * Cz], g_w1lo[(size_t)1536 * Cz];
__device__ bf16 g_w2hi[(size_t)Cz * Cz],   g_w2lo[(size_t)Cz * Cz];

// rope outputs, [BH, T, D] bf16 hi/lo
__device__ bf16 g_Kh[(size_t)BHz * Tz * Dz], g_Kl[(size_t)BHz * Tz * Dz];
__device__ bf16 g_Qh[(size_t)BHz * Tz * Dz], g_Ql[(size_t)BHz * Tz * Dz];
__device__ bf16 g_Vh[(size_t)BHz * Tz * Dz], g_Vl[(size_t)BHz * Tz * Dz];

// ---------------------------------------------------------------------------
// Warp-MMA + async-copy helpers (sm_80-compatible under plain sm_100 target)
// ---------------------------------------------------------------------------
__device__ __forceinline__ uint32_t smem_u32(const void* p) {
    uint32_t a;
    asm("{ .reg .u64 t; cvta.to.shared.u64 t, %1; cvt.u32.u64 %0, t; }"
        : "=r"(a) : "l"(p));
    return a;
}
__device__ __forceinline__ void mma_bf16(float* d, const uint32_t* a,
                                         uint32_t b0, uint32_t b1) {
    asm volatile(
        "mma.sync.aligned.m16n8k16.row.col.f32.bf16.bf16.f32 "
        "{%0,%1,%2,%3}, {%4,%5,%6,%7}, {%8,%9}, {%0,%1,%2,%3};"
        : "+f"(d[0]), "+f"(d[1]), "+f"(d[2]), "+f"(d[3])
        : "r"(a[0]), "r"(a[1]), "r"(a[2]), "r"(a[3]), "r"(b0), "r"(b1));
}
__device__ __forceinline__ void ldmx4(uint32_t* r, uint32_t addr) {
    asm volatile("ldmatrix.sync.aligned.m8n8.x4.shared.b16 {%0,%1,%2,%3}, [%4];"
        : "=r"(r[0]), "=r"(r[1]), "=r"(r[2]), "=r"(r[3]) : "r"(addr));
}
__device__ __forceinline__ void ldmx4t(uint32_t* r, uint32_t addr) {
    asm volatile("ldmatrix.sync.aligned.m8n8.x4.trans.shared.b16 {%0,%1,%2,%3}, [%4];"
        : "=r"(r[0]), "=r"(r[1]), "=r"(r[2]), "=r"(r[3]) : "r"(addr));
}
__device__ __forceinline__ void cpa16(uint32_t d, const void* s) {
    asm volatile("cp.async.cg.shared.global [%0], [%1], 16;" :: "r"(d), "l"(s));
}
#define CP_COMMIT() asm volatile("cp.async.commit_group;" ::: "memory")
#define CP_WAIT(n)  asm volatile("cp.async.wait_group %0;" :: "n"(n) : "memory")

// bf16 packing helpers
__device__ __forceinline__ uint32_t pack_hi_trunc(float a, float b) {
    return (__float_as_uint(b) & 0xFFFF0000u) | (__float_as_uint(a) >> 16);
}
__device__ __forceinline__ float trunc_bf(float a) {
    return __uint_as_float(__float_as_uint(a) & 0xFFFF0000u);
}
__device__ __forceinline__ uint32_t pack_lo_rn(float a, float b) {
    uint32_t u;
    float ra = a - trunc_bf(a), rb = b - trunc_bf(b);
    asm("cvt.rn.bf16x2.f32 %0, %1, %2;" : "=r"(u) : "f"(rb), "f"(ra));
    return u;
}
__device__ __forceinline__ void bsplit(float v, bf16* hp, bf16* lp) {
    bf16 h = __float2bfloat16(v);
    *hp = h;
    *lp = __float2bfloat16(v - __bfloat162float(h));
}

// ---------------------------------------------------------------------------
// bf16 split prep kernels
// ---------------------------------------------------------------------------
__global__ __launch_bounds__(256) void split_rows_kernel(
    const float* __restrict__ in, bf16* __restrict__ hi, bf16* __restrict__ lo, int n)
{
    int i = blockIdx.x * 256 + threadIdx.x;
    if (i >= n) return;
    float v = in[i];
    bf16 h = __float2bfloat16(v);
    hi[i] = h;
    lo[i] = __float2bfloat16(v - __bfloat162float(h));
}

__global__ __launch_bounds__(256) void splitT_kernel(
    const float* __restrict__ W, bf16* __restrict__ hi, bf16* __restrict__ lo,
    int N, int K, int ldw, int nsplit)
{
    int idx = blockIdx.x * 256 + threadIdx.x;
    if (idx >= N * K) return;
    int k = idx % K;
    int n = idx / K;
    int col = n + (n >= nsplit ? 768 : 0);
    float v = W[(size_t)k * ldw + col];
    bf16 h = __float2bfloat16(v);
    hi[idx] = h;
    lo[idx] = __float2bfloat16(v - __bfloat162float(h));
}

// ---------------------------------------------------------------------------
// Dense GEMM via mma.sync, 3-stage cp.async pipeline.
// C[M,N] = A[M,K] @ Bt[N,K]^T, bf16x3 split. 128x128x32 CTA, 8 warps.
// ---------------------------------------------------------------------------
#define MG_STRIDE 80            // 32 bf16 = 64B data + 16B pad
#define MG_AH 0
#define MG_AL 10240
#define MG_BH 20480
#define MG_BL 30720
#define MG_STAGE 40960
#define MG_SMEM (3 * MG_STAGE)  // 122880

__global__ __launch_bounds__(256) void mm_gemm_kernel(
    const bf16* __restrict__ Ahi, const bf16* __restrict__ Alo,
    const bf16* __restrict__ Bhi, const bf16* __restrict__ Blo,
    float* __restrict__ Cmat, const float* __restrict__ bias,
    int K, int ldc)
{
    extern __shared__ __align__(16) char gsm[];
    const uint32_t smb = smem_u32(gsm);
    const int tid  = threadIdx.x;
    const int w    = tid >> 5;
    const int lane = tid & 31;
    const int n0 = blockIdx.x * 128;
    const int m0 = blockIdx.y * 128;
    const int wm = w & 3;
    const int wn = w >> 2;

    auto load_stage = [&](int s, int kc) {
        uint32_t base = smb + s * MG_STAGE;
        #pragma unroll
        for (int it = 0; it < 2; it++) {
            int u   = tid + it * 256;
            int row = u >> 2, cc = u & 3;
            size_t ga = (size_t)(m0 + row) * K + kc + cc * 8;
            size_t gb = (size_t)(n0 + row) * K + kc + cc * 8;
            uint32_t off = (uint32_t)(row * MG_STRIDE + cc * 16);
            cpa16(base + MG_AH + off, Ahi + ga);
            cpa16(base + MG_AL + off, Alo + ga);
            cpa16(base + MG_BH + off, Bhi + gb);
            cpa16(base + MG_BL + off, Blo + gb);
        }
    };

    float acc[2][8][4];
    #pragma unroll
    for (int a = 0; a < 2; a++)
        #pragma unroll
        for (int b = 0; b < 8; b++)
            #pragma unroll
            for (int c = 0; c < 4; c++) acc[a][b][c] = 0.f;

    const int arow = lane & 15, asel = lane >> 4;
    const int brow = lane & 7,  bsel = (lane >> 3) & 3;
    const int nch = K / 32;

    // prologue: stages 0 and 1 in flight
    load_stage(0, 0);  CP_COMMIT();
    load_stage(1, 32); CP_COMMIT();

    for (int c = 0; c < nch; c++) {
        CP_WAIT(1);             // stage c ready; stage c+1 may be in flight
        __syncthreads();        // all threads past compute of stage c-1
        if (c + 2 < nch) load_stage((c + 2) % 3, (c + 2) * 32);
        CP_COMMIT();            // uniform group numbering (may be empty)

        const uint32_t sb = smb + (c % 3) * MG_STAGE;

        uint32_t ah[2][2][4], al[2][2][4];
        #pragma unroll
        for (int ma = 0; ma < 2; ma++)
            #pragma unroll
            for (int ks = 0; ks < 2; ks++) {
                uint32_t off = (uint32_t)((wm * 32 + ma * 16 + arow) * MG_STRIDE
                                          + ks * 32 + asel * 16);
                ldmx4(ah[ma][ks], sb + MG_AH + off);
                ldmx4(al[ma][ks], sb + MG_AL + off);
            }

        #pragma unroll
        for (int na = 0; na < 8; na++) {
            uint32_t boff = (uint32_t)((wn * 64 + na * 8 + brow) * MG_STRIDE + bsel * 16);
            uint32_t bh4[4], bl4[4];
            ldmx4(bh4, sb + MG_BH + boff);
            #pragma unroll
            for (int ma = 0; ma < 2; ma++) {
                mma_bf16(acc[ma][na], ah[ma][0], bh4[0], bh4[1]);
                mma_bf16(acc[ma][na], ah[ma][1], bh4[2], bh4[3]);
                mma_bf16(acc[ma][na], al[ma][0], bh4[0], bh4[1]);
                mma_bf16(acc[ma][na], al[ma][1], bh4[2], bh4[3]);
            }
            ldmx4(bl4, sb + MG_BL + boff);
            #pragma unroll
            for (int ma = 0; ma < 2; ma++) {
                mma_bf16(acc[ma][na], ah[ma][0], bl4[0], bl4[1]);
                mma_bf16(acc[ma][na], ah[ma][1], bl4[2], bl4[3]);
            }
        }
    }

    const int rg = lane >> 2, cg = lane & 3;
    #pragma unroll
    for (int ma = 0; ma < 2; ma++) {
        int row = m0 + wm * 32 + ma * 16 + rg;
        #pragma unroll
        for (int na = 0; na < 8; na++) {
            int col = n0 + wn * 64 + na * 8 + 2 * cg;
            float b0 = bias ? bias[col] : 0.f;
            float b1 = bias ? bias[col + 1] : 0.f;
            *reinterpret_cast<float2*>(Cmat + (size_t)row * ldc + col) =
                make_float2(acc[ma][na][0] + b0, acc[ma][na][1] + b1);
            *reinterpret_cast<float2*>(Cmat + (size_t)(row + 8) * ldc + col) =
                make_float2(acc[ma][na][2] + b0, acc[ma][na][3] + b1);
        }
    }
}

// ---------------------------------------------------------------------------
// RoPE + transpose + bf16 split. K=rope(k), Q=rope(v)*scale (faithful bug), V=v.
// ---------------------------------------------------------------------------
__global__ __launch_bounds__(256) void rope_split_kernel(
    const float* __restrict__ tmp,
    const float* __restrict__ cosb, const float* __restrict__ sinb,
    bf16* __restrict__ Kh, bf16* __restrict__ Kl,
    bf16* __restrict__ Qh, bf16* __restrict__ Ql,
    bf16* __restrict__ Vh, bf16* __restrict__ Vl)
{
    int idx = blockIdx.x * blockDim.x + threadIdx.x;
    if (idx >= Mz * Hz * (Dz / 2)) return;
    int i = idx & 31;
    int h = (idx >> 5) % Hz;
    int m = idx / (Hz * 32);
    int b = m >> 11;
    int t = m & (Tz - 1);

    const float* row = tmp + (size_t)m * 1536;
    float kr = row[h * Dz + 2 * i];
    float ki = row[h * Dz + 2 * i + 1];
    float vr = row[768 + h * Dz + 2 * i];
    float vi = row[768 + h * Dz + 2 * i + 1];

    float c = cosb[t * 32 + i];
    float s = sinb[t * 32 + i];

    size_t o = ((size_t)(b * Hz + h) * Tz + t) * Dz + 2 * i;
    const float scale = 0.125f;   // D^-0.5, folded into Q
    bsplit(kr * c - ki * s, Kh + o,     Kl + o);
    bsplit(kr * s + ki * c, Kh + o + 1, Kl + o + 1);
    bsplit((vr * c - vi * s) * scale, Qh + o,     Ql + o);
    bsplit((vr * s + vi * c) * scale, Qh + o + 1, Ql + o + 1);
    bsplit(vr, Vh + o,     Vl + o);
    bsplit(vi, Vh + o + 1, Vl + o + 1);
}

// ---------------------------------------------------------------------------
// Flash attention via mma.sync, 2-stage cp.async on K/V tiles.
// 128 q-rows x 128 keys, 8 warps x 16 q-rows. Epilogue emits split bf16
// (feeds proj GEMM directly — no fp32 round trip).
// ---------------------------------------------------------------------------
#define FL_STRIDE 144                // 64 bf16 = 128B + 16B pad
#define FL_TILE   (128 * FL_STRIDE)  // 18432
#define FL_STAGE  (4 * FL_TILE)      // KH,KL,VH,VL = 73728
#define FL_Q      (2 * FL_STAGE)     // 147456
#define FL4_SMEM  (FL_Q + 2 * FL_TILE)   // 184320

__global__ __launch_bounds__(256) void flash4_kernel(
    const bf16* __restrict__ Qh, const bf16* __restrict__ Ql,
    const bf16* __restrict__ Kh, const bf16* __restrict__ Kl,
    const bf16* __restrict__ Vh, const bf16* __restrict__ Vl,
    bf16* __restrict__ Ohi, bf16* __restrict__ Olo)
{
    extern __shared__ __align__(16) char sm4[];
    const uint32_t smb = smem_u32(sm4);
    const int tid  = threadIdx.x;
    const int w    = tid >> 5;
    const int lane = tid & 31;
    const int qt   = (int)gridDim.x - 1 - (int)blockIdx.x;   // heavy tiles first
    const int bh   = blockIdx.y;
    const size_t hb = (size_t)bh * Tz * Dz;

    auto load_kv = [&](int s, int j) {
        uint32_t base = smb + s * FL_STAGE;
        const size_t kb = hb + (size_t)j * 128 * 64;
        #pragma unroll
        for (int it = 0; it < 4; it++) {
            int u = tid + it * 256;
            int row = u >> 3, cc = u & 7;
            uint32_t off = (uint32_t)(row * FL_STRIDE + cc * 16);
            size_t g = kb + row * 64 + cc * 8;
            cpa16(base + 0 * FL_TILE + off, Kh + g);
            cpa16(base + 1 * FL_TILE + off, Kl + g);
            cpa16(base + 2 * FL_TILE + off, Vh + g);
            cpa16(base + 3 * FL_TILE + off, Vl + g);
        }
    };

    // Q tile (hi/lo) via regular loads; start K/V prefetch for jt=0 first.
    load_kv(0, 0);
    CP_COMMIT();
    {
        const bf16* qh = Qh + hb + (size_t)qt * 128 * 64;
        const bf16* ql = Ql + hb + (size_t)qt * 128 * 64;
        #pragma unroll
        for (int it = 0; it < 4; it++) {
            int u = tid + it * 256;
            int row = u >> 3, cc = u & 7;
            char* d = sm4 + FL_Q + row * FL_STRIDE + cc * 16;
            *reinterpret_cast<uint4*>(d) =
                *reinterpret_cast<const uint4*>(qh + row * 64 + cc * 8);
            *reinterpret_cast<uint4*>(d + FL_TILE) =
                *reinterpret_cast<const uint4*>(ql + row * 64 + cc * 8);
        }
    }
    __syncthreads();

    uint32_t qfh[16], qfl[16];
    {
        int arow = lane & 15, asel = lane >> 4;
        #pragma unroll
        for (int ka = 0; ka < 4; ka++) {
            uint32_t off = (uint32_t)((16 * w + arow) * FL_STRIDE + ka * 32 + asel * 16);
            ldmx4(qfh + ka * 4, smb + FL_Q + off);
            ldmx4(qfl + ka * 4, smb + FL_Q + FL_TILE + off);
        }
    }

    float o[8][4];
    #pragma unroll
    for (int nv = 0; nv < 8; nv++)
        #pragma unroll
        for (int c = 0; c < 4; c++) o[nv][c] = 0.f;
    float mA = -1e30f, mB = -1e30f, lA = 0.f, lB = 0.f;

    const int rg = lane >> 2, cg = lane & 3;
    const int brow = lane & 7, bsel = (lane >> 3) & 3;
    const int vkey = lane & 15, vsel = lane >> 4;

    for (int jt = 0; jt <= qt; jt++) {
        if (jt < qt) load_kv((jt + 1) & 1, jt + 1);
        CP_COMMIT();
        CP_WAIT(1);             // stage jt ready; jt+1 in flight
        __syncthreads();

        const uint32_t sb = smb + (jt & 1) * FL_STAGE;

        // ---- S = Q@K^T (bf16x3) ----
        float s[16][4];
        #pragma unroll
        for (int na = 0; na < 16; na++)
            #pragma unroll
            for (int c = 0; c < 4; c++) s[na][c] = 0.f;

        #pragma unroll
        for (int na = 0; na < 16; na++) {
            #pragma unroll
            for (int kp = 0; kp < 2; kp++) {
                uint32_t off = (uint32_t)((na * 8 + brow) * FL_STRIDE + kp * 64 + bsel * 16);
                uint32_t kh4[4], kl4[4];
                ldmx4(kh4, sb + 0 * FL_TILE + off);
                mma_bf16(s[na], qfh + (2 * kp) * 4,     kh4[0], kh4[1]);
                mma_bf16(s[na], qfh + (2 * kp + 1) * 4, kh4[2], kh4[3]);
                mma_bf16(s[na], qfl + (2 * kp) * 4,     kh4[0], kh4[1]);
                mma_bf16(s[na], qfl + (2 * kp + 1) * 4, kh4[2], kh4[3]);
                ldmx4(kl4, sb + 1 * FL_TILE + off);
                mma_bf16(s[na], qfh + (2 * kp) * 4,     kl4[0], kl4[1]);
                mma_bf16(s[na], qfh + (2 * kp + 1) * 4, kl4[2], kl4[3]);
            }
        }

        // ---- causal mask (diagonal tile) ----
        if (jt == qt) {
            int rA = 16 * w + rg, rB = rA + 8;
            #pragma unroll
            for (int na = 0; na < 16; na++) {
                int c0 = 8 * na + 2 * cg;
                if (c0 > rA)     s[na][0] = -1e30f;
                if (c0 + 1 > rA) s[na][1] = -1e30f;
                if (c0 > rB)     s[na][2] = -1e30f;
                if (c0 + 1 > rB) s[na][3] = -1e30f;
            }
        }

        // ---- online softmax ----
        float xA = -1e30f, xB = -1e30f;
        #pragma unroll
        for (int na = 0; na < 16; na++) {
            xA = fmaxf(xA, fmaxf(s[na][0], s[na][1]));
            xB = fmaxf(xB, fmaxf(s[na][2], s[na][3]));
        }
        xA = fmaxf(xA, __shfl_xor_sync(0xffffffffu, xA, 1));
        xA = fmaxf(xA, __shfl_xor_sync(0xffffffffu, xA, 2));
        xB = fmaxf(xB, __shfl_xor_sync(0xffffffffu, xB, 1));
        xB = fmaxf(xB, __shfl_xor_sync(0xffffffffu, xB, 2));
        float nmA = fmaxf(mA, xA), nmB = fmaxf(mB, xB);
        float cA = __expf(mA - nmA), cB = __expf(mB - nmB);
        mA = nmA; mB = nmB;
        #pragma unroll
        for (int nv = 0; nv < 8; nv++) {
            o[nv][0] *= cA; o[nv][1] *= cA;
            o[nv][2] *= cB; o[nv][3] *= cB;
        }
        float sA = 0.f, sB = 0.f;

        // ---- exp + in-register P conversion + PV mma ----
        #pragma unroll
        for (int ka = 0; ka < 8; ka++) {
            float e00 = __expf(s[2 * ka][0] - nmA);
            float e01 = __expf(s[2 * ka][1] - nmA);
            float e02 = __expf(s[2 * ka][2] - nmB);
            float e03 = __expf(s[2 * ka][3] - nmB);
            float e10 = __expf(s[2 * ka + 1][0] - nmA);
            float e11 = __expf(s[2 * ka + 1][1] - nmA);
            float e12 = __expf(s[2 * ka + 1][2] - nmB);
            float e13 = __expf(s[2 * ka + 1][3] - nmB);
            sA += (e00 + e01) + (e10 + e11);
            sB += (e02 + e03) + (e12 + e13);

            uint32_t pah[4], pal[4];
            pah[0] = pack_hi_trunc(e00, e01);
            pah[1] = pack_hi_trunc(e02, e03);
            pah[2] = pack_hi_trunc(e10, e11);
            pah[3] = pack_hi_trunc(e12, e13);
            pal[0] = pack_lo_rn(e00, e01);
            pal[1] = pack_lo_rn(e02, e03);
            pal[2] = pack_lo_rn(e10, e11);
            pal[3] = pack_lo_rn(e12, e13);

            #pragma unroll
            for (int nv = 0; nv < 4; nv++) {
                uint32_t voff = (uint32_t)((ka * 16 + vkey) * FL_STRIDE
                                           + (nv * 16 + vsel * 8) * 2);
                uint32_t vh4[4], vl4[4];
                ldmx4t(vh4, sb + 2 * FL_TILE + voff);
                mma_bf16(o[2 * nv],     pah, vh4[0], vh4[1]);
                mma_bf16(o[2 * nv + 1], pah, vh4[2], vh4[3]);
                mma_bf16(o[2 * nv],     pal, vh4[0], vh4[1]);
                mma_bf16(o[2 * nv + 1], pal, vh4[2], vh4[3]);
                ldmx4t(vl4, sb + 3 * FL_TILE + voff);
                mma_bf16(o[2 * nv],     pah, vl4[0], vl4[1]);
                mma_bf16(o[2 * nv + 1], pah, vl4[2], vl4[3]);
            }
        }
        sA += __shfl_xor_sync(0xffffffffu, sA, 1);
        sA += __shfl_xor_sync(0xffffffffu, sA, 2);
        sB += __shfl_xor_sync(0xffffffffu, sB, 1);
        sB += __shfl_xor_sync(0xffffffffu, sB, 2);
        lA = lA * cA + sA;
        lB = lB * cB + sB;

        __syncthreads();   // protect stage (jt&1) from next iter's prefetch
    }

    // ---- normalize + split + write bf16 [B,T,C] hi/lo ----
    const int b = bh / Hz, h = bh % Hz;
    const float invA = 1.f / lA, invB = 1.f / lB;
    int rA = qt * 128 + 16 * w + rg;
    #pragma unroll
    for (int nv = 0; nv < 8; nv++) {
        int col = h * 64 + nv * 8 + 2 * cg;
        size_t baseA = (size_t)(b * Tz + rA) * Cz + col;
        size_t baseB = (size_t)(b * Tz + rA + 8) * Cz + col;
        float v0 = o[nv][0] * invA, v1 = o[nv][1] * invA;
        float v2 = o[nv][2] * invB, v3 = o[nv][3] * invB;
        bf16 h0, l0, h1, l1, h2, l2, h3, l3;
        bsplit(v0, &h0, &l0); bsplit(v1, &h1, &l1);
        bsplit(v2, &h2, &l2); bsplit(v3, &h3, &l3);
        *reinterpret_cast<__nv_bfloat162*>(Ohi + baseA) = __nv_bfloat162(h0, h1);
        *reinterpret_cast<__nv_bfloat162*>(Olo + baseA) = __nv_bfloat162(l0, l1);
        *reinterpret_cast<__nv_bfloat162*>(Ohi + baseB) = __nv_bfloat162(h2, h3);
        *reinterpret_cast<__nv_bfloat162*>(Olo + baseB) = __nv_bfloat162(l2, l3);
    }
}

// ---------------------------------------------------------------------------
// kernel_launch
// ---------------------------------------------------------------------------
extern "C" void kernel_launch(void* const* d_in, const int* in_sizes, int n_in,
                              void* d_out, int out_size)
{
    const float* x      = (const float*)d_in[0];
    const float* cosb   = (const float*)d_in[1];
    const float* sinb   = (const float*)d_in[2];
    const float* W_att  = (const float*)d_in[3];
    const float* W_proj = (const float*)d_in[4];
    const float* b_proj = (const float*)d_in[5];
    float* out = (float*)d_out;

    float* tmp;
    cudaGetSymbolAddress((void**)&tmp, g_tmp);
    bf16 *xhi, *xlo, *ahi, *alo, *w1hi, *w1lo, *w2hi, *w2lo;
    cudaGetSymbolAddress((void**)&xhi, g_xhi);
    cudaGetSymbolAddress((void**)&xlo, g_xlo);
    cudaGetSymbolAddress((void**)&ahi, g_ahi);
    cudaGetSymbolAddress((void**)&alo, g_alo);
    cudaGetSymbolAddress((void**)&w1hi, g_w1hi);
    cudaGetSymbolAddress((void**)&w1lo, g_w1lo);
    cudaGetSymbolAddress((void**)&w2hi, g_w2hi);
    cudaGetSymbolAddress((void**)&w2lo, g_w2lo);
    bf16 *Khp, *Klp, *Qhp, *Qlp, *Vhp, *Vlp;
    cudaGetSymbolAddress((void**)&Khp, g_Kh);
    cudaGetSymbolAddress((void**)&Klp, g_Kl);
    cudaGetSymbolAddress((void**)&Qhp, g_Qh);
    cudaGetSymbolAddress((void**)&Qlp, g_Ql);
    cudaGetSymbolAddress((void**)&Vhp, g_Vh);
    cudaGetSymbolAddress((void**)&Vlp, g_Vl);

    cudaFuncSetAttribute(mm_gemm_kernel,
                         cudaFuncAttributeMaxDynamicSharedMemorySize, MG_SMEM);
    cudaFuncSetAttribute(flash4_kernel,
                         cudaFuncAttributeMaxDynamicSharedMemorySize, FL4_SMEM);

    // prep: bf16 splits
    split_rows_kernel<<<(Mz * Cz + 255) / 256, 256>>>(x, xhi, xlo, Mz * Cz);
    splitT_kernel<<<(1536 * Cz + 255) / 256, 256>>>(W_att, w1hi, w1lo, 1536, Cz, 3 * Cz, 768);
    splitT_kernel<<<(Cz * Cz + 255) / 256, 256>>>(W_proj, w2hi, w2lo, Cz, Cz, Cz, 1 << 30);

    // 1) QKV GEMM (k and v chunks only) -> g_tmp [4096,1536]
    mm_gemm_kernel<<<dim3(1536 / 128, Mz / 128), 256, MG_SMEM>>>(
        xhi, xlo, w1hi, w1lo, tmp, nullptr, Cz, 1536);

    // 2) RoPE + transpose + split -> [BH,T,D] bf16 hi/lo
    {
        int total = Mz * Hz * (Dz / 2);
        rope_split_kernel<<<(total + 255) / 256, 256>>>(
            tmp, cosb, sinb, Khp, Klp, Qhp, Qlp, Vhp, Vlp);
    }

    // 3) Flash attention (HMMA, cp.async) -> split bf16 directly
    flash4_kernel<<<dim3(Tz / 128, BHz), 256, FL4_SMEM>>>(
        Qhp, Qlp, Khp, Klp, Vhp, Vlp, ahi, alo);

    // 4) proj GEMM + bias -> d_out
    mm_gemm_kernel<<<dim3(Cz / 128, Mz / 128), 256, MG_SMEM>>>(
        ahi, alo, w2hi, w2lo, out, b_proj, Cz, Cz);
}

// round 6
// speedup vs baseline: 6.7659x; 1.0238x over previous
#include <cuda_runtime.h>
#include <cuda_bf16.h>
#include <cstdint>

// Problem constants
#define Bz 2
#define Tz 2048
#define Cz 768
#define Hz 12
#define Dz 64
#define BHz (Bz*Hz)        // 24
#define Mz (Bz*Tz)         // 4096

typedef __nv_bfloat16 bf16;

// ---------------------------------------------------------------------------
// Scratch (static device arrays — no cudaMalloc allowed)
// ---------------------------------------------------------------------------
__device__ float g_tmp[(size_t)Mz * 1536];        // QKV gemm out: k-chunk | v-chunk

__device__ bf16 g_xhi[(size_t)Mz * Cz],  g_xlo[(size_t)Mz * Cz];
__device__ bf16 g_ahi[(size_t)Mz * Cz],  g_alo[(size_t)Mz * Cz];
__device__ bf16 g_w1hi[(size_t)1536 * Cz], g_w1lo[(size_t)1536 * Cz];
__device__ bf16 g_w2hi[(size_t)Cz * Cz],   g_w2lo[(size_t)Cz * Cz];

// rope outputs, [BH, T, D] bf16 hi/lo
__device__ bf16 g_Kh[(size_t)BHz * Tz * Dz], g_Kl[(size_t)BHz * Tz * Dz];
__device__ bf16 g_Qh[(size_t)BHz * Tz * Dz], g_Ql[(size_t)BHz * Tz * Dz];
__device__ bf16 g_Vh[(size_t)BHz * Tz * Dz], g_Vl[(size_t)BHz * Tz * Dz];

// ---------------------------------------------------------------------------
// Warp-MMA + async-copy helpers (sm_80-compatible under plain sm_100 target)
// ---------------------------------------------------------------------------
__device__ __forceinline__ uint32_t smem_u32(const void* p) {
    uint32_t a;
    asm("{ .reg .u64 t; cvta.to.shared.u64 t, %1; cvt.u32.u64 %0, t; }"
        : "=r"(a) : "l"(p));
    return a;
}
__device__ __forceinline__ void mma_bf16(float* d, const uint32_t* a,
                                         uint32_t b0, uint32_t b1) {
    asm volatile(
        "mma.sync.aligned.m16n8k16.row.col.f32.bf16.bf16.f32 "
        "{%0,%1,%2,%3}, {%4,%5,%6,%7}, {%8,%9}, {%0,%1,%2,%3};"
        : "+f"(d[0]), "+f"(d[1]), "+f"(d[2]), "+f"(d[3])
        : "r"(a[0]), "r"(a[1]), "r"(a[2]), "r"(a[3]), "r"(b0), "r"(b1));
}
__device__ __forceinline__ void ldmx4(uint32_t* r, uint32_t addr) {
    asm volatile("ldmatrix.sync.aligned.m8n8.x4.shared.b16 {%0,%1,%2,%3}, [%4];"
        : "=r"(r[0]), "=r"(r[1]), "=r"(r[2]), "=r"(r[3]) : "r"(addr));
}
__device__ __forceinline__ void ldmx4t(uint32_t* r, uint32_t addr) {
    asm volatile("ldmatrix.sync.aligned.m8n8.x4.trans.shared.b16 {%0,%1,%2,%3}, [%4];"
        : "=r"(r[0]), "=r"(r[1]), "=r"(r[2]), "=r"(r[3]) : "r"(addr));
}
__device__ __forceinline__ void cpa16(uint32_t d, const void* s) {
    asm volatile("cp.async.cg.shared.global [%0], [%1], 16;" :: "r"(d), "l"(s));
}
#define CP_COMMIT() asm volatile("cp.async.commit_group;" ::: "memory")
#define CP_WAIT(n)  asm volatile("cp.async.wait_group %0;" :: "n"(n) : "memory")

// bf16 packing helpers
__device__ __forceinline__ uint32_t pack_hi_trunc(float a, float b) {
    return (__float_as_uint(b) & 0xFFFF0000u) | (__float_as_uint(a) >> 16);
}
__device__ __forceinline__ float trunc_bf(float a) {
    return __uint_as_float(__float_as_uint(a) & 0xFFFF0000u);
}
__device__ __forceinline__ uint32_t pack_lo_rn(float a, float b) {
    uint32_t u;
    float ra = a - trunc_bf(a), rb = b - trunc_bf(b);
    asm("cvt.rn.bf16x2.f32 %0, %1, %2;" : "=r"(u) : "f"(rb), "f"(ra));
    return u;
}
__device__ __forceinline__ void bsplit(float v, bf16* hp, bf16* lp) {
    bf16 h = __float2bfloat16(v);
    *hp = h;
    *lp = __float2bfloat16(v - __bfloat162float(h));
}

// ---------------------------------------------------------------------------
// bf16 split prep kernels
// ---------------------------------------------------------------------------
__global__ __launch_bounds__(256) void split_rows_kernel(
    const float* __restrict__ in, bf16* __restrict__ hi, bf16* __restrict__ lo, int n)
{
    int i = blockIdx.x * 256 + threadIdx.x;
    if (i >= n) return;
    float v = in[i];
    bf16 h = __float2bfloat16(v);
    hi[i] = h;
    lo[i] = __float2bfloat16(v - __bfloat162float(h));
}

// Tiled transpose+split: Wt[n][k] = W[k][col(n)]; coalesced both sides.
__global__ __launch_bounds__(256) void splitT_kernel(
    const float* __restrict__ W, bf16* __restrict__ hi, bf16* __restrict__ lo,
    int N, int K, int ldw, int nsplit)
{
    __shared__ float t[32][33];
    int tx = threadIdx.x & 31, ty = threadIdx.x >> 5;
    int n0 = blockIdx.x * 32;
    int k0 = blockIdx.y * 32;
    int col0 = n0 + (n0 >= nsplit ? 768 : 0);

    #pragma unroll
    for (int i = 0; i < 4; i++) {
        int k = k0 + ty + i * 8;
        t[ty + i * 8][tx] = W[(size_t)k * ldw + col0 + tx];
    }
    __syncthreads();
    #pragma unroll
    for (int i = 0; i < 4; i++) {
        int n = n0 + ty + i * 8;
        float v = t[tx][ty + i * 8];
        bf16 h = __float2bfloat16(v);
        size_t o = (size_t)n * K + k0 + tx;
        hi[o] = h;
        lo[o] = __float2bfloat16(v - __bfloat162float(h));
    }
}

// ---------------------------------------------------------------------------
// Dense GEMM via mma.sync, 2-stage cp.async pipeline, 2 CTAs/SM.
// C[M,N] = A[M,K] @ Bt[N,K]^T, bf16x3 split. 128x128x32 CTA, 8 warps.
// ---------------------------------------------------------------------------
#define MG_STRIDE 80            // 32 bf16 = 64B data + 16B pad
#define MG_AH 0
#define MG_AL 10240
#define MG_BH 20480
#define MG_BL 30720
#define MG_STAGE 40960
#define MG_SMEM (2 * MG_STAGE)  // 81920 -> 2 CTAs/SM

__global__ __launch_bounds__(256, 2) void mm_gemm_kernel(
    const bf16* __restrict__ Ahi, const bf16* __restrict__ Alo,
    const bf16* __restrict__ Bhi, const bf16* __restrict__ Blo,
    float* __restrict__ Cmat, const float* __restrict__ bias,
    int K, int ldc)
{
    extern __shared__ __align__(16) char gsm[];
    const uint32_t smb = smem_u32(gsm);
    const int tid  = threadIdx.x;
    const int w    = tid >> 5;
    const int lane = tid & 31;
    const int n0 = blockIdx.x * 128;
    const int m0 = blockIdx.y * 128;
    const int wm = w & 3;
    const int wn = w >> 2;

    auto load_stage = [&](int s, int kc) {
        uint32_t base = smb + s * MG_STAGE;
        #pragma unroll
        for (int it = 0; it < 2; it++) {
            int u   = tid + it * 256;
            int row = u >> 2, cc = u & 3;
            size_t ga = (size_t)(m0 + row) * K + kc + cc * 8;
            size_t gb = (size_t)(n0 + row) * K + kc + cc * 8;
            uint32_t off = (uint32_t)(row * MG_STRIDE + cc * 16);
            cpa16(base + MG_AH + off, Ahi + ga);
            cpa16(base + MG_AL + off, Alo + ga);
            cpa16(base + MG_BH + off, Bhi + gb);
            cpa16(base + MG_BL + off, Blo + gb);
        }
    };

    float acc[2][8][4];
    #pragma unroll
    for (int a = 0; a < 2; a++)
        #pragma unroll
        for (int b = 0; b < 8; b++)
            #pragma unroll
            for (int c = 0; c < 4; c++) acc[a][b][c] = 0.f;

    const int arow = lane & 15, asel = lane >> 4;
    const int brow = lane & 7,  bsel = (lane >> 3) & 3;
    const int nch = K / 32;

    load_stage(0, 0);  CP_COMMIT();
    load_stage(1, 32); CP_COMMIT();

    for (int c = 0; c < nch; c++) {
        CP_WAIT(1);             // oldest group (stage c) retired
        __syncthreads();

        const uint32_t sb = smb + (c & 1) * MG_STAGE;

        uint32_t ah[2][2][4], al[2][2][4];
        #pragma unroll
        for (int ma = 0; ma < 2; ma++)
            #pragma unroll
            for (int ks = 0; ks < 2; ks++) {
                uint32_t off = (uint32_t)((wm * 32 + ma * 16 + arow) * MG_STRIDE
                                          + ks * 32 + asel * 16);
                ldmx4(ah[ma][ks], sb + MG_AH + off);
                ldmx4(al[ma][ks], sb + MG_AL + off);
            }

        // prefetched B-fragment stream
        uint32_t bf4[2][8];
        auto ldB = [&](int na, uint32_t* dst) {
            uint32_t boff = (uint32_t)((wn * 64 + na * 8 + brow) * MG_STRIDE + bsel * 16);
            ldmx4(dst,     sb + MG_BH + boff);
            ldmx4(dst + 4, sb + MG_BL + boff);
        };
        ldB(0, bf4[0]);
        #pragma unroll
        for (int na = 0; na < 8; na++) {
            uint32_t* cur = bf4[na & 1];
            if (na + 1 < 8) ldB(na + 1, bf4[(na + 1) & 1]);
            #pragma unroll
            for (int ma = 0; ma < 2; ma++) {
                mma_bf16(acc[ma][na], ah[ma][0], cur[0], cur[1]);
                mma_bf16(acc[ma][na], ah[ma][1], cur[2], cur[3]);
                mma_bf16(acc[ma][na], al[ma][0], cur[0], cur[1]);
                mma_bf16(acc[ma][na], al[ma][1], cur[2], cur[3]);
                mma_bf16(acc[ma][na], ah[ma][0], cur[4], cur[5]);
                mma_bf16(acc[ma][na], ah[ma][1], cur[6], cur[7]);
            }
        }

        __syncthreads();        // done reading stage c
        if (c + 2 < nch) load_stage(c & 1, (c + 2) * 32);
        CP_COMMIT();            // uniform group numbering (may be empty)
    }

    const int rg = lane >> 2, cg = lane & 3;
    #pragma unroll
    for (int ma = 0; ma < 2; ma++) {
        int row = m0 + wm * 32 + ma * 16 + rg;
        #pragma unroll
        for (int na = 0; na < 8; na++) {
            int col = n0 + wn * 64 + na * 8 + 2 * cg;
            float b0 = bias ? bias[col] : 0.f;
            float b1 = bias ? bias[col + 1] : 0.f;
            *reinterpret_cast<float2*>(Cmat + (size_t)row * ldc + col) =
                make_float2(acc[ma][na][0] + b0, acc[ma][na][1] + b1);
            *reinterpret_cast<float2*>(Cmat + (size_t)(row + 8) * ldc + col) =
                make_float2(acc[ma][na][2] + b0, acc[ma][na][3] + b1);
        }
    }
}

// ---------------------------------------------------------------------------
// RoPE + transpose + bf16 split. K=rope(k), Q=rope(v)*scale (faithful bug), V=v.
// ---------------------------------------------------------------------------
__global__ __launch_bounds__(256) void rope_split_kernel(
    const float* __restrict__ tmp,
    const float* __restrict__ cosb, const float* __restrict__ sinb,
    bf16* __restrict__ Kh, bf16* __restrict__ Kl,
    bf16* __restrict__ Qh, bf16* __restrict__ Ql,
    bf16* __restrict__ Vh, bf16* __restrict__ Vl)
{
    int idx = blockIdx.x * blockDim.x + threadIdx.x;
    if (idx >= Mz * Hz * (Dz / 2)) return;
    int i = idx & 31;
    int h = (idx >> 5) % Hz;
    int m = idx / (Hz * 32);
    int b = m >> 11;
    int t = m & (Tz - 1);

    const float* row = tmp + (size_t)m * 1536;
    float kr = row[h * Dz + 2 * i];
    float ki = row[h * Dz + 2 * i + 1];
    float vr = row[768 + h * Dz + 2 * i];
    float vi = row[768 + h * Dz + 2 * i + 1];

    float c = cosb[t * 32 + i];
    float s = sinb[t * 32 + i];

    size_t o = ((size_t)(b * Hz + h) * Tz + t) * Dz + 2 * i;
    const float scale = 0.125f;   // D^-0.5, folded into Q
    bsplit(kr * c - ki * s, Kh + o,     Kl + o);
    bsplit(kr * s + ki * c, Kh + o + 1, Kl + o + 1);
    bsplit((vr * c - vi * s) * scale, Qh + o,     Ql + o);
    bsplit((vr * s + vi * c) * scale, Qh + o + 1, Ql + o + 1);
    bsplit(vr, Vh + o,     Vl + o);
    bsplit(vi, Vh + o + 1, Vl + o + 1);
}

// ---------------------------------------------------------------------------
// Flash attention via mma.sync, 2-stage cp.async on K/V, fragment prefetch.
// 128 q-rows x 128 keys, 8 warps x 16 q-rows. Epilogue emits split bf16.
// ---------------------------------------------------------------------------
#define FL_STRIDE 144                // 64 bf16 = 128B + 16B pad
#define FL_TILE   (128 * FL_STRIDE)  // 18432
#define FL_STAGE  (4 * FL_TILE)      // KH,KL,VH,VL = 73728
#define FL_Q      (2 * FL_STAGE)     // 147456
#define FL4_SMEM  (FL_Q + 2 * FL_TILE)   // 184320

__global__ __launch_bounds__(256) void flash4_kernel(
    const bf16* __restrict__ Qh, const bf16* __restrict__ Ql,
    const bf16* __restrict__ Kh, const bf16* __restrict__ Kl,
    const bf16* __restrict__ Vh, const bf16* __restrict__ Vl,
    bf16* __restrict__ Ohi, bf16* __restrict__ Olo)
{
    extern __shared__ __align__(16) char sm4[];
    const uint32_t smb = smem_u32(sm4);
    const int tid  = threadIdx.x;
    const int w    = tid >> 5;
    const int lane = tid & 31;
    const int qt   = (int)gridDim.x - 1 - (int)blockIdx.x;   // heavy tiles first
    const int bh   = blockIdx.y;
    const size_t hb = (size_t)bh * Tz * Dz;

    auto load_kv = [&](int s, int j) {
        uint32_t base = smb + s * FL_STAGE;
        const size_t kb = hb + (size_t)j * 128 * 64;
        #pragma unroll
        for (int it = 0; it < 4; it++) {
            int u = tid + it * 256;
            int row = u >> 3, cc = u & 7;
            uint32_t off = (uint32_t)(row * FL_STRIDE + cc * 16);
            size_t g = kb + row * 64 + cc * 8;
            cpa16(base + 0 * FL_TILE + off, Kh + g);
            cpa16(base + 1 * FL_TILE + off, Kl + g);
            cpa16(base + 2 * FL_TILE + off, Vh + g);
            cpa16(base + 3 * FL_TILE + off, Vl + g);
        }
    };

    load_kv(0, 0);
    CP_COMMIT();
    {
        const bf16* qh = Qh + hb + (size_t)qt * 128 * 64;
        const bf16* ql = Ql + hb + (size_t)qt * 128 * 64;
        #pragma unroll
        for (int it = 0; it < 4; it++) {
            int u = tid + it * 256;
            int row = u >> 3, cc = u & 7;
            char* d = sm4 + FL_Q + row * FL_STRIDE + cc * 16;
            *reinterpret_cast<uint4*>(d) =
                *reinterpret_cast<const uint4*>(qh + row * 64 + cc * 8);
            *reinterpret_cast<uint4*>(d + FL_TILE) =
                *reinterpret_cast<const uint4*>(ql + row * 64 + cc * 8);
        }
    }
    __syncthreads();

    uint32_t qfh[16], qfl[16];
    {
        int arow = lane & 15, asel = lane >> 4;
        #pragma unroll
        for (int ka = 0; ka < 4; ka++) {
            uint32_t off = (uint32_t)((16 * w + arow) * FL_STRIDE + ka * 32 + asel * 16);
            ldmx4(qfh + ka * 4, smb + FL_Q + off);
            ldmx4(qfl + ka * 4, smb + FL_Q + FL_TILE + off);
        }
    }

    float o[8][4];
    #pragma unroll
    for (int nv = 0; nv < 8; nv++)
        #pragma unroll
        for (int c = 0; c < 4; c++) o[nv][c] = 0.f;
    float mA = -1e30f, mB = -1e30f, lA = 0.f, lB = 0.f;

    const int rg = lane >> 2, cg = lane & 3;
    const int brow = lane & 7, bsel = (lane >> 3) & 3;
    const int vkey = lane & 15, vsel = lane >> 4;

    for (int jt = 0; jt <= qt; jt++) {
        if (jt < qt) load_kv((jt + 1) & 1, jt + 1);
        CP_COMMIT();
        CP_WAIT(1);
        __syncthreads();

        const uint32_t sb = smb + (jt & 1) * FL_STAGE;

        // ---- S = Q@K^T (bf16x3), prefetched K-fragment stream ----
        float s[16][4];
        #pragma unroll
        for (int na = 0; na < 16; na++)
            #pragma unroll
            for (int c = 0; c < 4; c++) s[na][c] = 0.f;

        {
            uint32_t kf[2][8];
            auto ldK = [&](int idx, uint32_t* dst) {
                int na = idx >> 1, kp = idx & 1;
                uint32_t off = (uint32_t)((na * 8 + brow) * FL_STRIDE + kp * 64 + bsel * 16);
                ldmx4(dst,     sb + 0 * FL_TILE + off);
                ldmx4(dst + 4, sb + 1 * FL_TILE + off);
            };
            ldK(0, kf[0]);
            #pragma unroll
            for (int idx = 0; idx < 32; idx++) {
                uint32_t* cur = kf[idx & 1];
                if (idx + 1 < 32) ldK(idx + 1, kf[(idx + 1) & 1]);
                int na = idx >> 1, kp = idx & 1;
                mma_bf16(s[na], qfh + (2 * kp) * 4,     cur[0], cur[1]);
                mma_bf16(s[na], qfh + (2 * kp + 1) * 4, cur[2], cur[3]);
                mma_bf16(s[na], qfl + (2 * kp) * 4,     cur[0], cur[1]);
                mma_bf16(s[na], qfl + (2 * kp + 1) * 4, cur[2], cur[3]);
                mma_bf16(s[na], qfh + (2 * kp) * 4,     cur[4], cur[5]);
                mma_bf16(s[na], qfh + (2 * kp + 1) * 4, cur[6], cur[7]);
            }
        }

        // ---- causal mask (diagonal tile) ----
        if (jt == qt) {
            int rA = 16 * w + rg, rB = rA + 8;
            #pragma unroll
            for (int na = 0; na < 16; na++) {
                int c0 = 8 * na + 2 * cg;
                if (c0 > rA)     s[na][0] = -1e30f;
                if (c0 + 1 > rA) s[na][1] = -1e30f;
                if (c0 > rB)     s[na][2] = -1e30f;
                if (c0 + 1 > rB) s[na][3] = -1e30f;
            }
        }

        // ---- online softmax ----
        float xA = -1e30f, xB = -1e30f;
        #pragma unroll
        for (int na = 0; na < 16; na++) {
            xA = fmaxf(xA, fmaxf(s[na][0], s[na][1]));
            xB = fmaxf(xB, fmaxf(s[na][2], s[na][3]));
        }
        xA = fmaxf(xA, __shfl_xor_sync(0xffffffffu, xA, 1));
        xA = fmaxf(xA, __shfl_xor_sync(0xffffffffu, xA, 2));
        xB = fmaxf(xB, __shfl_xor_sync(0xffffffffu, xB, 1));
        xB = fmaxf(xB, __shfl_xor_sync(0xffffffffu, xB, 2));
        float nmA = fmaxf(mA, xA), nmB = fmaxf(mB, xB);
        float cA = __expf(mA - nmA), cB = __expf(mB - nmB);
        mA = nmA; mB = nmB;
        #pragma unroll
        for (int nv = 0; nv < 8; nv++) {
            o[nv][0] *= cA; o[nv][1] *= cA;
            o[nv][2] *= cB; o[nv][3] *= cB;
        }

        // ---- exp + pack all P fragments (s dies here) ----
        float sA = 0.f, sB = 0.f;
        uint32_t pah[8][4], pal[8][4];
        #pragma unroll
        for (int ka = 0; ka < 8; ka++) {
            float e00 = __expf(s[2 * ka][0] - nmA);
            float e01 = __expf(s[2 * ka][1] - nmA);
            float e02 = __expf(s[2 * ka][2] - nmB);
            float e03 = __expf(s[2 * ka][3] - nmB);
            float e10 = __expf(s[2 * ka + 1][0] - nmA);
            float e11 = __expf(s[2 * ka + 1][1] - nmA);
            float e12 = __expf(s[2 * ka + 1][2] - nmB);
            float e13 = __expf(s[2 * ka + 1][3] - nmB);
            sA += (e00 + e01) + (e10 + e11);
            sB += (e02 + e03) + (e12 + e13);
            pah[ka][0] = pack_hi_trunc(e00, e01);
            pah[ka][1] = pack_hi_trunc(e02, e03);
            pah[ka][2] = pack_hi_trunc(e10, e11);
            pah[ka][3] = pack_hi_trunc(e12, e13);
            pal[ka][0] = pack_lo_rn(e00, e01);
            pal[ka][1] = pack_lo_rn(e02, e03);
            pal[ka][2] = pack_lo_rn(e10, e11);
            pal[ka][3] = pack_lo_rn(e12, e13);
        }
        sA += __shfl_xor_sync(0xffffffffu, sA, 1);
        sA += __shfl_xor_sync(0xffffffffu, sA, 2);
        sB += __shfl_xor_sync(0xffffffffu, sB, 1);
        sB += __shfl_xor_sync(0xffffffffu, sB, 2);
        lA = lA * cA + sA;
        lB = lB * cB + sB;

        // ---- PV mma, prefetched V-fragment stream ----
        {
            uint32_t vf[2][8];
            auto ldV = [&](int idx, uint32_t* dst) {
                int ka = idx >> 2, nv = idx & 3;
                uint32_t voff = (uint32_t)((ka * 16 + vkey) * FL_STRIDE
                                           + (nv * 16 + vsel * 8) * 2);
                ldmx4t(dst,     sb + 2 * FL_TILE + voff);
                ldmx4t(dst + 4, sb + 3 * FL_TILE + voff);
            };
            ldV(0, vf[0]);
            #pragma unroll
            for (int idx = 0; idx < 32; idx++) {
                uint32_t* cur = vf[idx & 1];
                if (idx + 1 < 32) ldV(idx + 1, vf[(idx + 1) & 1]);
                int ka = idx >> 2, nv = idx & 3;
                mma_bf16(o[2 * nv],     pah[ka], cur[0], cur[1]);
                mma_bf16(o[2 * nv + 1], pah[ka], cur[2], cur[3]);
                mma_bf16(o[2 * nv],     pal[ka], cur[0], cur[1]);
                mma_bf16(o[2 * nv + 1], pal[ka], cur[2], cur[3]);
                mma_bf16(o[2 * nv],     pah[ka], cur[4], cur[5]);
                mma_bf16(o[2 * nv + 1], pah[ka], cur[6], cur[7]);
            }
        }

        __syncthreads();   // protect stage (jt&1) from next iter's prefetch
    }

    // ---- normalize + split + write bf16 [B,T,C] hi/lo ----
    const int b = bh / Hz, h = bh % Hz;
    const float invA = 1.f / lA, invB = 1.f / lB;
    int rA = qt * 128 + 16 * w + rg;
    #pragma unroll
    for (int nv = 0; nv < 8; nv++) {
        int col = h * 64 + nv * 8 + 2 * cg;
        size_t baseA = (size_t)(b * Tz + rA) * Cz + col;
        size_t baseB = (size_t)(b * Tz + rA + 8) * Cz + col;
        float v0 = o[nv][0] * invA, v1 = o[nv][1] * invA;
        float v2 = o[nv][2] * invB, v3 = o[nv][3] * invB;
        bf16 h0, l0, h1, l1, h2, l2, h3, l3;
        bsplit(v0, &h0, &l0); bsplit(v1, &h1, &l1);
        bsplit(v2, &h2, &l2); bsplit(v3, &h3, &l3);
        *reinterpret_cast<__nv_bfloat162*>(Ohi + baseA) = __nv_bfloat162(h0, h1);
        *reinterpret_cast<__nv_bfloat162*>(Olo + baseA) = __nv_bfloat162(l0, l1);
        *reinterpret_cast<__nv_bfloat162*>(Ohi + baseB) = __nv_bfloat162(h2, h3);
        *reinterpret_cast<__nv_bfloat162*>(Olo + baseB) = __nv_bfloat162(l2, l3);
    }
}

// ---------------------------------------------------------------------------
// kernel_launch
// ---------------------------------------------------------------------------
extern "C" void kernel_launch(void* const* d_in, const int* in_sizes, int n_in,
                              void* d_out, int out_size)
{
    const float* x      = (const float*)d_in[0];
    const float* cosb   = (const float*)d_in[1];
    const float* sinb   = (const float*)d_in[2];
    const float* W_att  = (const float*)d_in[3];
    const float* W_proj = (const float*)d_in[4];
    const float* b_proj = (const float*)d_in[5];
    float* out = (float*)d_out;

    float* tmp;
    cudaGetSymbolAddress((void**)&tmp, g_tmp);
    bf16 *xhi, *xlo, *ahi, *alo, *w1hi, *w1lo, *w2hi, *w2lo;
    cudaGetSymbolAddress((void**)&xhi, g_xhi);
    cudaGetSymbolAddress((void**)&xlo, g_xlo);
    cudaGetSymbolAddress((void**)&ahi, g_ahi);
    cudaGetSymbolAddress((void**)&alo, g_alo);
    cudaGetSymbolAddress((void**)&w1hi, g_w1hi);
    cudaGetSymbolAddress((void**)&w1lo, g_w1lo);
    cudaGetSymbolAddress((void**)&w2hi, g_w2hi);
    cudaGetSymbolAddress((void**)&w2lo, g_w2lo);
    bf16 *Khp, *Klp, *Qhp, *Qlp, *Vhp, *Vlp;
    cudaGetSymbolAddress((void**)&Khp, g_Kh);
    cudaGetSymbolAddress((void**)&Klp, g_Kl);
    cudaGetSymbolAddress((void**)&Qhp, g_Qh);
    cudaGetSymbolAddress((void**)&Qlp, g_Ql);
    cudaGetSymbolAddress((void**)&Vhp, g_Vh);
    cudaGetSymbolAddress((void**)&Vlp, g_Vl);

    cudaFuncSetAttribute(mm_gemm_kernel,
                         cudaFuncAttributeMaxDynamicSharedMemorySize, MG_SMEM);
    cudaFuncSetAttribute(flash4_kernel,
                         cudaFuncAttributeMaxDynamicSharedMemorySize, FL4_SMEM);

    // prep: bf16 splits
    split_rows_kernel<<<(Mz * Cz + 255) / 256, 256>>>(x, xhi, xlo, Mz * Cz);
    splitT_kernel<<<dim3(1536 / 32, Cz / 32), 256>>>(W_att, w1hi, w1lo, 1536, Cz, 3 * Cz, 768);
    splitT_kernel<<<dim3(Cz / 32, Cz / 32), 256>>>(W_proj, w2hi, w2lo, Cz, Cz, Cz, 1 << 30);

    // 1) QKV GEMM (k and v chunks only) -> g_tmp [4096,1536]
    mm_gemm_kernel<<<dim3(1536 / 128, Mz / 128), 256, MG_SMEM>>>(
        xhi, xlo, w1hi, w1lo, tmp, nullptr, Cz, 1536);

    // 2) RoPE + transpose + split -> [BH,T,D] bf16 hi/lo
    {
        int total = Mz * Hz * (Dz / 2);
        rope_split_kernel<<<(total + 255) / 256, 256>>>(
            tmp, cosb, sinb, Khp, Klp, Qhp, Qlp, Vhp, Vlp);
    }

    // 3) Flash attention (HMMA, cp.async, fragment prefetch) -> split bf16
    flash4_kernel<<<dim3(Tz / 128, BHz), 256, FL4_SMEM>>>(
        Qhp, Qlp, Khp, Klp, Vhp, Vlp, ahi, alo);

    // 4) proj GEMM + bias -> d_out
    mm_gemm_kernel<<<dim3(Cz / 128, Mz / 128), 256, MG_SMEM>>>(
        ahi, alo, w2hi, w2lo, out, b_proj, Cz, Cz);
}

// round 7
// speedup vs baseline: 6.8214x; 1.0082x over previous
#include <cuda_runtime.h>
#include <cuda_bf16.h>
#include <cstdint>

// Problem constants
#define Bz 2
#define Tz 2048
#define Cz 768
#define Hz 12
#define Dz 64
#define BHz (Bz*Hz)        // 24
#define Mz (Bz*Tz)         // 4096

typedef __nv_bfloat16 bf16;

// ---------------------------------------------------------------------------
// Scratch (static device arrays — no cudaMalloc allowed)
// ---------------------------------------------------------------------------
__device__ float g_tmp[(size_t)Mz * 1536];        // QKV gemm out: k-chunk | v-chunk

__device__ bf16 g_xhi[(size_t)Mz * Cz],  g_xlo[(size_t)Mz * Cz];
__device__ bf16 g_ahi[(size_t)Mz * Cz],  g_alo[(size_t)Mz * Cz];
__device__ bf16 g_w1hi[(size_t)1536 * Cz], g_w1lo[(size_t)1536 * Cz];
__device__ bf16 g_w2hi[(size_t)Cz * Cz],   g_w2lo[(size_t)Cz * Cz];

// rope outputs, [BH, T, D] bf16 hi/lo
__device__ bf16 g_Kh[(size_t)BHz * Tz * Dz], g_Kl[(size_t)BHz * Tz * Dz];
__device__ bf16 g_Qh[(size_t)BHz * Tz * Dz], g_Ql[(size_t)BHz * Tz * Dz];
__device__ bf16 g_Vh[(size_t)BHz * Tz * Dz], g_Vl[(size_t)BHz * Tz * Dz];

// ---------------------------------------------------------------------------
// Warp-MMA + async-copy helpers (sm_80-compatible under plain sm_100 target)
// ---------------------------------------------------------------------------
__device__ __forceinline__ uint32_t smem_u32(const void* p) {
    uint32_t a;
    asm("{ .reg .u64 t; cvta.to.shared.u64 t, %1; cvt.u32.u64 %0, t; }"
        : "=r"(a) : "l"(p));
    return a;
}
__device__ __forceinline__ void mma_bf16(float* d, const uint32_t* a,
                                         uint32_t b0, uint32_t b1) {
    asm volatile(
        "mma.sync.aligned.m16n8k16.row.col.f32.bf16.bf16.f32 "
        "{%0,%1,%2,%3}, {%4,%5,%6,%7}, {%8,%9}, {%0,%1,%2,%3};"
        : "+f"(d[0]), "+f"(d[1]), "+f"(d[2]), "+f"(d[3])
        : "r"(a[0]), "r"(a[1]), "r"(a[2]), "r"(a[3]), "r"(b0), "r"(b1));
}
__device__ __forceinline__ void ldmx4(uint32_t* r, uint32_t addr) {
    asm volatile("ldmatrix.sync.aligned.m8n8.x4.shared.b16 {%0,%1,%2,%3}, [%4];"
        : "=r"(r[0]), "=r"(r[1]), "=r"(r[2]), "=r"(r[3]) : "r"(addr));
}
__device__ __forceinline__ void ldmx4t(uint32_t* r, uint32_t addr) {
    asm volatile("ldmatrix.sync.aligned.m8n8.x4.trans.shared.b16 {%0,%1,%2,%3}, [%4];"
        : "=r"(r[0]), "=r"(r[1]), "=r"(r[2]), "=r"(r[3]) : "r"(addr));
}
__device__ __forceinline__ void cpa16(uint32_t d, const void* s) {
    asm volatile("cp.async.cg.shared.global [%0], [%1], 16;" :: "r"(d), "l"(s));
}
#define CP_COMMIT() asm volatile("cp.async.commit_group;" ::: "memory")
#define CP_WAIT(n)  asm volatile("cp.async.wait_group %0;" :: "n"(n) : "memory")

// bf16 packing helpers
__device__ __forceinline__ uint32_t pack_hi_trunc(float a, float b) {
    return (__float_as_uint(b) & 0xFFFF0000u) | (__float_as_uint(a) >> 16);
}
__device__ __forceinline__ float trunc_bf(float a) {
    return __uint_as_float(__float_as_uint(a) & 0xFFFF0000u);
}
__device__ __forceinline__ uint32_t pack_lo_rn(float a, float b) {
    uint32_t u;
    float ra = a - trunc_bf(a), rb = b - trunc_bf(b);
    asm("cvt.rn.bf16x2.f32 %0, %1, %2;" : "=r"(u) : "f"(rb), "f"(ra));
    return u;
}
__device__ __forceinline__ void bsplit(float v, bf16* hp, bf16* lp) {
    bf16 h = __float2bfloat16(v);
    *hp = h;
    *lp = __float2bfloat16(v - __bfloat162float(h));
}

// ---------------------------------------------------------------------------
// bf16 split prep kernels
// ---------------------------------------------------------------------------
__global__ __launch_bounds__(256) void split_rows_kernel(
    const float* __restrict__ in, bf16* __restrict__ hi, bf16* __restrict__ lo, int n)
{
    int i = blockIdx.x * 256 + threadIdx.x;
    if (i >= n) return;
    float v = in[i];
    bf16 h = __float2bfloat16(v);
    hi[i] = h;
    lo[i] = __float2bfloat16(v - __bfloat162float(h));
}

// Tiled transpose+split: Wt[n][k] = W[k][col(n)]; coalesced both sides.
__global__ __launch_bounds__(256) void splitT_kernel(
    const float* __restrict__ W, bf16* __restrict__ hi, bf16* __restrict__ lo,
    int N, int K, int ldw, int nsplit)
{
    __shared__ float t[32][33];
    int tx = threadIdx.x & 31, ty = threadIdx.x >> 5;
    int n0 = blockIdx.x * 32;
    int k0 = blockIdx.y * 32;
    int col0 = n0 + (n0 >= nsplit ? 768 : 0);

    #pragma unroll
    for (int i = 0; i < 4; i++) {
        int k = k0 + ty + i * 8;
        t[ty + i * 8][tx] = W[(size_t)k * ldw + col0 + tx];
    }
    __syncthreads();
    #pragma unroll
    for (int i = 0; i < 4; i++) {
        int n = n0 + ty + i * 8;
        float v = t[tx][ty + i * 8];
        bf16 h = __float2bfloat16(v);
        size_t o = (size_t)n * K + k0 + tx;
        hi[o] = h;
        lo[o] = __float2bfloat16(v - __bfloat162float(h));
    }
}

// ---------------------------------------------------------------------------
// Dense GEMM via mma.sync, 2-stage cp.async, 2 CTAs/SM, chain-free MMA order.
// C[M,N] = A[M,K] @ Bt[N,K]^T, bf16x3 split. 128x128x32 CTA, 8 warps.
// ---------------------------------------------------------------------------
#define MG_STRIDE 80            // 32 bf16 = 64B data + 16B pad
#define MG_AH 0
#define MG_AL 10240
#define MG_BH 20480
#define MG_BL 30720
#define MG_STAGE 40960
#define MG_SMEM (2 * MG_STAGE)  // 81920 -> 2 CTAs/SM

__global__ __launch_bounds__(256, 2) void mm_gemm_kernel(
    const bf16* __restrict__ Ahi, const bf16* __restrict__ Alo,
    const bf16* __restrict__ Bhi, const bf16* __restrict__ Blo,
    float* __restrict__ Cmat, const float* __restrict__ bias,
    int K, int ldc)
{
    extern __shared__ __align__(16) char gsm[];
    const uint32_t smb = smem_u32(gsm);
    const int tid  = threadIdx.x;
    const int w    = tid >> 5;
    const int lane = tid & 31;
    const int n0 = blockIdx.x * 128;
    const int m0 = blockIdx.y * 128;
    const int wm = w & 3;
    const int wn = w >> 2;

    auto load_stage = [&](int s, int kc) {
        uint32_t base = smb + s * MG_STAGE;
        #pragma unroll
        for (int it = 0; it < 2; it++) {
            int u   = tid + it * 256;
            int row = u >> 2, cc = u & 3;
            size_t ga = (size_t)(m0 + row) * K + kc + cc * 8;
            size_t gb = (size_t)(n0 + row) * K + kc + cc * 8;
            uint32_t off = (uint32_t)(row * MG_STRIDE + cc * 16);
            cpa16(base + MG_AH + off, Ahi + ga);
            cpa16(base + MG_AL + off, Alo + ga);
            cpa16(base + MG_BH + off, Bhi + gb);
            cpa16(base + MG_BL + off, Blo + gb);
        }
    };

    float acc[2][8][4];
    #pragma unroll
    for (int a = 0; a < 2; a++)
        #pragma unroll
        for (int b = 0; b < 8; b++)
            #pragma unroll
            for (int c = 0; c < 4; c++) acc[a][b][c] = 0.f;

    const int arow = lane & 15, asel = lane >> 4;
    const int brow = lane & 7,  bsel = (lane >> 3) & 3;
    const int nch = K / 32;

    load_stage(0, 0);  CP_COMMIT();
    load_stage(1, 32); CP_COMMIT();

    for (int c = 0; c < nch; c++) {
        CP_WAIT(1);
        __syncthreads();
        const uint32_t sb = smb + (c & 1) * MG_STAGE;

        uint32_t af[2][2][4];    // current A term (hi first, later lo)
        uint32_t bq[4][4];       // B quarter (4 na)

        #pragma unroll
        for (int ma = 0; ma < 2; ma++)
            #pragma unroll
            for (int ks = 0; ks < 2; ks++)
                ldmx4(af[ma][ks], sb + MG_AH +
                      (uint32_t)((wm * 32 + ma * 16 + arow) * MG_STRIDE + ks * 32 + asel * 16));

        // Phase 1: ah*bh and ah*bl, half of na at a time.
        #pragma unroll
        for (int half = 0; half < 2; half++) {
            #pragma unroll
            for (int q = 0; q < 4; q++)
                ldmx4(bq[q], sb + MG_BH +
                      (uint32_t)((wn * 64 + (half * 4 + q) * 8 + brow) * MG_STRIDE + bsel * 16));
            #pragma unroll
            for (int ks = 0; ks < 2; ks++)
                #pragma unroll
                for (int q = 0; q < 4; q++)
                    #pragma unroll
                    for (int ma = 0; ma < 2; ma++)
                        mma_bf16(acc[ma][half * 4 + q], af[ma][ks], bq[q][2 * ks], bq[q][2 * ks + 1]);

            #pragma unroll
            for (int q = 0; q < 4; q++)
                ldmx4(bq[q], sb + MG_BL +
                      (uint32_t)((wn * 64 + (half * 4 + q) * 8 + brow) * MG_STRIDE + bsel * 16));
            #pragma unroll
            for (int ks = 0; ks < 2; ks++)
                #pragma unroll
                for (int q = 0; q < 4; q++)
                    #pragma unroll
                    for (int ma = 0; ma < 2; ma++)
                        mma_bf16(acc[ma][half * 4 + q], af[ma][ks], bq[q][2 * ks], bq[q][2 * ks + 1]);
        }

        // Phase 2: al*bh
        #pragma unroll
        for (int ma = 0; ma < 2; ma++)
            #pragma unroll
            for (int ks = 0; ks < 2; ks++)
                ldmx4(af[ma][ks], sb + MG_AL +
                      (uint32_t)((wm * 32 + ma * 16 + arow) * MG_STRIDE + ks * 32 + asel * 16));
        #pragma unroll
        for (int half = 0; half < 2; half++) {
            #pragma unroll
            for (int q = 0; q < 4; q++)
                ldmx4(bq[q], sb + MG_BH +
                      (uint32_t)((wn * 64 + (half * 4 + q) * 8 + brow) * MG_STRIDE + bsel * 16));
            #pragma unroll
            for (int ks = 0; ks < 2; ks++)
                #pragma unroll
                for (int q = 0; q < 4; q++)
                    #pragma unroll
                    for (int ma = 0; ma < 2; ma++)
                        mma_bf16(acc[ma][half * 4 + q], af[ma][ks], bq[q][2 * ks], bq[q][2 * ks + 1]);
        }

        __syncthreads();
        if (c + 2 < nch) load_stage(c & 1, (c + 2) * 32);
        CP_COMMIT();
    }

    const int rg = lane >> 2, cg = lane & 3;
    #pragma unroll
    for (int ma = 0; ma < 2; ma++) {
        int row = m0 + wm * 32 + ma * 16 + rg;
        #pragma unroll
        for (int na = 0; na < 8; na++) {
            int col = n0 + wn * 64 + na * 8 + 2 * cg;
            float b0 = bias ? bias[col] : 0.f;
            float b1 = bias ? bias[col + 1] : 0.f;
            *reinterpret_cast<float2*>(Cmat + (size_t)row * ldc + col) =
                make_float2(acc[ma][na][0] + b0, acc[ma][na][1] + b1);
            *reinterpret_cast<float2*>(Cmat + (size_t)(row + 8) * ldc + col) =
                make_float2(acc[ma][na][2] + b0, acc[ma][na][3] + b1);
        }
    }
}

// ---------------------------------------------------------------------------
// RoPE + transpose + bf16 split. K=rope(k), Q=rope(v)*scale (faithful bug), V=v.
// ---------------------------------------------------------------------------
__global__ __launch_bounds__(256) void rope_split_kernel(
    const float* __restrict__ tmp,
    const float* __restrict__ cosb, const float* __restrict__ sinb,
    bf16* __restrict__ Kh, bf16* __restrict__ Kl,
    bf16* __restrict__ Qh, bf16* __restrict__ Ql,
    bf16* __restrict__ Vh, bf16* __restrict__ Vl)
{
    int idx = blockIdx.x * blockDim.x + threadIdx.x;
    if (idx >= Mz * Hz * (Dz / 2)) return;
    int i = idx & 31;
    int h = (idx >> 5) % Hz;
    int m = idx / (Hz * 32);
    int b = m >> 11;
    int t = m & (Tz - 1);

    const float* row = tmp + (size_t)m * 1536;
    float kr = row[h * Dz + 2 * i];
    float ki = row[h * Dz + 2 * i + 1];
    float vr = row[768 + h * Dz + 2 * i];
    float vi = row[768 + h * Dz + 2 * i + 1];

    float c = cosb[t * 32 + i];
    float s = sinb[t * 32 + i];

    size_t o = ((size_t)(b * Hz + h) * Tz + t) * Dz + 2 * i;
    const float scale = 0.125f;   // D^-0.5, folded into Q
    bsplit(kr * c - ki * s, Kh + o,     Kl + o);
    bsplit(kr * s + ki * c, Kh + o + 1, Kl + o + 1);
    bsplit((vr * c - vi * s) * scale, Qh + o,     Ql + o);
    bsplit((vr * s + vi * c) * scale, Qh + o + 1, Ql + o + 1);
    bsplit(vr, Vh + o,     Vl + o);
    bsplit(vi, Vh + o + 1, Vl + o + 1);
}

// ---------------------------------------------------------------------------
// Flash attention via mma.sync, 2-stage cp.async, chain-free MMA order.
// 128 q-rows x 128 keys, 8 warps x 16 q-rows. Epilogue emits split bf16.
// ---------------------------------------------------------------------------
#define FL_STRIDE 144                // 64 bf16 = 128B + 16B pad
#define FL_TILE   (128 * FL_STRIDE)  // 18432
#define FL_STAGE  (4 * FL_TILE)      // KH,KL,VH,VL = 73728
#define FL_Q      (2 * FL_STAGE)     // 147456
#define FL4_SMEM  (FL_Q + 2 * FL_TILE)   // 184320

__global__ __launch_bounds__(256) void flash4_kernel(
    const bf16* __restrict__ Qh, const bf16* __restrict__ Ql,
    const bf16* __restrict__ Kh, const bf16* __restrict__ Kl,
    const bf16* __restrict__ Vh, const bf16* __restrict__ Vl,
    bf16* __restrict__ Ohi, bf16* __restrict__ Olo)
{
    extern __shared__ __align__(16) char sm4[];
    const uint32_t smb = smem_u32(sm4);
    const int tid  = threadIdx.x;
    const int w    = tid >> 5;
    const int lane = tid & 31;
    const int qt   = (int)gridDim.x - 1 - (int)blockIdx.x;   // heavy tiles first
    const int bh   = blockIdx.y;
    const size_t hb = (size_t)bh * Tz * Dz;

    auto load_kv = [&](int s, int j) {
        uint32_t base = smb + s * FL_STAGE;
        const size_t kb = hb + (size_t)j * 128 * 64;
        #pragma unroll
        for (int it = 0; it < 4; it++) {
            int u = tid + it * 256;
            int row = u >> 3, cc = u & 7;
            uint32_t off = (uint32_t)(row * FL_STRIDE + cc * 16);
            size_t g = kb + row * 64 + cc * 8;
            cpa16(base + 0 * FL_TILE + off, Kh + g);
            cpa16(base + 1 * FL_TILE + off, Kl + g);
            cpa16(base + 2 * FL_TILE + off, Vh + g);
            cpa16(base + 3 * FL_TILE + off, Vl + g);
        }
    };

    load_kv(0, 0);
    CP_COMMIT();
    {
        const bf16* qh = Qh + hb + (size_t)qt * 128 * 64;
        const bf16* ql = Ql + hb + (size_t)qt * 128 * 64;
        #pragma unroll
        for (int it = 0; it < 4; it++) {
            int u = tid + it * 256;
            int row = u >> 3, cc = u & 7;
            char* d = sm4 + FL_Q + row * FL_STRIDE + cc * 16;
            *reinterpret_cast<uint4*>(d) =
                *reinterpret_cast<const uint4*>(qh + row * 64 + cc * 8);
            *reinterpret_cast<uint4*>(d + FL_TILE) =
                *reinterpret_cast<const uint4*>(ql + row * 64 + cc * 8);
        }
    }
    __syncthreads();

    uint32_t qfh[16], qfl[16];
    {
        int arow = lane & 15, asel = lane >> 4;
        #pragma unroll
        for (int ka = 0; ka < 4; ka++) {
            uint32_t off = (uint32_t)((16 * w + arow) * FL_STRIDE + ka * 32 + asel * 16);
            ldmx4(qfh + ka * 4, smb + FL_Q + off);
            ldmx4(qfl + ka * 4, smb + FL_Q + FL_TILE + off);
        }
    }

    float o[8][4];
    #pragma unroll
    for (int nv = 0; nv < 8; nv++)
        #pragma unroll
        for (int c = 0; c < 4; c++) o[nv][c] = 0.f;
    float mA = -1e30f, mB = -1e30f, lA = 0.f, lB = 0.f;

    const int rg = lane >> 2, cg = lane & 3;
    const int brow = lane & 7, bsel = (lane >> 3) & 3;
    const int vkey = lane & 15, vsel = lane >> 4;

    for (int jt = 0; jt <= qt; jt++) {
        if (jt < qt) load_kv((jt + 1) & 1, jt + 1);
        CP_COMMIT();
        CP_WAIT(1);
        __syncthreads();

        const uint32_t sb = smb + (jt & 1) * FL_STAGE;

        // ---- S = Q@K^T (bf16x3), pass-major chain-free order ----
        float s[16][4];
        #pragma unroll
        for (int na = 0; na < 16; na++)
            #pragma unroll
            for (int c = 0; c < 4; c++) s[na][c] = 0.f;

        #pragma unroll
        for (int kp = 0; kp < 2; kp++) {
            #pragma unroll
            for (int half = 0; half < 2; half++) {
                uint32_t kf[8][4];
                #pragma unroll
                for (int q = 0; q < 8; q++)
                    ldmx4(kf[q], sb + 0 * FL_TILE +
                          (uint32_t)(((half * 8 + q) * 8 + brow) * FL_STRIDE + kp * 64 + bsel * 16));
                #pragma unroll
                for (int j = 0; j < 2; j++)
                    #pragma unroll
                    for (int q = 0; q < 8; q++)
                        mma_bf16(s[half * 8 + q], qfh + (2 * kp + j) * 4, kf[q][2 * j], kf[q][2 * j + 1]);
                #pragma unroll
                for (int j = 0; j < 2; j++)
                    #pragma unroll
                    for (int q = 0; q < 8; q++)
                        mma_bf16(s[half * 8 + q], qfl + (2 * kp + j) * 4, kf[q][2 * j], kf[q][2 * j + 1]);
                #pragma unroll
                for (int q = 0; q < 8; q++)
                    ldmx4(kf[q], sb + 1 * FL_TILE +
                          (uint32_t)(((half * 8 + q) * 8 + brow) * FL_STRIDE + kp * 64 + bsel * 16));
                #pragma unroll
                for (int j = 0; j < 2; j++)
                    #pragma unroll
                    for (int q = 0; q < 8; q++)
                        mma_bf16(s[half * 8 + q], qfh + (2 * kp + j) * 4, kf[q][2 * j], kf[q][2 * j + 1]);
            }
        }

        // ---- causal mask (diagonal tile) ----
        if (jt == qt) {
            int rA = 16 * w + rg, rB = rA + 8;
            #pragma unroll
            for (int na = 0; na < 16; na++) {
                int c0 = 8 * na + 2 * cg;
                if (c0 > rA)     s[na][0] = -1e30f;
                if (c0 + 1 > rA) s[na][1] = -1e30f;
                if (c0 > rB)     s[na][2] = -1e30f;
                if (c0 + 1 > rB) s[na][3] = -1e30f;
            }
        }

        // ---- online softmax: row maxes + rescale ----
        float xA = -1e30f, xB = -1e30f;
        #pragma unroll
        for (int na = 0; na < 16; na++) {
            xA = fmaxf(xA, fmaxf(s[na][0], s[na][1]));
            xB = fmaxf(xB, fmaxf(s[na][2], s[na][3]));
        }
        xA = fmaxf(xA, __shfl_xor_sync(0xffffffffu, xA, 1));
        xA = fmaxf(xA, __shfl_xor_sync(0xffffffffu, xA, 2));
        xB = fmaxf(xB, __shfl_xor_sync(0xffffffffu, xB, 1));
        xB = fmaxf(xB, __shfl_xor_sync(0xffffffffu, xB, 2));
        float nmA = fmaxf(mA, xA), nmB = fmaxf(mB, xB);
        float cA = __expf(mA - nmA), cB = __expf(mB - nmB);
        mA = nmA; mB = nmB;
        #pragma unroll
        for (int nv = 0; nv < 8; nv++) {
            o[nv][0] *= cA; o[nv][1] *= cA;
            o[nv][2] *= cB; o[nv][3] *= cB;
        }

        // ---- PV: per-ka exp+pack inline, pass-major chain-free V mma ----
        float sA = 0.f, sB = 0.f;
        #pragma unroll
        for (int ka = 0; ka < 8; ka++) {
            float e00 = __expf(s[2 * ka][0] - nmA);
            float e01 = __expf(s[2 * ka][1] - nmA);
            float e02 = __expf(s[2 * ka][2] - nmB);
            float e03 = __expf(s[2 * ka][3] - nmB);
            float e10 = __expf(s[2 * ka + 1][0] - nmA);
            float e11 = __expf(s[2 * ka + 1][1] - nmA);
            float e12 = __expf(s[2 * ka + 1][2] - nmB);
            float e13 = __expf(s[2 * ka + 1][3] - nmB);
            sA += (e00 + e01) + (e10 + e11);
            sB += (e02 + e03) + (e12 + e13);

            uint32_t pah4[4], pal4[4];
            pah4[0] = pack_hi_trunc(e00, e01);
            pah4[1] = pack_hi_trunc(e02, e03);
            pah4[2] = pack_hi_trunc(e10, e11);
            pah4[3] = pack_hi_trunc(e12, e13);
            pal4[0] = pack_lo_rn(e00, e01);
            pal4[1] = pack_lo_rn(e02, e03);
            pal4[2] = pack_lo_rn(e10, e11);
            pal4[3] = pack_lo_rn(e12, e13);

            uint32_t vf[4][4];
            #pragma unroll
            for (int nv = 0; nv < 4; nv++)
                ldmx4t(vf[nv], sb + 2 * FL_TILE +
                       (uint32_t)((ka * 16 + vkey) * FL_STRIDE + (nv * 16 + vsel * 8) * 2));
            #pragma unroll
            for (int nv = 0; nv < 4; nv++) {
                mma_bf16(o[2 * nv],     pah4, vf[nv][0], vf[nv][1]);
                mma_bf16(o[2 * nv + 1], pah4, vf[nv][2], vf[nv][3]);
            }
            #pragma unroll
            for (int nv = 0; nv < 4; nv++) {
                mma_bf16(o[2 * nv],     pal4, vf[nv][0], vf[nv][1]);
                mma_bf16(o[2 * nv + 1], pal4, vf[nv][2], vf[nv][3]);
            }
            #pragma unroll
            for (int nv = 0; nv < 4; nv++)
                ldmx4t(vf[nv], sb + 3 * FL_TILE +
                       (uint32_t)((ka * 16 + vkey) * FL_STRIDE + (nv * 16 + vsel * 8) * 2));
            #pragma unroll
            for (int nv = 0; nv < 4; nv++) {
                mma_bf16(o[2 * nv],     pah4, vf[nv][0], vf[nv][1]);
                mma_bf16(o[2 * nv + 1], pah4, vf[nv][2], vf[nv][3]);
            }
        }
        sA += __shfl_xor_sync(0xffffffffu, sA, 1);
        sA += __shfl_xor_sync(0xffffffffu, sA, 2);
        sB += __shfl_xor_sync(0xffffffffu, sB, 1);
        sB += __shfl_xor_sync(0xffffffffu, sB, 2);
        lA = lA * cA + sA;
        lB = lB * cB + sB;

        __syncthreads();   // protect stage (jt&1) from next iter's prefetch
    }

    // ---- normalize + split + write bf16 [B,T,C] hi/lo ----
    const int b = bh / Hz, h = bh % Hz;
    const float invA = 1.f / lA, invB = 1.f / lB;
    int rA = qt * 128 + 16 * w + rg;
    #pragma unroll
    for (int nv = 0; nv < 8; nv++) {
        int col = h * 64 + nv * 8 + 2 * cg;
        size_t baseA = (size_t)(b * Tz + rA) * Cz + col;
        size_t baseB = (size_t)(b * Tz + rA + 8) * Cz + col;
        float v0 = o[nv][0] * invA, v1 = o[nv][1] * invA;
        float v2 = o[nv][2] * invB, v3 = o[nv][3] * invB;
        bf16 h0, l0, h1, l1, h2, l2, h3, l3;
        bsplit(v0, &h0, &l0); bsplit(v1, &h1, &l1);
        bsplit(v2, &h2, &l2); bsplit(v3, &h3, &l3);
        *reinterpret_cast<__nv_bfloat162*>(Ohi + baseA) = __nv_bfloat162(h0, h1);
        *reinterpret_cast<__nv_bfloat162*>(Olo + baseA) = __nv_bfloat162(l0, l1);
        *reinterpret_cast<__nv_bfloat162*>(Ohi + baseB) = __nv_bfloat162(h2, h3);
        *reinterpret_cast<__nv_bfloat162*>(Olo + baseB) = __nv_bfloat162(l2, l3);
    }
}

// ---------------------------------------------------------------------------
// kernel_launch
// ---------------------------------------------------------------------------
extern "C" void kernel_launch(void* const* d_in, const int* in_sizes, int n_in,
                              void* d_out, int out_size)
{
    const float* x      = (const float*)d_in[0];
    const float* cosb   = (const float*)d_in[1];
    const float* sinb   = (const float*)d_in[2];
    const float* W_att  = (const float*)d_in[3];
    const float* W_proj = (const float*)d_in[4];
    const float* b_proj = (const float*)d_in[5];
    float* out = (float*)d_out;

    float* tmp;
    cudaGetSymbolAddress((void**)&tmp, g_tmp);
    bf16 *xhi, *xlo, *ahi, *alo, *w1hi, *w1lo, *w2hi, *w2lo;
    cudaGetSymbolAddress((void**)&xhi, g_xhi);
    cudaGetSymbolAddress((void**)&xlo, g_xlo);
    cudaGetSymbolAddress((void**)&ahi, g_ahi);
    cudaGetSymbolAddress((void**)&alo, g_alo);
    cudaGetSymbolAddress((void**)&w1hi, g_w1hi);
    cudaGetSymbolAddress((void**)&w1lo, g_w1lo);
    cudaGetSymbolAddress((void**)&w2hi, g_w2hi);
    cudaGetSymbolAddress((void**)&w2lo, g_w2lo);
    bf16 *Khp, *Klp, *Qhp, *Qlp, *Vhp, *Vlp;
    cudaGetSymbolAddress((void**)&Khp, g_Kh);
    cudaGetSymbolAddress((void**)&Klp, g_Kl);
    cudaGetSymbolAddress((void**)&Qhp, g_Qh);
    cudaGetSymbolAddress((void**)&Qlp, g_Ql);
    cudaGetSymbolAddress((void**)&Vhp, g_Vh);
    cudaGetSymbolAddress((void**)&Vlp, g_Vl);

    cudaFuncSetAttribute(mm_gemm_kernel,
                         cudaFuncAttributeMaxDynamicSharedMemorySize, MG_SMEM);
    cudaFuncSetAttribute(flash4_kernel,
                         cudaFuncAttributeMaxDynamicSharedMemorySize, FL4_SMEM);

    // prep: bf16 splits
    split_rows_kernel<<<(Mz * Cz + 255) / 256, 256>>>(x, xhi, xlo, Mz * Cz);
    splitT_kernel<<<dim3(1536 / 32, Cz / 32), 256>>>(W_att, w1hi, w1lo, 1536, Cz, 3 * Cz, 768);
    splitT_kernel<<<dim3(Cz / 32, Cz / 32), 256>>>(W_proj, w2hi, w2lo, Cz, Cz, Cz, 1 << 30);

    // 1) QKV GEMM (k and v chunks only) -> g_tmp [4096,1536]
    mm_gemm_kernel<<<dim3(1536 / 128, Mz / 128), 256, MG_SMEM>>>(
        xhi, xlo, w1hi, w1lo, tmp, nullptr, Cz, 1536);

    // 2) RoPE + transpose + split -> [BH,T,D] bf16 hi/lo
    {
        int total = Mz * Hz * (Dz / 2);
        rope_split_kernel<<<(total + 255) / 256, 256>>>(
            tmp, cosb, sinb, Khp, Klp, Qhp, Qlp, Vhp, Vlp);
    }

    // 3) Flash attention (HMMA, cp.async, chain-free) -> split bf16
    flash4_kernel<<<dim3(Tz / 128, BHz), 256, FL4_SMEM>>>(
        Qhp, Qlp, Khp, Klp, Vhp, Vlp, ahi, alo);

    // 4) proj GEMM + bias -> d_out
    mm_gemm_kernel<<<dim3(Cz / 128, Mz / 128), 256, MG_SMEM>>>(
        ahi, alo, w2hi, w2lo, out, b_proj, Cz, Cz);
}

// round 8
// speedup vs baseline: 9.2844x; 1.3611x over previous
#include <cuda_runtime.h>
#include <cuda_fp16.h>
#include <cstdint>

// Problem constants
#define Bz 2
#define Tz 2048
#define Cz 768
#define Hz 12
#define Dz 64
#define BHz (Bz*Hz)        // 24
#define Mz (Bz*Tz)         // 4096

typedef __half fp16;

// ---------------------------------------------------------------------------
// Scratch (static device arrays — no cudaMalloc allowed)
// ---------------------------------------------------------------------------
__device__ float g_tmp[(size_t)Mz * 1536];        // QKV gemm out: k-chunk | v-chunk

__device__ fp16 g_xhi[(size_t)Mz * Cz],  g_xlo[(size_t)Mz * Cz];
__device__ fp16 g_ahi[(size_t)Mz * Cz],  g_alo[(size_t)Mz * Cz];
__device__ fp16 g_w1[(size_t)1536 * Cz];          // W_att^T, single fp16
__device__ fp16 g_w2[(size_t)Cz * Cz];            // W_proj^T, single fp16

// rope outputs, [BH, T, D]
__device__ fp16 g_Kf[(size_t)BHz * Tz * Dz];               // K single
__device__ fp16 g_Qh[(size_t)BHz * Tz * Dz], g_Ql[(size_t)BHz * Tz * Dz];
__device__ fp16 g_Vf[(size_t)BHz * Tz * Dz];               // V single

// ---------------------------------------------------------------------------
// Warp-MMA + async-copy helpers (sm_80-compatible under plain sm_100 target)
// ---------------------------------------------------------------------------
__device__ __forceinline__ uint32_t smem_u32(const void* p) {
    uint32_t a;
    asm("{ .reg .u64 t; cvta.to.shared.u64 t, %1; cvt.u32.u64 %0, t; }"
        : "=r"(a) : "l"(p));
    return a;
}
__device__ __forceinline__ void mma_f16(float* d, const uint32_t* a,
                                        uint32_t b0, uint32_t b1) {
    asm volatile(
        "mma.sync.aligned.m16n8k16.row.col.f32.f16.f16.f32 "
        "{%0,%1,%2,%3}, {%4,%5,%6,%7}, {%8,%9}, {%0,%1,%2,%3};"
        : "+f"(d[0]), "+f"(d[1]), "+f"(d[2]), "+f"(d[3])
        : "r"(a[0]), "r"(a[1]), "r"(a[2]), "r"(a[3]), "r"(b0), "r"(b1));
}
__device__ __forceinline__ void ldmx4(uint32_t* r, uint32_t addr) {
    asm volatile("ldmatrix.sync.aligned.m8n8.x4.shared.b16 {%0,%1,%2,%3}, [%4];"
        : "=r"(r[0]), "=r"(r[1]), "=r"(r[2]), "=r"(r[3]) : "r"(addr));
}
__device__ __forceinline__ void ldmx4t(uint32_t* r, uint32_t addr) {
    asm volatile("ldmatrix.sync.aligned.m8n8.x4.trans.shared.b16 {%0,%1,%2,%3}, [%4];"
        : "=r"(r[0]), "=r"(r[1]), "=r"(r[2]), "=r"(r[3]) : "r"(addr));
}
__device__ __forceinline__ void cpa16(uint32_t d, const void* s) {
    asm volatile("cp.async.cg.shared.global [%0], [%1], 16;" :: "r"(d), "l"(s));
}
#define CP_COMMIT() asm volatile("cp.async.commit_group;" ::: "memory")
#define CP_WAIT(n)  asm volatile("cp.async.wait_group %0;" :: "n"(n) : "memory")

// fp16 packing helpers
__device__ __forceinline__ uint32_t packh2(float lo, float hi) {
    __half2 h = __floats2half2_rn(lo, hi);
    return *reinterpret_cast<uint32_t*>(&h);
}
__device__ __forceinline__ void hsplit(float v, fp16* hp, fp16* lp) {
    fp16 h = __float2half_rn(v);
    *hp = h;
    *lp = __float2half_rn(v - __half2float(h));
}

// ---------------------------------------------------------------------------
// fp16 prep kernels
// ---------------------------------------------------------------------------
__global__ __launch_bounds__(256) void split_rows_kernel(
    const float* __restrict__ in, fp16* __restrict__ hi, fp16* __restrict__ lo, int n)
{
    int i = blockIdx.x * 256 + threadIdx.x;
    if (i >= n) return;
    hsplit(in[i], hi + i, lo + i);
}

// Tiled transpose to single fp16: Wt[n][k] = W[k][col(n)]
__global__ __launch_bounds__(256) void transT_kernel(
    const float* __restrict__ W, fp16* __restrict__ out,
    int N, int K, int ldw, int nsplit)
{
    __shared__ float t[32][33];
    int tx = threadIdx.x & 31, ty = threadIdx.x >> 5;
    int n0 = blockIdx.x * 32;
    int k0 = blockIdx.y * 32;
    int col0 = n0 + (n0 >= nsplit ? 768 : 0);

    #pragma unroll
    for (int i = 0; i < 4; i++) {
        int k = k0 + ty + i * 8;
        t[ty + i * 8][tx] = W[(size_t)k * ldw + col0 + tx];
    }
    __syncthreads();
    #pragma unroll
    for (int i = 0; i < 4; i++) {
        int n = n0 + ty + i * 8;
        out[(size_t)n * K + k0 + tx] = __float2half_rn(t[tx][ty + i * 8]);
    }
}

// ---------------------------------------------------------------------------
// Dense GEMM via mma.sync fp16, 2-pass (A split x B single), 2-stage cp.async.
// C[M,N] = A[M,K] @ Bt[N,K]^T. 128x128x32 CTA, 8 warps, 2 CTAs/SM.
// ---------------------------------------------------------------------------
#define MG_STRIDE 80            // 32 fp16 = 64B data + 16B pad
#define MG_AH 0
#define MG_AL 10240
#define MG_B  20480
#define MG_STAGE 30720
#define MG_SMEM (2 * MG_STAGE)  // 61440 -> 2 CTAs/SM

__global__ __launch_bounds__(256, 2) void mm_gemm_kernel(
    const fp16* __restrict__ Ahi, const fp16* __restrict__ Alo,
    const fp16* __restrict__ Bf,
    float* __restrict__ Cmat, const float* __restrict__ bias,
    int K, int ldc)
{
    extern __shared__ __align__(16) char gsm[];
    const uint32_t smb = smem_u32(gsm);
    const int tid  = threadIdx.x;
    const int w    = tid >> 5;
    const int lane = tid & 31;
    const int n0 = blockIdx.x * 128;
    const int m0 = blockIdx.y * 128;
    const int wm = w & 3;
    const int wn = w >> 2;

    auto load_stage = [&](int s, int kc) {
        uint32_t base = smb + s * MG_STAGE;
        #pragma unroll
        for (int it = 0; it < 2; it++) {
            int u   = tid + it * 256;
            int row = u >> 2, cc = u & 3;
            size_t ga = (size_t)(m0 + row) * K + kc + cc * 8;
            size_t gb = (size_t)(n0 + row) * K + kc + cc * 8;
            uint32_t off = (uint32_t)(row * MG_STRIDE + cc * 16);
            cpa16(base + MG_AH + off, Ahi + ga);
            cpa16(base + MG_AL + off, Alo + ga);
            cpa16(base + MG_B  + off, Bf  + gb);
        }
    };

    float acc[2][8][4];
    #pragma unroll
    for (int a = 0; a < 2; a++)
        #pragma unroll
        for (int b = 0; b < 8; b++)
            #pragma unroll
            for (int c = 0; c < 4; c++) acc[a][b][c] = 0.f;

    const int arow = lane & 15, asel = lane >> 4;
    const int brow = lane & 7,  bsel = (lane >> 3) & 3;
    const int nch = K / 32;

    load_stage(0, 0);  CP_COMMIT();
    load_stage(1, 32); CP_COMMIT();

    for (int c = 0; c < nch; c++) {
        CP_WAIT(1);
        __syncthreads();
        const uint32_t sb = smb + (c & 1) * MG_STAGE;

        uint32_t af[2][2][4];    // current A term
        uint32_t bq[4][4];       // B quarter

        // Phase 1: ah * b
        #pragma unroll
        for (int ma = 0; ma < 2; ma++)
            #pragma unroll
            for (int ks = 0; ks < 2; ks++)
                ldmx4(af[ma][ks], sb + MG_AH +
                      (uint32_t)((wm * 32 + ma * 16 + arow) * MG_STRIDE + ks * 32 + asel * 16));
        #pragma unroll
        for (int half = 0; half < 2; half++) {
            #pragma unroll
            for (int q = 0; q < 4; q++)
                ldmx4(bq[q], sb + MG_B +
                      (uint32_t)((wn * 64 + (half * 4 + q) * 8 + brow) * MG_STRIDE + bsel * 16));
            #pragma unroll
            for (int ks = 0; ks < 2; ks++)
                #pragma unroll
                for (int q = 0; q < 4; q++)
                    #pragma unroll
                    for (int ma = 0; ma < 2; ma++)
                        mma_f16(acc[ma][half * 4 + q], af[ma][ks], bq[q][2 * ks], bq[q][2 * ks + 1]);
        }

        // Phase 2: al * b
        #pragma unroll
        for (int ma = 0; ma < 2; ma++)
            #pragma unroll
            for (int ks = 0; ks < 2; ks++)
                ldmx4(af[ma][ks], sb + MG_AL +
                      (uint32_t)((wm * 32 + ma * 16 + arow) * MG_STRIDE + ks * 32 + asel * 16));
        #pragma unroll
        for (int half = 0; half < 2; half++) {
            #pragma unroll
            for (int q = 0; q < 4; q++)
                ldmx4(bq[q], sb + MG_B +
                      (uint32_t)((wn * 64 + (half * 4 + q) * 8 + brow) * MG_STRIDE + bsel * 16));
            #pragma unroll
            for (int ks = 0; ks < 2; ks++)
                #pragma unroll
                for (int q = 0; q < 4; q++)
                    #pragma unroll
                    for (int ma = 0; ma < 2; ma++)
                        mma_f16(acc[ma][half * 4 + q], af[ma][ks], bq[q][2 * ks], bq[q][2 * ks + 1]);
        }

        __syncthreads();
        if (c + 2 < nch) load_stage(c & 1, (c + 2) * 32);
        CP_COMMIT();
    }

    const int rg = lane >> 2, cg = lane & 3;
    #pragma unroll
    for (int ma = 0; ma < 2; ma++) {
        int row = m0 + wm * 32 + ma * 16 + rg;
        #pragma unroll
        for (int na = 0; na < 8; na++) {
            int col = n0 + wn * 64 + na * 8 + 2 * cg;
            float b0 = bias ? bias[col] : 0.f;
            float b1 = bias ? bias[col + 1] : 0.f;
            *reinterpret_cast<float2*>(Cmat + (size_t)row * ldc + col) =
                make_float2(acc[ma][na][0] + b0, acc[ma][na][1] + b1);
            *reinterpret_cast<float2*>(Cmat + (size_t)(row + 8) * ldc + col) =
                make_float2(acc[ma][na][2] + b0, acc[ma][na][3] + b1);
        }
    }
}

// ---------------------------------------------------------------------------
// RoPE + transpose + fp16 prep. K=rope(k) single, Q=rope(v)*scale split, V single.
// ---------------------------------------------------------------------------
__global__ __launch_bounds__(256) void rope_split_kernel(
    const float* __restrict__ tmp,
    const float* __restrict__ cosb, const float* __restrict__ sinb,
    fp16* __restrict__ Kf,
    fp16* __restrict__ Qh, fp16* __restrict__ Ql,
    fp16* __restrict__ Vf)
{
    int idx = blockIdx.x * blockDim.x + threadIdx.x;
    if (idx >= Mz * Hz * (Dz / 2)) return;
    int i = idx & 31;
    int h = (idx >> 5) % Hz;
    int m = idx / (Hz * 32);
    int b = m >> 11;
    int t = m & (Tz - 1);

    const float* row = tmp + (size_t)m * 1536;
    float kr = row[h * Dz + 2 * i];
    float ki = row[h * Dz + 2 * i + 1];
    float vr = row[768 + h * Dz + 2 * i];
    float vi = row[768 + h * Dz + 2 * i + 1];

    float c = cosb[t * 32 + i];
    float s = sinb[t * 32 + i];

    size_t o = ((size_t)(b * Hz + h) * Tz + t) * Dz + 2 * i;
    const float scale = 0.125f;   // D^-0.5, folded into Q
    Kf[o]     = __float2half_rn(kr * c - ki * s);
    Kf[o + 1] = __float2half_rn(kr * s + ki * c);
    hsplit((vr * c - vi * s) * scale, Qh + o,     Ql + o);
    hsplit((vr * s + vi * c) * scale, Qh + o + 1, Ql + o + 1);
    Vf[o]     = __float2half_rn(vr);
    Vf[o + 1] = __float2half_rn(vi);
}

// ---------------------------------------------------------------------------
// Flash attention via fp16 mma.sync: S = (Qh+Ql) x Kf (2-pass),
// PV = (Ph+Pl) x Vf (2-pass). 2-stage cp.async on K/V singles.
// 128 q-rows x 128 keys, 8 warps x 16 q-rows. Epilogue emits split fp16.
// ---------------------------------------------------------------------------
#define FL_STRIDE 144                // 64 fp16 = 128B + 16B pad
#define FL_TILE   (128 * FL_STRIDE)  // 18432
#define FL_STAGE  (2 * FL_TILE)      // KF,VF = 36864
#define FL_Q      (2 * FL_STAGE)     // 73728
#define FL5_SMEM  (FL_Q + 2 * FL_TILE)   // 110592

__global__ __launch_bounds__(256) void flash5_kernel(
    const fp16* __restrict__ Qh, const fp16* __restrict__ Ql,
    const fp16* __restrict__ Kf, const fp16* __restrict__ Vf,
    fp16* __restrict__ Ohi, fp16* __restrict__ Olo)
{
    extern __shared__ __align__(16) char sm5[];
    const uint32_t smb = smem_u32(sm5);
    const int tid  = threadIdx.x;
    const int w    = tid >> 5;
    const int lane = tid & 31;
    const int qt   = (int)gridDim.x - 1 - (int)blockIdx.x;   // heavy tiles first
    const int bh   = blockIdx.y;
    const size_t hb = (size_t)bh * Tz * Dz;

    auto load_kv = [&](int s, int j) {
        uint32_t base = smb + s * FL_STAGE;
        const size_t kb = hb + (size_t)j * 128 * 64;
        #pragma unroll
        for (int it = 0; it < 4; it++) {
            int u = tid + it * 256;
            int row = u >> 3, cc = u & 7;
            uint32_t off = (uint32_t)(row * FL_STRIDE + cc * 16);
            size_t g = kb + row * 64 + cc * 8;
            cpa16(base + 0 * FL_TILE + off, Kf + g);
            cpa16(base + 1 * FL_TILE + off, Vf + g);
        }
    };

    load_kv(0, 0);
    CP_COMMIT();
    {
        const fp16* qh = Qh + hb + (size_t)qt * 128 * 64;
        const fp16* ql = Ql + hb + (size_t)qt * 128 * 64;
        #pragma unroll
        for (int it = 0; it < 4; it++) {
            int u = tid + it * 256;
            int row = u >> 3, cc = u & 7;
            char* d = sm5 + FL_Q + row * FL_STRIDE + cc * 16;
            *reinterpret_cast<uint4*>(d) =
                *reinterpret_cast<const uint4*>(qh + row * 64 + cc * 8);
            *reinterpret_cast<uint4*>(d + FL_TILE) =
                *reinterpret_cast<const uint4*>(ql + row * 64 + cc * 8);
        }
    }
    __syncthreads();

    uint32_t qfh[16], qfl[16];
    {
        int arow = lane & 15, asel = lane >> 4;
        #pragma unroll
        for (int ka = 0; ka < 4; ka++) {
            uint32_t off = (uint32_t)((16 * w + arow) * FL_STRIDE + ka * 32 + asel * 16);
            ldmx4(qfh + ka * 4, smb + FL_Q + off);
            ldmx4(qfl + ka * 4, smb + FL_Q + FL_TILE + off);
        }
    }

    float o[8][4];
    #pragma unroll
    for (int nv = 0; nv < 8; nv++)
        #pragma unroll
        for (int c = 0; c < 4; c++) o[nv][c] = 0.f;
    float mA = -1e30f, mB = -1e30f, lA = 0.f, lB = 0.f;

    const int rg = lane >> 2, cg = lane & 3;
    const int brow = lane & 7, bsel = (lane >> 3) & 3;
    const int vkey = lane & 15, vsel = lane >> 4;

    for (int jt = 0; jt <= qt; jt++) {
        if (jt < qt) load_kv((jt + 1) & 1, jt + 1);
        CP_COMMIT();
        CP_WAIT(1);
        __syncthreads();

        const uint32_t sb = smb + (jt & 1) * FL_STAGE;

        // ---- S = Q@K^T, 2-pass fp16 (Q split, K single) ----
        float s[16][4];
        #pragma unroll
        for (int na = 0; na < 16; na++)
            #pragma unroll
            for (int c = 0; c < 4; c++) s[na][c] = 0.f;

        #pragma unroll
        for (int kp = 0; kp < 2; kp++) {
            #pragma unroll
            for (int half = 0; half < 2; half++) {
                uint32_t kf[8][4];
                #pragma unroll
                for (int q = 0; q < 8; q++)
                    ldmx4(kf[q], sb +
                          (uint32_t)(((half * 8 + q) * 8 + brow) * FL_STRIDE + kp * 64 + bsel * 16));
                #pragma unroll
                for (int j = 0; j < 2; j++)
                    #pragma unroll
                    for (int q = 0; q < 8; q++)
                        mma_f16(s[half * 8 + q], qfh + (2 * kp + j) * 4, kf[q][2 * j], kf[q][2 * j + 1]);
                #pragma unroll
                for (int j = 0; j < 2; j++)
                    #pragma unroll
                    for (int q = 0; q < 8; q++)
                        mma_f16(s[half * 8 + q], qfl + (2 * kp + j) * 4, kf[q][2 * j], kf[q][2 * j + 1]);
            }
        }

        // ---- causal mask (diagonal tile) ----
        if (jt == qt) {
            int rA = 16 * w + rg, rB = rA + 8;
            #pragma unroll
            for (int na = 0; na < 16; na++) {
                int c0 = 8 * na + 2 * cg;
                if (c0 > rA)     s[na][0] = -1e30f;
                if (c0 + 1 > rA) s[na][1] = -1e30f;
                if (c0 > rB)     s[na][2] = -1e30f;
                if (c0 + 1 > rB) s[na][3] = -1e30f;
            }
        }

        // ---- online softmax: row maxes + rescale ----
        float xA = -1e30f, xB = -1e30f;
        #pragma unroll
        for (int na = 0; na < 16; na++) {
            xA = fmaxf(xA, fmaxf(s[na][0], s[na][1]));
            xB = fmaxf(xB, fmaxf(s[na][2], s[na][3]));
        }
        xA = fmaxf(xA, __shfl_xor_sync(0xffffffffu, xA, 1));
        xA = fmaxf(xA, __shfl_xor_sync(0xffffffffu, xA, 2));
        xB = fmaxf(xB, __shfl_xor_sync(0xffffffffu, xB, 1));
        xB = fmaxf(xB, __shfl_xor_sync(0xffffffffu, xB, 2));
        float nmA = fmaxf(mA, xA), nmB = fmaxf(mB, xB);
        float cA = __expf(mA - nmA), cB = __expf(mB - nmB);
        mA = nmA; mB = nmB;
        #pragma unroll
        for (int nv = 0; nv < 8; nv++) {
            o[nv][0] *= cA; o[nv][1] *= cA;
            o[nv][2] *= cB; o[nv][3] *= cB;
        }

        // ---- PV: exp + fp16 rz-split P, V single: 2-pass ----
        float sA = 0.f, sB = 0.f;
        #pragma unroll
        for (int ka = 0; ka < 8; ka++) {
            float e00 = __expf(s[2 * ka][0] - nmA);
            float e01 = __expf(s[2 * ka][1] - nmA);
            float e02 = __expf(s[2 * ka][2] - nmB);
            float e03 = __expf(s[2 * ka][3] - nmB);
            float e10 = __expf(s[2 * ka + 1][0] - nmA);
            float e11 = __expf(s[2 * ka + 1][1] - nmA);
            float e12 = __expf(s[2 * ka + 1][2] - nmB);
            float e13 = __expf(s[2 * ka + 1][3] - nmB);
            sA += (e00 + e01) + (e10 + e11);
            sB += (e02 + e03) + (e12 + e13);

            // hi = rz(p) (fp16-exact), lo = residual
            float h00 = __half2float(__float2half_rz(e00));
            float h01 = __half2float(__float2half_rz(e01));
            float h02 = __half2float(__float2half_rz(e02));
            float h03 = __half2float(__float2half_rz(e03));
            float h10 = __half2float(__float2half_rz(e10));
            float h11 = __half2float(__float2half_rz(e11));
            float h12 = __half2float(__float2half_rz(e12));
            float h13 = __half2float(__float2half_rz(e13));
            uint32_t ph4[4], pl4[4];
            ph4[0] = packh2(h00, h01);
            ph4[1] = packh2(h02, h03);
            ph4[2] = packh2(h10, h11);
            ph4[3] = packh2(h12, h13);
            pl4[0] = packh2(e00 - h00, e01 - h01);
            pl4[1] = packh2(e02 - h02, e03 - h03);
            pl4[2] = packh2(e10 - h10, e11 - h11);
            pl4[3] = packh2(e12 - h12, e13 - h13);

            uint32_t vf[4][4];
            #pragma unroll
            for (int nv = 0; nv < 4; nv++)
                ldmx4t(vf[nv], sb + 1 * FL_TILE +
                       (uint32_t)((ka * 16 + vkey) * FL_STRIDE + (nv * 16 + vsel * 8) * 2));
            #pragma unroll
            for (int nv = 0; nv < 4; nv++) {
                mma_f16(o[2 * nv],     ph4, vf[nv][0], vf[nv][1]);
                mma_f16(o[2 * nv + 1], ph4, vf[nv][2], vf[nv][3]);
            }
            #pragma unroll
            for (int nv = 0; nv < 4; nv++) {
                mma_f16(o[2 * nv],     pl4, vf[nv][0], vf[nv][1]);
                mma_f16(o[2 * nv + 1], pl4, vf[nv][2], vf[nv][3]);
            }
        }
        sA += __shfl_xor_sync(0xffffffffu, sA, 1);
        sA += __shfl_xor_sync(0xffffffffu, sA, 2);
        sB += __shfl_xor_sync(0xffffffffu, sB, 1);
        sB += __shfl_xor_sync(0xffffffffu, sB, 2);
        lA = lA * cA + sA;
        lB = lB * cB + sB;

        __syncthreads();   // protect stage (jt&1) from next iter's prefetch
    }

    // ---- normalize + split + write fp16 [B,T,C] hi/lo ----
    const int b = bh / Hz, h = bh % Hz;
    const float invA = 1.f / lA, invB = 1.f / lB;
    int rA = qt * 128 + 16 * w + rg;
    #pragma unroll
    for (int nv = 0; nv < 8; nv++) {
        int col = h * 64 + nv * 8 + 2 * cg;
        size_t baseA = (size_t)(b * Tz + rA) * Cz + col;
        size_t baseB = (size_t)(b * Tz + rA + 8) * Cz + col;
        float v0 = o[nv][0] * invA, v1 = o[nv][1] * invA;
        float v2 = o[nv][2] * invB, v3 = o[nv][3] * invB;
        fp16 h0, l0, h1, l1, h2, l2, h3, l3;
        hsplit(v0, &h0, &l0); hsplit(v1, &h1, &l1);
        hsplit(v2, &h2, &l2); hsplit(v3, &h3, &l3);
        *reinterpret_cast<__half2*>(Ohi + baseA) = __halves2half2(h0, h1);
        *reinterpret_cast<__half2*>(Olo + baseA) = __halves2half2(l0, l1);
        *reinterpret_cast<__half2*>(Ohi + baseB) = __halves2half2(h2, h3);
        *reinterpret_cast<__half2*>(Olo + baseB) = __halves2half2(l2, l3);
    }
}

// ---------------------------------------------------------------------------
// kernel_launch
// ---------------------------------------------------------------------------
extern "C" void kernel_launch(void* const* d_in, const int* in_sizes, int n_in,
                              void* d_out, int out_size)
{
    const float* x      = (const float*)d_in[0];
    const float* cosb   = (const float*)d_in[1];
    const float* sinb   = (const float*)d_in[2];
    const float* W_att  = (const float*)d_in[3];
    const float* W_proj = (const float*)d_in[4];
    const float* b_proj = (const float*)d_in[5];
    float* out = (float*)d_out;

    float* tmp;
    cudaGetSymbolAddress((void**)&tmp, g_tmp);
    fp16 *xhi, *xlo, *ahi, *alo, *w1, *w2;
    cudaGetSymbolAddress((void**)&xhi, g_xhi);
    cudaGetSymbolAddress((void**)&xlo, g_xlo);
    cudaGetSymbolAddress((void**)&ahi, g_ahi);
    cudaGetSymbolAddress((void**)&alo, g_alo);
    cudaGetSymbolAddress((void**)&w1,  g_w1);
    cudaGetSymbolAddress((void**)&w2,  g_w2);
    fp16 *Kfp, *Qhp, *Qlp, *Vfp;
    cudaGetSymbolAddress((void**)&Kfp, g_Kf);
    cudaGetSymbolAddress((void**)&Qhp, g_Qh);
    cudaGetSymbolAddress((void**)&Qlp, g_Ql);
    cudaGetSymbolAddress((void**)&Vfp, g_Vf);

    cudaFuncSetAttribute(mm_gemm_kernel,
                         cudaFuncAttributeMaxDynamicSharedMemorySize, MG_SMEM);
    cudaFuncSetAttribute(flash5_kernel,
                         cudaFuncAttributeMaxDynamicSharedMemorySize, FL5_SMEM);

    // prep: fp16 splits / transposes
    split_rows_kernel<<<(Mz * Cz + 255) / 256, 256>>>(x, xhi, xlo, Mz * Cz);
    transT_kernel<<<dim3(1536 / 32, Cz / 32), 256>>>(W_att, w1, 1536, Cz, 3 * Cz, 768);
    transT_kernel<<<dim3(Cz / 32, Cz / 32), 256>>>(W_proj, w2, Cz, Cz, Cz, 1 << 30);

    // 1) QKV GEMM (k and v chunks only) -> g_tmp [4096,1536]
    mm_gemm_kernel<<<dim3(1536 / 128, Mz / 128), 256, MG_SMEM>>>(
        xhi, xlo, w1, tmp, nullptr, Cz, 1536);

    // 2) RoPE + transpose + fp16 prep -> [BH,T,D]
    {
        int total = Mz * Hz * (Dz / 2);
        rope_split_kernel<<<(total + 255) / 256, 256>>>(
            tmp, cosb, sinb, Kfp, Qhp, Qlp, Vfp);
    }

    // 3) Flash attention (fp16 2-pass) -> split fp16
    flash5_kernel<<<dim3(Tz / 128, BHz), 256, FL5_SMEM>>>(
        Qhp, Qlp, Kfp, Vfp, ahi, alo);

    // 4) proj GEMM + bias -> d_out
    mm_gemm_kernel<<<dim3(Cz / 128, Mz / 128), 256, MG_SMEM>>>(
        ahi, alo, w2, out, b_proj, Cz, Cz);
}

// round 9
// speedup vs baseline: 9.3273x; 1.0046x over previous
#include <cuda_runtime.h>
#include <cuda_fp16.h>
#include <cstdint>

// Problem constants
#define Bz 2
#define Tz 2048
#define Cz 768
#define Hz 12
#define Dz 64
#define BHz (Bz*Hz)        // 24
#define Mz (Bz*Tz)         // 4096

typedef __half fp16;

// ---------------------------------------------------------------------------
// Scratch (static device arrays — no cudaMalloc allowed)
// ---------------------------------------------------------------------------
__device__ fp16 g_xhi[(size_t)Mz * Cz],  g_xlo[(size_t)Mz * Cz];
__device__ fp16 g_ahi[(size_t)Mz * Cz],  g_alo[(size_t)Mz * Cz];
__device__ fp16 g_w1[(size_t)1536 * Cz];          // W_att^T (k|v chunks), fp16
__device__ fp16 g_w2[(size_t)Cz * Cz];            // W_proj^T, fp16

// attention operands, [BH, T, D]
__device__ fp16 g_Kf[(size_t)BHz * Tz * Dz];
__device__ fp16 g_Qh[(size_t)BHz * Tz * Dz], g_Ql[(size_t)BHz * Tz * Dz];
__device__ fp16 g_Vf[(size_t)BHz * Tz * Dz];

// ---------------------------------------------------------------------------
// Warp-MMA + async-copy helpers (sm_80-compatible under plain sm_100 target)
// ---------------------------------------------------------------------------
__device__ __forceinline__ uint32_t smem_u32(const void* p) {
    uint32_t a;
    asm("{ .reg .u64 t; cvta.to.shared.u64 t, %1; cvt.u32.u64 %0, t; }"
        : "=r"(a) : "l"(p));
    return a;
}
__device__ __forceinline__ void mma_f16(float* d, const uint32_t* a,
                                        uint32_t b0, uint32_t b1) {
    asm volatile(
        "mma.sync.aligned.m16n8k16.row.col.f32.f16.f16.f32 "
        "{%0,%1,%2,%3}, {%4,%5,%6,%7}, {%8,%9}, {%0,%1,%2,%3};"
        : "+f"(d[0]), "+f"(d[1]), "+f"(d[2]), "+f"(d[3])
        : "r"(a[0]), "r"(a[1]), "r"(a[2]), "r"(a[3]), "r"(b0), "r"(b1));
}
__device__ __forceinline__ void ldmx4(uint32_t* r, uint32_t addr) {
    asm volatile("ldmatrix.sync.aligned.m8n8.x4.shared.b16 {%0,%1,%2,%3}, [%4];"
        : "=r"(r[0]), "=r"(r[1]), "=r"(r[2]), "=r"(r[3]) : "r"(addr));
}
__device__ __forceinline__ void ldmx4t(uint32_t* r, uint32_t addr) {
    asm volatile("ldmatrix.sync.aligned.m8n8.x4.trans.shared.b16 {%0,%1,%2,%3}, [%4];"
        : "=r"(r[0]), "=r"(r[1]), "=r"(r[2]), "=r"(r[3]) : "r"(addr));
}
__device__ __forceinline__ void cpa16(uint32_t d, const void* s) {
    asm volatile("cp.async.cg.shared.global [%0], [%1], 16;" :: "r"(d), "l"(s));
}
#define CP_COMMIT() asm volatile("cp.async.commit_group;" ::: "memory")
#define CP_WAIT(n)  asm volatile("cp.async.wait_group %0;" :: "n"(n) : "memory")

// fp16 packing helpers
__device__ __forceinline__ uint32_t packh2(float lo, float hi) {
    __half2 h = __floats2half2_rn(lo, hi);
    return *reinterpret_cast<uint32_t*>(&h);
}
__device__ __forceinline__ void hsplit(float v, fp16* hp, fp16* lp) {
    fp16 h = __float2half_rn(v);
    *hp = h;
    *lp = __float2half_rn(v - __half2float(h));
}

// ---------------------------------------------------------------------------
// fp16 prep kernels
// ---------------------------------------------------------------------------
__global__ __launch_bounds__(256) void split_rows_kernel(
    const float* __restrict__ in, fp16* __restrict__ hi, fp16* __restrict__ lo, int n)
{
    int i = blockIdx.x * 256 + threadIdx.x;
    if (i >= n) return;
    hsplit(in[i], hi + i, lo + i);
}

// Merged tiled transposes: z=0 -> W_att (with k|v col remap), z=1 -> W_proj.
__global__ __launch_bounds__(256) void transT2_kernel(
    const float* __restrict__ W1, fp16* __restrict__ out1,
    const float* __restrict__ W2, fp16* __restrict__ out2)
{
    __shared__ float t[32][33];
    int tx = threadIdx.x & 31, ty = threadIdx.x >> 5;
    int z = blockIdx.z;
    int N = z ? Cz : 1536;
    int ldw = z ? Cz : 3 * Cz;
    if ((int)blockIdx.x * 32 >= N) return;
    const float* W = z ? W2 : W1;
    fp16* out = z ? out2 : out1;

    int n0 = blockIdx.x * 32;
    int k0 = blockIdx.y * 32;
    int col0 = n0 + ((!z && n0 >= 768) ? 768 : 0);   // v-chunk remap for W_att

    #pragma unroll
    for (int i = 0; i < 4; i++) {
        int k = k0 + ty + i * 8;
        t[ty + i * 8][tx] = W[(size_t)k * ldw + col0 + tx];
    }
    __syncthreads();
    #pragma unroll
    for (int i = 0; i < 4; i++) {
        int n = n0 + ty + i * 8;
        out[(size_t)n * Cz + k0 + tx] = __float2half_rn(t[tx][ty + i * 8]);
    }
}

// ---------------------------------------------------------------------------
// Dense GEMM via mma.sync fp16, 2-pass (A split x B single), 2-stage cp.async.
// 128x128x32 CTA, 8 warps, 2 CTAs/SM.
// MODE 0: epilogue = fp32 C + bias (proj).
// MODE 1: epilogue = fused RoPE + fp16 prep (QKV).
// ---------------------------------------------------------------------------
#define MG_STRIDE 80            // 32 fp16 = 64B data + 16B pad
#define MG_AH 0
#define MG_AL 10240
#define MG_B  20480
#define MG_STAGE 30720
#define MG_SMEM (2 * MG_STAGE)  // 61440 -> 2 CTAs/SM

template<int MODE>
__global__ __launch_bounds__(256, 2) void mm_gemm_kernel(
    const fp16* __restrict__ Ahi, const fp16* __restrict__ Alo,
    const fp16* __restrict__ Bf,
    float* __restrict__ Cmat, const float* __restrict__ bias,
    const float* __restrict__ cosb, const float* __restrict__ sinb,
    fp16* __restrict__ Kf, fp16* __restrict__ Qh,
    fp16* __restrict__ Ql, fp16* __restrict__ Vf,
    int K, int ldc)
{
    extern __shared__ __align__(16) char gsm[];
    const uint32_t smb = smem_u32(gsm);
    const int tid  = threadIdx.x;
    const int w    = tid >> 5;
    const int lane = tid & 31;
    const int n0 = blockIdx.x * 128;
    const int m0 = blockIdx.y * 128;
    const int wm = w & 3;
    const int wn = w >> 2;

    auto load_stage = [&](int s, int kc) {
        uint32_t base = smb + s * MG_STAGE;
        #pragma unroll
        for (int it = 0; it < 2; it++) {
            int u   = tid + it * 256;
            int row = u >> 2, cc = u & 3;
            size_t ga = (size_t)(m0 + row) * K + kc + cc * 8;
            size_t gb = (size_t)(n0 + row) * K + kc + cc * 8;
            uint32_t off = (uint32_t)(row * MG_STRIDE + cc * 16);
            cpa16(base + MG_AH + off, Ahi + ga);
            cpa16(base + MG_AL + off, Alo + ga);
            cpa16(base + MG_B  + off, Bf  + gb);
        }
    };

    float acc[2][8][4];
    #pragma unroll
    for (int a = 0; a < 2; a++)
        #pragma unroll
        for (int b = 0; b < 8; b++)
            #pragma unroll
            for (int c = 0; c < 4; c++) acc[a][b][c] = 0.f;

    const int arow = lane & 15, asel = lane >> 4;
    const int brow = lane & 7,  bsel = (lane >> 3) & 3;
    const int nch = K / 32;

    load_stage(0, 0);  CP_COMMIT();
    load_stage(1, 32); CP_COMMIT();

    for (int c = 0; c < nch; c++) {
        CP_WAIT(1);
        __syncthreads();
        const uint32_t sb = smb + (c & 1) * MG_STAGE;

        uint32_t af[2][2][4];
        uint32_t bq[4][4];

        // Phase 1: ah * b
        #pragma unroll
        for (int ma = 0; ma < 2; ma++)
            #pragma unroll
            for (int ks = 0; ks < 2; ks++)
                ldmx4(af[ma][ks], sb + MG_AH +
                      (uint32_t)((wm * 32 + ma * 16 + arow) * MG_STRIDE + ks * 32 + asel * 16));
        #pragma unroll
        for (int half = 0; half < 2; half++) {
            #pragma unroll
            for (int q = 0; q < 4; q++)
                ldmx4(bq[q], sb + MG_B +
                      (uint32_t)((wn * 64 + (half * 4 + q) * 8 + brow) * MG_STRIDE + bsel * 16));
            #pragma unroll
            for (int ks = 0; ks < 2; ks++)
                #pragma unroll
                for (int q = 0; q < 4; q++)
                    #pragma unroll
                    for (int ma = 0; ma < 2; ma++)
                        mma_f16(acc[ma][half * 4 + q], af[ma][ks], bq[q][2 * ks], bq[q][2 * ks + 1]);
        }

        // Phase 2: al * b
        #pragma unroll
        for (int ma = 0; ma < 2; ma++)
            #pragma unroll
            for (int ks = 0; ks < 2; ks++)
                ldmx4(af[ma][ks], sb + MG_AL +
                      (uint32_t)((wm * 32 + ma * 16 + arow) * MG_STRIDE + ks * 32 + asel * 16));
        #pragma unroll
        for (int half = 0; half < 2; half++) {
            #pragma unroll
            for (int q = 0; q < 4; q++)
                ldmx4(bq[q], sb + MG_B +
                      (uint32_t)((wn * 64 + (half * 4 + q) * 8 + brow) * MG_STRIDE + bsel * 16));
            #pragma unroll
            for (int ks = 0; ks < 2; ks++)
                #pragma unroll
                for (int q = 0; q < 4; q++)
                    #pragma unroll
                    for (int ma = 0; ma < 2; ma++)
                        mma_f16(acc[ma][half * 4 + q], af[ma][ks], bq[q][2 * ks], bq[q][2 * ks + 1]);
        }

        __syncthreads();
        if (c + 2 < nch) load_stage(c & 1, (c + 2) * 32);
        CP_COMMIT();
    }

    const int rg = lane >> 2, cg = lane & 3;

    if (MODE == 0) {
        #pragma unroll
        for (int ma = 0; ma < 2; ma++) {
            int row = m0 + wm * 32 + ma * 16 + rg;
            #pragma unroll
            for (int na = 0; na < 8; na++) {
                int col = n0 + wn * 64 + na * 8 + 2 * cg;
                float b0 = bias ? bias[col] : 0.f;
                float b1 = bias ? bias[col + 1] : 0.f;
                *reinterpret_cast<float2*>(Cmat + (size_t)row * ldc + col) =
                    make_float2(acc[ma][na][0] + b0, acc[ma][na][1] + b1);
                *reinterpret_cast<float2*>(Cmat + (size_t)(row + 8) * ldc + col) =
                    make_float2(acc[ma][na][2] + b0, acc[ma][na][3] + b1);
            }
        }
    } else {
        // Fused RoPE epilogue. Whole CTA is k-chunk or v-chunk (n0 aligned to 768).
        const bool isv = (n0 >= 768);
        const float scale = 0.125f;   // D^-0.5, folded into Q
        #pragma unroll
        for (int ma = 0; ma < 2; ma++) {
            int row = m0 + wm * 32 + ma * 16 + rg;   // = b*T + t
            int b  = row >> 11;
            int t0 = row & (Tz - 1);
            int t1 = t0 + 8;
            #pragma unroll
            for (int na = 0; na < 8; na++) {
                int col = n0 + wn * 64 + na * 8 + 2 * cg;
                int ch  = isv ? col - 768 : col;
                int h   = ch >> 6;
                int d   = ch & 63;
                int i   = d >> 1;
                float c0 = cosb[t0 * 32 + i], s0 = sinb[t0 * 32 + i];
                float c1 = cosb[t1 * 32 + i], s1 = sinb[t1 * 32 + i];
                size_t o0 = ((size_t)(b * Hz + h) * Tz + t0) * Dz + d;
                size_t o1 = ((size_t)(b * Hz + h) * Tz + t1) * Dz + d;
                float v0 = acc[ma][na][0], v1 = acc[ma][na][1];
                float v2 = acc[ma][na][2], v3 = acc[ma][na][3];
                if (!isv) {
                    *reinterpret_cast<uint32_t*>(Kf + o0) =
                        packh2(v0 * c0 - v1 * s0, v0 * s0 + v1 * c0);
                    *reinterpret_cast<uint32_t*>(Kf + o1) =
                        packh2(v2 * c1 - v3 * s1, v2 * s1 + v3 * c1);
                } else {
                    fp16 qh0, ql0, qh1, ql1;
                    hsplit((v0 * c0 - v1 * s0) * scale, &qh0, &ql0);
                    hsplit((v0 * s0 + v1 * c0) * scale, &qh1, &ql1);
                    *reinterpret_cast<__half2*>(Qh + o0) = __halves2half2(qh0, qh1);
                    *reinterpret_cast<__half2*>(Ql + o0) = __halves2half2(ql0, ql1);
                    *reinterpret_cast<uint32_t*>(Vf + o0) = packh2(v0, v1);
                    hsplit((v2 * c1 - v3 * s1) * scale, &qh0, &ql0);
                    hsplit((v2 * s1 + v3 * c1) * scale, &qh1, &ql1);
                    *reinterpret_cast<__half2*>(Qh + o1) = __halves2half2(qh0, qh1);
                    *reinterpret_cast<__half2*>(Ql + o1) = __halves2half2(ql0, ql1);
                    *reinterpret_cast<uint32_t*>(Vf + o1) = packh2(v2, v3);
                }
            }
        }
    }
}

// ---------------------------------------------------------------------------
// Flash attention via fp16 mma.sync: S = (Qh+Ql) x Kf (2-pass),
// PV = (Ph+Pl) x Vf (2-pass). 2-stage cp.async on K/V singles.
// ---------------------------------------------------------------------------
#define FL_STRIDE 144                // 64 fp16 = 128B + 16B pad
#define FL_TILE   (128 * FL_STRIDE)  // 18432
#define FL_STAGE  (2 * FL_TILE)      // KF,VF = 36864
#define FL_Q      (2 * FL_STAGE)     // 73728
#define FL5_SMEM  (FL_Q + 2 * FL_TILE)   // 110592

__global__ __launch_bounds__(256) void flash5_kernel(
    const fp16* __restrict__ Qh, const fp16* __restrict__ Ql,
    const fp16* __restrict__ Kf, const fp16* __restrict__ Vf,
    fp16* __restrict__ Ohi, fp16* __restrict__ Olo)
{
    extern __shared__ __align__(16) char sm5[];
    const uint32_t smb = smem_u32(sm5);
    const int tid  = threadIdx.x;
    const int w    = tid >> 5;
    const int lane = tid & 31;
    const int qt   = (int)gridDim.x - 1 - (int)blockIdx.x;   // heavy tiles first
    const int bh   = blockIdx.y;
    const size_t hb = (size_t)bh * Tz * Dz;

    auto load_kv = [&](int s, int j) {
        uint32_t base = smb + s * FL_STAGE;
        const size_t kb = hb + (size_t)j * 128 * 64;
        #pragma unroll
        for (int it = 0; it < 4; it++) {
            int u = tid + it * 256;
            int row = u >> 3, cc = u & 7;
            uint32_t off = (uint32_t)(row * FL_STRIDE + cc * 16);
            size_t g = kb + row * 64 + cc * 8;
            cpa16(base + 0 * FL_TILE + off, Kf + g);
            cpa16(base + 1 * FL_TILE + off, Vf + g);
        }
    };

    load_kv(0, 0);
    CP_COMMIT();
    {
        const fp16* qh = Qh + hb + (size_t)qt * 128 * 64;
        const fp16* ql = Ql + hb + (size_t)qt * 128 * 64;
        #pragma unroll
        for (int it = 0; it < 4; it++) {
            int u = tid + it * 256;
            int row = u >> 3, cc = u & 7;
            char* d = sm5 + FL_Q + row * FL_STRIDE + cc * 16;
            *reinterpret_cast<uint4*>(d) =
                *reinterpret_cast<const uint4*>(qh + row * 64 + cc * 8);
            *reinterpret_cast<uint4*>(d + FL_TILE) =
                *reinterpret_cast<const uint4*>(ql + row * 64 + cc * 8);
        }
    }
    __syncthreads();

    uint32_t qfh[16], qfl[16];
    {
        int arow = lane & 15, asel = lane >> 4;
        #pragma unroll
        for (int ka = 0; ka < 4; ka++) {
            uint32_t off = (uint32_t)((16 * w + arow) * FL_STRIDE + ka * 32 + asel * 16);
            ldmx4(qfh + ka * 4, smb + FL_Q + off);
            ldmx4(qfl + ka * 4, smb + FL_Q + FL_TILE + off);
        }
    }

    float o[8][4];
    #pragma unroll
    for (int nv = 0; nv < 8; nv++)
        #pragma unroll
        for (int c = 0; c < 4; c++) o[nv][c] = 0.f;
    float mA = -1e30f, mB = -1e30f, lA = 0.f, lB = 0.f;

    const int rg = lane >> 2, cg = lane & 3;
    const int brow = lane & 7, bsel = (lane >> 3) & 3;
    const int vkey = lane & 15, vsel = lane >> 4;

    for (int jt = 0; jt <= qt; jt++) {
        if (jt < qt) load_kv((jt + 1) & 1, jt + 1);
        CP_COMMIT();
        CP_WAIT(1);
        __syncthreads();

        const uint32_t sb = smb + (jt & 1) * FL_STAGE;

        float s[16][4];
        #pragma unroll
        for (int na = 0; na < 16; na++)
            #pragma unroll
            for (int c = 0; c < 4; c++) s[na][c] = 0.f;

        #pragma unroll
        for (int kp = 0; kp < 2; kp++) {
            #pragma unroll
            for (int half = 0; half < 2; half++) {
                uint32_t kf[8][4];
                #pragma unroll
                for (int q = 0; q < 8; q++)
                    ldmx4(kf[q], sb +
                          (uint32_t)(((half * 8 + q) * 8 + brow) * FL_STRIDE + kp * 64 + bsel * 16));
                #pragma unroll
                for (int j = 0; j < 2; j++)
                    #pragma unroll
                    for (int q = 0; q < 8; q++)
                        mma_f16(s[half * 8 + q], qfh + (2 * kp + j) * 4, kf[q][2 * j], kf[q][2 * j + 1]);
                #pragma unroll
                for (int j = 0; j < 2; j++)
                    #pragma unroll
                    for (int q = 0; q < 8; q++)
                        mma_f16(s[half * 8 + q], qfl + (2 * kp + j) * 4, kf[q][2 * j], kf[q][2 * j + 1]);
            }
        }

        if (jt == qt) {
            int rA = 16 * w + rg, rB = rA + 8;
            #pragma unroll
            for (int na = 0; na < 16; na++) {
                int c0 = 8 * na + 2 * cg;
                if (c0 > rA)     s[na][0] = -1e30f;
                if (c0 + 1 > rA) s[na][1] = -1e30f;
                if (c0 > rB)     s[na][2] = -1e30f;
                if (c0 + 1 > rB) s[na][3] = -1e30f;
            }
        }

        float xA = -1e30f, xB = -1e30f;
        #pragma unroll
        for (int na = 0; na < 16; na++) {
            xA = fmaxf(xA, fmaxf(s[na][0], s[na][1]));
            xB = fmaxf(xB, fmaxf(s[na][2], s[na][3]));
        }
        xA = fmaxf(xA, __shfl_xor_sync(0xffffffffu, xA, 1));
        xA = fmaxf(xA, __shfl_xor_sync(0xffffffffu, xA, 2));
        xB = fmaxf(xB, __shfl_xor_sync(0xffffffffu, xB, 1));
        xB = fmaxf(xB, __shfl_xor_sync(0xffffffffu, xB, 2));
        float nmA = fmaxf(mA, xA), nmB = fmaxf(mB, xB);
        float cA = __expf(mA - nmA), cB = __expf(mB - nmB);
        mA = nmA; mB = nmB;
        #pragma unroll
        for (int nv = 0; nv < 8; nv++) {
            o[nv][0] *= cA; o[nv][1] *= cA;
            o[nv][2] *= cB; o[nv][3] *= cB;
        }

        float sA = 0.f, sB = 0.f;
        #pragma unroll
        for (int ka = 0; ka < 8; ka++) {
            float e00 = __expf(s[2 * ka][0] - nmA);
            float e01 = __expf(s[2 * ka][1] - nmA);
            float e02 = __expf(s[2 * ka][2] - nmB);
            float e03 = __expf(s[2 * ka][3] - nmB);
            float e10 = __expf(s[2 * ka + 1][0] - nmA);
            float e11 = __expf(s[2 * ka + 1][1] - nmA);
            float e12 = __expf(s[2 * ka + 1][2] - nmB);
            float e13 = __expf(s[2 * ka + 1][3] - nmB);
            sA += (e00 + e01) + (e10 + e11);
            sB += (e02 + e03) + (e12 + e13);

            float h00 = __half2float(__float2half_rz(e00));
            float h01 = __half2float(__float2half_rz(e01));
            float h02 = __half2float(__float2half_rz(e02));
            float h03 = __half2float(__float2half_rz(e03));
            float h10 = __half2float(__float2half_rz(e10));
            float h11 = __half2float(__float2half_rz(e11));
            float h12 = __half2float(__float2half_rz(e12));
            float h13 = __half2float(__float2half_rz(e13));
            uint32_t ph4[4], pl4[4];
            ph4[0] = packh2(h00, h01);
            ph4[1] = packh2(h02, h03);
            ph4[2] = packh2(h10, h11);
            ph4[3] = packh2(h12, h13);
            pl4[0] = packh2(e00 - h00, e01 - h01);
            pl4[1] = packh2(e02 - h02, e03 - h03);
            pl4[2] = packh2(e10 - h10, e11 - h11);
            pl4[3] = packh2(e12 - h12, e13 - h13);

            uint32_t vf[4][4];
            #pragma unroll
            for (int nv = 0; nv < 4; nv++)
                ldmx4t(vf[nv], sb + 1 * FL_TILE +
                       (uint32_t)((ka * 16 + vkey) * FL_STRIDE + (nv * 16 + vsel * 8) * 2));
            #pragma unroll
            for (int nv = 0; nv < 4; nv++) {
                mma_f16(o[2 * nv],     ph4, vf[nv][0], vf[nv][1]);
                mma_f16(o[2 * nv + 1], ph4, vf[nv][2], vf[nv][3]);
            }
            #pragma unroll
            for (int nv = 0; nv < 4; nv++) {
                mma_f16(o[2 * nv],     pl4, vf[nv][0], vf[nv][1]);
                mma_f16(o[2 * nv + 1], pl4, vf[nv][2], vf[nv][3]);
            }
        }
        sA += __shfl_xor_sync(0xffffffffu, sA, 1);
        sA += __shfl_xor_sync(0xffffffffu, sA, 2);
        sB += __shfl_xor_sync(0xffffffffu, sB, 1);
        sB += __shfl_xor_sync(0xffffffffu, sB, 2);
        lA = lA * cA + sA;
        lB = lB * cB + sB;

        __syncthreads();
    }

    const int b = bh / Hz, h = bh % Hz;
    const float invA = 1.f / lA, invB = 1.f / lB;
    int rA = qt * 128 + 16 * w + rg;
    #pragma unroll
    for (int nv = 0; nv < 8; nv++) {
        int col = h * 64 + nv * 8 + 2 * cg;
        size_t baseA = (size_t)(b * Tz + rA) * Cz + col;
        size_t baseB = (size_t)(b * Tz + rA + 8) * Cz + col;
        float v0 = o[nv][0] * invA, v1 = o[nv][1] * invA;
        float v2 = o[nv][2] * invB, v3 = o[nv][3] * invB;
        fp16 h0, l0, h1, l1, h2, l2, h3, l3;
        hsplit(v0, &h0, &l0); hsplit(v1, &h1, &l1);
        hsplit(v2, &h2, &l2); hsplit(v3, &h3, &l3);
        *reinterpret_cast<__half2*>(Ohi + baseA) = __halves2half2(h0, h1);
        *reinterpret_cast<__half2*>(Olo + baseA) = __halves2half2(l0, l1);
        *reinterpret_cast<__half2*>(Ohi + baseB) = __halves2half2(h2, h3);
        *reinterpret_cast<__half2*>(Olo + baseB) = __halves2half2(l2, l3);
    }
}

// ---------------------------------------------------------------------------
// kernel_launch
// ---------------------------------------------------------------------------
extern "C" void kernel_launch(void* const* d_in, const int* in_sizes, int n_in,
                              void* d_out, int out_size)
{
    const float* x      = (const float*)d_in[0];
    const float* cosb   = (const float*)d_in[1];
    const float* sinb   = (const float*)d_in[2];
    const float* W_att  = (const float*)d_in[3];
    const float* W_proj = (const float*)d_in[4];
    const float* b_proj = (const float*)d_in[5];
    float* out = (float*)d_out;

    fp16 *xhi, *xlo, *ahi, *alo, *w1, *w2;
    cudaGetSymbolAddress((void**)&xhi, g_xhi);
    cudaGetSymbolAddress((void**)&xlo, g_xlo);
    cudaGetSymbolAddress((void**)&ahi, g_ahi);
    cudaGetSymbolAddress((void**)&alo, g_alo);
    cudaGetSymbolAddress((void**)&w1,  g_w1);
    cudaGetSymbolAddress((void**)&w2,  g_w2);
    fp16 *Kfp, *Qhp, *Qlp, *Vfp;
    cudaGetSymbolAddress((void**)&Kfp, g_Kf);
    cudaGetSymbolAddress((void**)&Qhp, g_Qh);
    cudaGetSymbolAddress((void**)&Qlp, g_Ql);
    cudaGetSymbolAddress((void**)&Vfp, g_Vf);

    cudaFuncSetAttribute(mm_gemm_kernel<0>,
                         cudaFuncAttributeMaxDynamicSharedMemorySize, MG_SMEM);
    cudaFuncSetAttribute(mm_gemm_kernel<1>,
                         cudaFuncAttributeMaxDynamicSharedMemorySize, MG_SMEM);
    cudaFuncSetAttribute(flash5_kernel,
                         cudaFuncAttributeMaxDynamicSharedMemorySize, FL5_SMEM);

    // prep: x split + merged weight transposes
    split_rows_kernel<<<(Mz * Cz + 255) / 256, 256>>>(x, xhi, xlo, Mz * Cz);
    transT2_kernel<<<dim3(1536 / 32, Cz / 32, 2), 256>>>(W_att, w1, W_proj, w2);

    // 1) QKV GEMM + fused RoPE epilogue -> Kf / (Qh,Ql) / Vf  [BH,T,D]
    mm_gemm_kernel<1><<<dim3(1536 / 128, Mz / 128), 256, MG_SMEM>>>(
        xhi, xlo, w1, nullptr, nullptr, cosb, sinb, Kfp, Qhp, Qlp, Vfp, Cz, 0);

    // 2) Flash attention (fp16 2-pass) -> split fp16 (ahi/alo)
    flash5_kernel<<<dim3(Tz / 128, BHz), 256, FL5_SMEM>>>(
        Qhp, Qlp, Kfp, Vfp, ahi, alo);

    // 3) proj GEMM + bias -> d_out
    mm_gemm_kernel<0><<<dim3(Cz / 128, Mz / 128), 256, MG_SMEM>>>(
        ahi, alo, w2, out, b_proj, nullptr, nullptr,
        nullptr, nullptr, nullptr, nullptr, Cz, Cz);
}

// round 10
// speedup vs baseline: 10.0956x; 1.0824x over previous
#include <cuda_runtime.h>
#include <cuda_fp16.h>
#include <cstdint>

// Problem constants
#define Bz 2
#define Tz 2048
#define Cz 768
#define Hz 12
#define Dz 64
#define BHz (Bz*Hz)        // 24
#define Mz (Bz*Tz)         // 4096

typedef __half fp16;

// ---------------------------------------------------------------------------
// Scratch (static device arrays — no cudaMalloc allowed)
// ---------------------------------------------------------------------------
__device__ fp16 g_xhi[(size_t)Mz * Cz],  g_xlo[(size_t)Mz * Cz];
__device__ fp16 g_ahi[(size_t)Mz * Cz],  g_alo[(size_t)Mz * Cz];
__device__ fp16 g_w1[(size_t)1536 * Cz];          // W_att^T (k|v chunks), fp16
__device__ fp16 g_w2[(size_t)Cz * Cz];            // W_proj^T, fp16

// attention operands, [BH, T, D]
__device__ fp16 g_Kf[(size_t)BHz * Tz * Dz];
__device__ fp16 g_Qh[(size_t)BHz * Tz * Dz], g_Ql[(size_t)BHz * Tz * Dz];
__device__ fp16 g_Vf[(size_t)BHz * Tz * Dz];

// ---------------------------------------------------------------------------
// Warp-MMA + async-copy helpers (sm_80-compatible under plain sm_100 target)
// ---------------------------------------------------------------------------
__device__ __forceinline__ uint32_t smem_u32(const void* p) {
    uint32_t a;
    asm("{ .reg .u64 t; cvta.to.shared.u64 t, %1; cvt.u32.u64 %0, t; }"
        : "=r"(a) : "l"(p));
    return a;
}
__device__ __forceinline__ void mma_f16(float* d, const uint32_t* a,
                                        uint32_t b0, uint32_t b1) {
    asm volatile(
        "mma.sync.aligned.m16n8k16.row.col.f32.f16.f16.f32 "
        "{%0,%1,%2,%3}, {%4,%5,%6,%7}, {%8,%9}, {%0,%1,%2,%3};"
        : "+f"(d[0]), "+f"(d[1]), "+f"(d[2]), "+f"(d[3])
        : "r"(a[0]), "r"(a[1]), "r"(a[2]), "r"(a[3]), "r"(b0), "r"(b1));
}
__device__ __forceinline__ void ldmx4(uint32_t* r, uint32_t addr) {
    asm volatile("ldmatrix.sync.aligned.m8n8.x4.shared.b16 {%0,%1,%2,%3}, [%4];"
        : "=r"(r[0]), "=r"(r[1]), "=r"(r[2]), "=r"(r[3]) : "r"(addr));
}
__device__ __forceinline__ void ldmx4t(uint32_t* r, uint32_t addr) {
    asm volatile("ldmatrix.sync.aligned.m8n8.x4.trans.shared.b16 {%0,%1,%2,%3}, [%4];"
        : "=r"(r[0]), "=r"(r[1]), "=r"(r[2]), "=r"(r[3]) : "r"(addr));
}
__device__ __forceinline__ void cpa16(uint32_t d, const void* s) {
    asm volatile("cp.async.cg.shared.global [%0], [%1], 16;" :: "r"(d), "l"(s));
}
#define CP_COMMIT() asm volatile("cp.async.commit_group;" ::: "memory")
#define CP_WAIT(n)  asm volatile("cp.async.wait_group %0;" :: "n"(n) : "memory")

// fp16 packing helpers
__device__ __forceinline__ uint32_t packh2(float lo, float hi) {
    __half2 h = __floats2half2_rn(lo, hi);
    return *reinterpret_cast<uint32_t*>(&h);
}
__device__ __forceinline__ void hsplit(float v, fp16* hp, fp16* lp) {
    fp16 h = __float2half_rn(v);
    *hp = h;
    *lp = __float2half_rn(v - __half2float(h));
}

// ---------------------------------------------------------------------------
// fp16 prep kernels
// ---------------------------------------------------------------------------
__global__ __launch_bounds__(256) void split_rows_kernel(
    const float* __restrict__ in, fp16* __restrict__ hi, fp16* __restrict__ lo, int n)
{
    int i = blockIdx.x * 256 + threadIdx.x;
    if (i >= n) return;
    hsplit(in[i], hi + i, lo + i);
}

// Merged tiled transposes: z=0 -> W_att (with k|v col remap), z=1 -> W_proj.
__global__ __launch_bounds__(256) void transT2_kernel(
    const float* __restrict__ W1, fp16* __restrict__ out1,
    const float* __restrict__ W2, fp16* __restrict__ out2)
{
    __shared__ float t[32][33];
    int tx = threadIdx.x & 31, ty = threadIdx.x >> 5;
    int z = blockIdx.z;
    int N = z ? Cz : 1536;
    int ldw = z ? Cz : 3 * Cz;
    if ((int)blockIdx.x * 32 >= N) return;
    const float* W = z ? W2 : W1;
    fp16* out = z ? out2 : out1;

    int n0 = blockIdx.x * 32;
    int k0 = blockIdx.y * 32;
    int col0 = n0 + ((!z && n0 >= 768) ? 768 : 0);   // v-chunk remap for W_att

    #pragma unroll
    for (int i = 0; i < 4; i++) {
        int k = k0 + ty + i * 8;
        t[ty + i * 8][tx] = W[(size_t)k * ldw + col0 + tx];
    }
    __syncthreads();
    #pragma unroll
    for (int i = 0; i < 4; i++) {
        int n = n0 + ty + i * 8;
        out[(size_t)n * Cz + k0 + tx] = __float2half_rn(t[tx][ty + i * 8]);
    }
}

// ---------------------------------------------------------------------------
// Dense GEMM via mma.sync fp16, 2-pass (A split x B single), 2-stage cp.async.
// 128x128x32 CTA, 8 warps, 2 CTAs/SM.
// MODE 0: epilogue = fp32 C + bias (proj).
// MODE 1: epilogue = fused RoPE + fp16 prep (QKV).
// ---------------------------------------------------------------------------
#define MG_STRIDE 80            // 32 fp16 = 64B data + 16B pad
#define MG_AH 0
#define MG_AL 10240
#define MG_B  20480
#define MG_STAGE 30720
#define MG_SMEM (2 * MG_STAGE)  // 61440 -> 2 CTAs/SM

template<int MODE>
__global__ __launch_bounds__(256, 2) void mm_gemm_kernel(
    const fp16* __restrict__ Ahi, const fp16* __restrict__ Alo,
    const fp16* __restrict__ Bf,
    float* __restrict__ Cmat, const float* __restrict__ bias,
    const float* __restrict__ cosb, const float* __restrict__ sinb,
    fp16* __restrict__ Kf, fp16* __restrict__ Qh,
    fp16* __restrict__ Ql, fp16* __restrict__ Vf,
    int K, int ldc)
{
    extern __shared__ __align__(16) char gsm[];
    const uint32_t smb = smem_u32(gsm);
    const int tid  = threadIdx.x;
    const int w    = tid >> 5;
    const int lane = tid & 31;
    const int n0 = blockIdx.x * 128;
    const int m0 = blockIdx.y * 128;
    const int wm = w & 3;
    const int wn = w >> 2;

    auto load_stage = [&](int s, int kc) {
        uint32_t base = smb + s * MG_STAGE;
        #pragma unroll
        for (int it = 0; it < 2; it++) {
            int u   = tid + it * 256;
            int row = u >> 2, cc = u & 3;
            size_t ga = (size_t)(m0 + row) * K + kc + cc * 8;
            size_t gb = (size_t)(n0 + row) * K + kc + cc * 8;
            uint32_t off = (uint32_t)(row * MG_STRIDE + cc * 16);
            cpa16(base + MG_AH + off, Ahi + ga);
            cpa16(base + MG_AL + off, Alo + ga);
            cpa16(base + MG_B  + off, Bf  + gb);
        }
    };

    float acc[2][8][4];
    #pragma unroll
    for (int a = 0; a < 2; a++)
        #pragma unroll
        for (int b = 0; b < 8; b++)
            #pragma unroll
            for (int c = 0; c < 4; c++) acc[a][b][c] = 0.f;

    const int arow = lane & 15, asel = lane >> 4;
    const int brow = lane & 7,  bsel = (lane >> 3) & 3;
    const int nch = K / 32;

    load_stage(0, 0);  CP_COMMIT();
    load_stage(1, 32); CP_COMMIT();

    for (int c = 0; c < nch; c++) {
        CP_WAIT(1);
        __syncthreads();
        const uint32_t sb = smb + (c & 1) * MG_STAGE;

        uint32_t af[2][2][4];
        uint32_t bq[4][4];

        // Phase 1: ah * b
        #pragma unroll
        for (int ma = 0; ma < 2; ma++)
            #pragma unroll
            for (int ks = 0; ks < 2; ks++)
                ldmx4(af[ma][ks], sb + MG_AH +
                      (uint32_t)((wm * 32 + ma * 16 + arow) * MG_STRIDE + ks * 32 + asel * 16));
        #pragma unroll
        for (int half = 0; half < 2; half++) {
            #pragma unroll
            for (int q = 0; q < 4; q++)
                ldmx4(bq[q], sb + MG_B +
                      (uint32_t)((wn * 64 + (half * 4 + q) * 8 + brow) * MG_STRIDE + bsel * 16));
            #pragma unroll
            for (int ks = 0; ks < 2; ks++)
                #pragma unroll
                for (int q = 0; q < 4; q++)
                    #pragma unroll
                    for (int ma = 0; ma < 2; ma++)
                        mma_f16(acc[ma][half * 4 + q], af[ma][ks], bq[q][2 * ks], bq[q][2 * ks + 1]);
        }

        // Phase 2: al * b
        #pragma unroll
        for (int ma = 0; ma < 2; ma++)
            #pragma unroll
            for (int ks = 0; ks < 2; ks++)
                ldmx4(af[ma][ks], sb + MG_AL +
                      (uint32_t)((wm * 32 + ma * 16 + arow) * MG_STRIDE + ks * 32 + asel * 16));
        #pragma unroll
        for (int half = 0; half < 2; half++) {
            #pragma unroll
            for (int q = 0; q < 4; q++)
                ldmx4(bq[q], sb + MG_B +
                      (uint32_t)((wn * 64 + (half * 4 + q) * 8 + brow) * MG_STRIDE + bsel * 16));
            #pragma unroll
            for (int ks = 0; ks < 2; ks++)
                #pragma unroll
                for (int q = 0; q < 4; q++)
                    #pragma unroll
                    for (int ma = 0; ma < 2; ma++)
                        mma_f16(acc[ma][half * 4 + q], af[ma][ks], bq[q][2 * ks], bq[q][2 * ks + 1]);
        }

        __syncthreads();
        if (c + 2 < nch) load_stage(c & 1, (c + 2) * 32);
        CP_COMMIT();
    }

    const int rg = lane >> 2, cg = lane & 3;

    if (MODE == 0) {
        #pragma unroll
        for (int ma = 0; ma < 2; ma++) {
            int row = m0 + wm * 32 + ma * 16 + rg;
            #pragma unroll
            for (int na = 0; na < 8; na++) {
                int col = n0 + wn * 64 + na * 8 + 2 * cg;
                float b0 = bias ? bias[col] : 0.f;
                float b1 = bias ? bias[col + 1] : 0.f;
                *reinterpret_cast<float2*>(Cmat + (size_t)row * ldc + col) =
                    make_float2(acc[ma][na][0] + b0, acc[ma][na][1] + b1);
                *reinterpret_cast<float2*>(Cmat + (size_t)(row + 8) * ldc + col) =
                    make_float2(acc[ma][na][2] + b0, acc[ma][na][3] + b1);
            }
        }
    } else {
        // Fused RoPE epilogue. Whole CTA is k-chunk or v-chunk (n0 aligned to 768).
        const bool isv = (n0 >= 768);
        const float scale = 0.125f;   // D^-0.5, folded into Q
        #pragma unroll
        for (int ma = 0; ma < 2; ma++) {
            int row = m0 + wm * 32 + ma * 16 + rg;   // = b*T + t
            int b  = row >> 11;
            int t0 = row & (Tz - 1);
            int t1 = t0 + 8;
            #pragma unroll
            for (int na = 0; na < 8; na++) {
                int col = n0 + wn * 64 + na * 8 + 2 * cg;
                int ch  = isv ? col - 768 : col;
                int h   = ch >> 6;
                int d   = ch & 63;
                int i   = d >> 1;
                float c0 = cosb[t0 * 32 + i], s0 = sinb[t0 * 32 + i];
                float c1 = cosb[t1 * 32 + i], s1 = sinb[t1 * 32 + i];
                size_t o0 = ((size_t)(b * Hz + h) * Tz + t0) * Dz + d;
                size_t o1 = ((size_t)(b * Hz + h) * Tz + t1) * Dz + d;
                float v0 = acc[ma][na][0], v1 = acc[ma][na][1];
                float v2 = acc[ma][na][2], v3 = acc[ma][na][3];
                if (!isv) {
                    *reinterpret_cast<uint32_t*>(Kf + o0) =
                        packh2(v0 * c0 - v1 * s0, v0 * s0 + v1 * c0);
                    *reinterpret_cast<uint32_t*>(Kf + o1) =
                        packh2(v2 * c1 - v3 * s1, v2 * s1 + v3 * c1);
                } else {
                    fp16 qh0, ql0, qh1, ql1;
                    hsplit((v0 * c0 - v1 * s0) * scale, &qh0, &ql0);
                    hsplit((v0 * s0 + v1 * c0) * scale, &qh1, &ql1);
                    *reinterpret_cast<__half2*>(Qh + o0) = __halves2half2(qh0, qh1);
                    *reinterpret_cast<__half2*>(Ql + o0) = __halves2half2(ql0, ql1);
                    *reinterpret_cast<uint32_t*>(Vf + o0) = packh2(v0, v1);
                    hsplit((v2 * c1 - v3 * s1) * scale, &qh0, &ql0);
                    hsplit((v2 * s1 + v3 * c1) * scale, &qh1, &ql1);
                    *reinterpret_cast<__half2*>(Qh + o1) = __halves2half2(qh0, qh1);
                    *reinterpret_cast<__half2*>(Ql + o1) = __halves2half2(ql0, ql1);
                    *reinterpret_cast<uint32_t*>(Vf + o1) = packh2(v2, v3);
                }
            }
        }
    }
}

// ---------------------------------------------------------------------------
// Flash attention via fp16 mma.sync: S = (Qh+Ql) x Kf (2-pass),
// PV = P(rn fp16) x Vf (single pass). 2-stage cp.async on K/V singles.
// ---------------------------------------------------------------------------
#define FL_STRIDE 144                // 64 fp16 = 128B + 16B pad
#define FL_TILE   (128 * FL_STRIDE)  // 18432
#define FL_STAGE  (2 * FL_TILE)      // KF,VF = 36864
#define FL_Q      (2 * FL_STAGE)     // 73728
#define FL5_SMEM  (FL_Q + 2 * FL_TILE)   // 110592

__global__ __launch_bounds__(256) void flash5_kernel(
    const fp16* __restrict__ Qh, const fp16* __restrict__ Ql,
    const fp16* __restrict__ Kf, const fp16* __restrict__ Vf,
    fp16* __restrict__ Ohi, fp16* __restrict__ Olo)
{
    extern __shared__ __align__(16) char sm5[];
    const uint32_t smb = smem_u32(sm5);
    const int tid  = threadIdx.x;
    const int w    = tid >> 5;
    const int lane = tid & 31;
    const int qt   = (int)gridDim.x - 1 - (int)blockIdx.x;   // heavy tiles first
    const int bh   = blockIdx.y;
    const size_t hb = (size_t)bh * Tz * Dz;

    auto load_kv = [&](int s, int j) {
        uint32_t base = smb + s * FL_STAGE;
        const size_t kb = hb + (size_t)j * 128 * 64;
        #pragma unroll
        for (int it = 0; it < 4; it++) {
            int u = tid + it * 256;
            int row = u >> 3, cc = u & 7;
            uint32_t off = (uint32_t)(row * FL_STRIDE + cc * 16);
            size_t g = kb + row * 64 + cc * 8;
            cpa16(base + 0 * FL_TILE + off, Kf + g);
            cpa16(base + 1 * FL_TILE + off, Vf + g);
        }
    };

    load_kv(0, 0);
    CP_COMMIT();
    {
        const fp16* qh = Qh + hb + (size_t)qt * 128 * 64;
        const fp16* ql = Ql + hb + (size_t)qt * 128 * 64;
        #pragma unroll
        for (int it = 0; it < 4; it++) {
            int u = tid + it * 256;
            int row = u >> 3, cc = u & 7;
            char* d = sm5 + FL_Q + row * FL_STRIDE + cc * 16;
            *reinterpret_cast<uint4*>(d) =
                *reinterpret_cast<const uint4*>(qh + row * 64 + cc * 8);
            *reinterpret_cast<uint4*>(d + FL_TILE) =
                *reinterpret_cast<const uint4*>(ql + row * 64 + cc * 8);
        }
    }
    __syncthreads();

    uint32_t qfh[16], qfl[16];
    {
        int arow = lane & 15, asel = lane >> 4;
        #pragma unroll
        for (int ka = 0; ka < 4; ka++) {
            uint32_t off = (uint32_t)((16 * w + arow) * FL_STRIDE + ka * 32 + asel * 16);
            ldmx4(qfh + ka * 4, smb + FL_Q + off);
            ldmx4(qfl + ka * 4, smb + FL_Q + FL_TILE + off);
        }
    }

    float o[8][4];
    #pragma unroll
    for (int nv = 0; nv < 8; nv++)
        #pragma unroll
        for (int c = 0; c < 4; c++) o[nv][c] = 0.f;
    float mA = -1e30f, mB = -1e30f, lA = 0.f, lB = 0.f;

    const int rg = lane >> 2, cg = lane & 3;
    const int brow = lane & 7, bsel = (lane >> 3) & 3;
    const int vkey = lane & 15, vsel = lane >> 4;

    for (int jt = 0; jt <= qt; jt++) {
        if (jt < qt) load_kv((jt + 1) & 1, jt + 1);
        CP_COMMIT();
        CP_WAIT(1);
        __syncthreads();

        const uint32_t sb = smb + (jt & 1) * FL_STAGE;

        // ---- S = Q@K^T, 2-pass fp16 (Q split, K single) ----
        float s[16][4];
        #pragma unroll
        for (int na = 0; na < 16; na++)
            #pragma unroll
            for (int c = 0; c < 4; c++) s[na][c] = 0.f;

        #pragma unroll
        for (int kp = 0; kp < 2; kp++) {
            #pragma unroll
            for (int half = 0; half < 2; half++) {
                uint32_t kf[8][4];
                #pragma unroll
                for (int q = 0; q < 8; q++)
                    ldmx4(kf[q], sb +
                          (uint32_t)(((half * 8 + q) * 8 + brow) * FL_STRIDE + kp * 64 + bsel * 16));
                #pragma unroll
                for (int j = 0; j < 2; j++)
                    #pragma unroll
                    for (int q = 0; q < 8; q++)
                        mma_f16(s[half * 8 + q], qfh + (2 * kp + j) * 4, kf[q][2 * j], kf[q][2 * j + 1]);
                #pragma unroll
                for (int j = 0; j < 2; j++)
                    #pragma unroll
                    for (int q = 0; q < 8; q++)
                        mma_f16(s[half * 8 + q], qfl + (2 * kp + j) * 4, kf[q][2 * j], kf[q][2 * j + 1]);
            }
        }

        // ---- causal mask (diagonal tile) ----
        if (jt == qt) {
            int rA = 16 * w + rg, rB = rA + 8;
            #pragma unroll
            for (int na = 0; na < 16; na++) {
                int c0 = 8 * na + 2 * cg;
                if (c0 > rA)     s[na][0] = -1e30f;
                if (c0 + 1 > rA) s[na][1] = -1e30f;
                if (c0 > rB)     s[na][2] = -1e30f;
                if (c0 + 1 > rB) s[na][3] = -1e30f;
            }
        }

        // ---- online softmax: row maxes + rescale ----
        float xA = -1e30f, xB = -1e30f;
        #pragma unroll
        for (int na = 0; na < 16; na++) {
            xA = fmaxf(xA, fmaxf(s[na][0], s[na][1]));
            xB = fmaxf(xB, fmaxf(s[na][2], s[na][3]));
        }
        xA = fmaxf(xA, __shfl_xor_sync(0xffffffffu, xA, 1));
        xA = fmaxf(xA, __shfl_xor_sync(0xffffffffu, xA, 2));
        xB = fmaxf(xB, __shfl_xor_sync(0xffffffffu, xB, 1));
        xB = fmaxf(xB, __shfl_xor_sync(0xffffffffu, xB, 2));
        float nmA = fmaxf(mA, xA), nmB = fmaxf(mB, xB);
        float cA = __expf(mA - nmA), cB = __expf(mB - nmB);
        mA = nmA; mB = nmB;
        #pragma unroll
        for (int nv = 0; nv < 8; nv++) {
            o[nv][0] *= cA; o[nv][1] *= cA;
            o[nv][2] *= cB; o[nv][3] *= cB;
        }

        // ---- PV: exp -> fp16(rn) P, single-pass V mma ----
        float sA = 0.f, sB = 0.f;
        #pragma unroll
        for (int ka = 0; ka < 8; ka++) {
            float e00 = __expf(s[2 * ka][0] - nmA);
            float e01 = __expf(s[2 * ka][1] - nmA);
            float e02 = __expf(s[2 * ka][2] - nmB);
            float e03 = __expf(s[2 * ka][3] - nmB);
            float e10 = __expf(s[2 * ka + 1][0] - nmA);
            float e11 = __expf(s[2 * ka + 1][1] - nmA);
            float e12 = __expf(s[2 * ka + 1][2] - nmB);
            float e13 = __expf(s[2 * ka + 1][3] - nmB);
            sA += (e00 + e01) + (e10 + e11);
            sB += (e02 + e03) + (e12 + e13);

            uint32_t p4[4];
            p4[0] = packh2(e00, e01);
            p4[1] = packh2(e02, e03);
            p4[2] = packh2(e10, e11);
            p4[3] = packh2(e12, e13);

            uint32_t vf[4][4];
            #pragma unroll
            for (int nv = 0; nv < 4; nv++)
                ldmx4t(vf[nv], sb + 1 * FL_TILE +
                       (uint32_t)((ka * 16 + vkey) * FL_STRIDE + (nv * 16 + vsel * 8) * 2));
            #pragma unroll
            for (int nv = 0; nv < 4; nv++) {
                mma_f16(o[2 * nv],     p4, vf[nv][0], vf[nv][1]);
                mma_f16(o[2 * nv + 1], p4, vf[nv][2], vf[nv][3]);
            }
        }
        sA += __shfl_xor_sync(0xffffffffu, sA, 1);
        sA += __shfl_xor_sync(0xffffffffu, sA, 2);
        sB += __shfl_xor_sync(0xffffffffu, sB, 1);
        sB += __shfl_xor_sync(0xffffffffu, sB, 2);
        lA = lA * cA + sA;
        lB = lB * cB + sB;

        __syncthreads();   // protect stage (jt&1) from next iter's prefetch
    }

    // ---- normalize + split + write fp16 [B,T,C] hi/lo ----
    const int b = bh / Hz, h = bh % Hz;
    const float invA = 1.f / lA, invB = 1.f / lB;
    int rA = qt * 128 + 16 * w + rg;
    #pragma unroll
    for (int nv = 0; nv < 8; nv++) {
        int col = h * 64 + nv * 8 + 2 * cg;
        size_t baseA = (size_t)(b * Tz + rA) * Cz + col;
        size_t baseB = (size_t)(b * Tz + rA + 8) * Cz + col;
        float v0 = o[nv][0] * invA, v1 = o[nv][1] * invA;
        float v2 = o[nv][2] * invB, v3 = o[nv][3] * invB;
        fp16 h0, l0, h1, l1, h2, l2, h3, l3;
        hsplit(v0, &h0, &l0); hsplit(v1, &h1, &l1);
        hsplit(v2, &h2, &l2); hsplit(v3, &h3, &l3);
        *reinterpret_cast<__half2*>(Ohi + baseA) = __halves2half2(h0, h1);
        *reinterpret_cast<__half2*>(Olo + baseA) = __halves2half2(l0, l1);
        *reinterpret_cast<__half2*>(Ohi + baseB) = __halves2half2(h2, h3);
        *reinterpret_cast<__half2*>(Olo + baseB) = __halves2half2(l2, l3);
    }
}

// ---------------------------------------------------------------------------
// kernel_launch
// ---------------------------------------------------------------------------
extern "C" void kernel_launch(void* const* d_in, const int* in_sizes, int n_in,
                              void* d_out, int out_size)
{
    const float* x      = (const float*)d_in[0];
    const float* cosb   = (const float*)d_in[1];
    const float* sinb   = (const float*)d_in[2];
    const float* W_att  = (const float*)d_in[3];
    const float* W_proj = (const float*)d_in[4];
    const float* b_proj = (const float*)d_in[5];
    float* out = (float*)d_out;

    fp16 *xhi, *xlo, *ahi, *alo, *w1, *w2;
    cudaGetSymbolAddress((void**)&xhi, g_xhi);
    cudaGetSymbolAddress((void**)&xlo, g_xlo);
    cudaGetSymbolAddress((void**)&ahi, g_ahi);
    cudaGetSymbolAddress((void**)&alo, g_alo);
    cudaGetSymbolAddress((void**)&w1,  g_w1);
    cudaGetSymbolAddress((void**)&w2,  g_w2);
    fp16 *Kfp, *Qhp, *Qlp, *Vfp;
    cudaGetSymbolAddress((void**)&Kfp, g_Kf);
    cudaGetSymbolAddress((void**)&Qhp, g_Qh);
    cudaGetSymbolAddress((void**)&Qlp, g_Ql);
    cudaGetSymbolAddress((void**)&Vfp, g_Vf);

    cudaFuncSetAttribute(mm_gemm_kernel<0>,
                         cudaFuncAttributeMaxDynamicSharedMemorySize, MG_SMEM);
    cudaFuncSetAttribute(mm_gemm_kernel<1>,
                         cudaFuncAttributeMaxDynamicSharedMemorySize, MG_SMEM);
    cudaFuncSetAttribute(flash5_kernel,
                         cudaFuncAttributeMaxDynamicSharedMemorySize, FL5_SMEM);

    // prep: x split + merged weight transposes
    split_rows_kernel<<<(Mz * Cz + 255) / 256, 256>>>(x, xhi, xlo, Mz * Cz);
    transT2_kernel<<<dim3(1536 / 32, Cz / 32, 2), 256>>>(W_att, w1, W_proj, w2);

    // 1) QKV GEMM + fused RoPE epilogue -> Kf / (Qh,Ql) / Vf  [BH,T,D]
    mm_gemm_kernel<1><<<dim3(1536 / 128, Mz / 128), 256, MG_SMEM>>>(
        xhi, xlo, w1, nullptr, nullptr, cosb, sinb, Kfp, Qhp, Qlp, Vfp, Cz, 0);

    // 2) Flash attention (fp16, S 2-pass, PV 1-pass) -> split fp16 (ahi/alo)
    flash5_kernel<<<dim3(Tz / 128, BHz), 256, FL5_SMEM>>>(
        Qhp, Qlp, Kfp, Vfp, ahi, alo);

    // 3) proj GEMM + bias -> d_out
    mm_gemm_kernel<0><<<dim3(Cz / 128, Mz / 128), 256, MG_SMEM>>>(
        ahi, alo, w2, out, b_proj, nullptr, nullptr,
        nullptr, nullptr, nullptr, nullptr, Cz, Cz);
}

// round 11
// speedup vs baseline: 13.6751x; 1.3546x over previous
#include <cuda_runtime.h>
#include <cuda_fp16.h>
#include <cstdint>

// Problem constants
#define Bz 2
#define Tz 2048
#define Cz 768
#define Hz 12
#define Dz 64
#define BHz (Bz*Hz)        // 24
#define Mz (Bz*Tz)         // 4096

typedef __half fp16;

// ---------------------------------------------------------------------------
// Scratch (static device arrays — no cudaMalloc allowed)
// ---------------------------------------------------------------------------
__device__ fp16 g_xf[(size_t)Mz * Cz];            // x, fp16
__device__ fp16 g_af[(size_t)Mz * Cz];            // attention out, fp16 [B,T,C]
__device__ fp16 g_w1[(size_t)1536 * Cz];          // W_att^T (k|v chunks), fp16
__device__ fp16 g_w2[(size_t)Cz * Cz];            // W_proj^T, fp16

// attention operands, [BH, T, D]
__device__ fp16 g_Kf[(size_t)BHz * Tz * Dz];
__device__ fp16 g_Qf[(size_t)BHz * Tz * Dz];
__device__ fp16 g_Vf[(size_t)BHz * Tz * Dz];

// ---------------------------------------------------------------------------
// Warp-MMA + async-copy helpers (sm_80-compatible under plain sm_100 target)
// ---------------------------------------------------------------------------
__device__ __forceinline__ uint32_t smem_u32(const void* p) {
    uint32_t a;
    asm("{ .reg .u64 t; cvta.to.shared.u64 t, %1; cvt.u32.u64 %0, t; }"
        : "=r"(a) : "l"(p));
    return a;
}
__device__ __forceinline__ void mma_f16(float* d, const uint32_t* a,
                                        uint32_t b0, uint32_t b1) {
    asm volatile(
        "mma.sync.aligned.m16n8k16.row.col.f32.f16.f16.f32 "
        "{%0,%1,%2,%3}, {%4,%5,%6,%7}, {%8,%9}, {%0,%1,%2,%3};"
        : "+f"(d[0]), "+f"(d[1]), "+f"(d[2]), "+f"(d[3])
        : "r"(a[0]), "r"(a[1]), "r"(a[2]), "r"(a[3]), "r"(b0), "r"(b1));
}
__device__ __forceinline__ void ldmx4(uint32_t* r, uint32_t addr) {
    asm volatile("ldmatrix.sync.aligned.m8n8.x4.shared.b16 {%0,%1,%2,%3}, [%4];"
        : "=r"(r[0]), "=r"(r[1]), "=r"(r[2]), "=r"(r[3]) : "r"(addr));
}
__device__ __forceinline__ void ldmx4t(uint32_t* r, uint32_t addr) {
    asm volatile("ldmatrix.sync.aligned.m8n8.x4.trans.shared.b16 {%0,%1,%2,%3}, [%4];"
        : "=r"(r[0]), "=r"(r[1]), "=r"(r[2]), "=r"(r[3]) : "r"(addr));
}
__device__ __forceinline__ void cpa16(uint32_t d, const void* s) {
    asm volatile("cp.async.cg.shared.global [%0], [%1], 16;" :: "r"(d), "l"(s));
}
#define CP_COMMIT() asm volatile("cp.async.commit_group;" ::: "memory")
#define CP_WAIT(n)  asm volatile("cp.async.wait_group %0;" :: "n"(n) : "memory")

__device__ __forceinline__ uint32_t packh2(float lo, float hi) {
    __half2 h = __floats2half2_rn(lo, hi);
    return *reinterpret_cast<uint32_t*>(&h);
}

// ---------------------------------------------------------------------------
// fp16 prep kernels
// ---------------------------------------------------------------------------
__global__ __launch_bounds__(256) void conv_rows_kernel(
    const float* __restrict__ in, fp16* __restrict__ out, int n)
{
    int i = blockIdx.x * 256 + threadIdx.x;
    if (i >= n) return;
    out[i] = __float2half_rn(in[i]);
}

// Merged tiled transposes: z=0 -> W_att (with k|v col remap), z=1 -> W_proj.
__global__ __launch_bounds__(256) void transT2_kernel(
    const float* __restrict__ W1, fp16* __restrict__ out1,
    const float* __restrict__ W2, fp16* __restrict__ out2)
{
    __shared__ float t[32][33];
    int tx = threadIdx.x & 31, ty = threadIdx.x >> 5;
    int z = blockIdx.z;
    int N = z ? Cz : 1536;
    int ldw = z ? Cz : 3 * Cz;
    if ((int)blockIdx.x * 32 >= N) return;
    const float* W = z ? W2 : W1;
    fp16* out = z ? out2 : out1;

    int n0 = blockIdx.x * 32;
    int k0 = blockIdx.y * 32;
    int col0 = n0 + ((!z && n0 >= 768) ? 768 : 0);   // v-chunk remap for W_att

    #pragma unroll
    for (int i = 0; i < 4; i++) {
        int k = k0 + ty + i * 8;
        t[ty + i * 8][tx] = W[(size_t)k * ldw + col0 + tx];
    }
    __syncthreads();
    #pragma unroll
    for (int i = 0; i < 4; i++) {
        int n = n0 + ty + i * 8;
        out[(size_t)n * Cz + k0 + tx] = __float2half_rn(t[tx][ty + i * 8]);
    }
}

// ---------------------------------------------------------------------------
// Dense GEMM via mma.sync fp16, single-pass, 2-stage cp.async.
// C[M,N] = A[M,K] @ Bt[N,K]^T. 128x128x32 CTA, 8 warps, 2 CTAs/SM.
// MODE 0: epilogue = fp32 C + bias (proj).
// MODE 1: epilogue = fused RoPE + fp16 prep (QKV).
// ---------------------------------------------------------------------------
#define MG_STRIDE 80            // 32 fp16 = 64B data + 16B pad
#define MG_A  0
#define MG_B  10240
#define MG_STAGE 20480
#define MG_SMEM (2 * MG_STAGE)  // 40960

template<int MODE>
__global__ __launch_bounds__(256, 2) void mm_gemm_kernel(
    const fp16* __restrict__ Af, const fp16* __restrict__ Bf,
    float* __restrict__ Cmat, const float* __restrict__ bias,
    const float* __restrict__ cosb, const float* __restrict__ sinb,
    fp16* __restrict__ Kf, fp16* __restrict__ Qf, fp16* __restrict__ Vf,
    int K, int ldc)
{
    extern __shared__ __align__(16) char gsm[];
    const uint32_t smb = smem_u32(gsm);
    const int tid  = threadIdx.x;
    const int w    = tid >> 5;
    const int lane = tid & 31;
    const int n0 = blockIdx.x * 128;
    const int m0 = blockIdx.y * 128;
    const int wm = w & 3;
    const int wn = w >> 2;

    auto load_stage = [&](int s, int kc) {
        uint32_t base = smb + s * MG_STAGE;
        #pragma unroll
        for (int it = 0; it < 2; it++) {
            int u   = tid + it * 256;
            int row = u >> 2, cc = u & 3;
            size_t ga = (size_t)(m0 + row) * K + kc + cc * 8;
            size_t gb = (size_t)(n0 + row) * K + kc + cc * 8;
            uint32_t off = (uint32_t)(row * MG_STRIDE + cc * 16);
            cpa16(base + MG_A + off, Af + ga);
            cpa16(base + MG_B + off, Bf + gb);
        }
    };

    float acc[2][8][4];
    #pragma unroll
    for (int a = 0; a < 2; a++)
        #pragma unroll
        for (int b = 0; b < 8; b++)
            #pragma unroll
            for (int c = 0; c < 4; c++) acc[a][b][c] = 0.f;

    const int arow = lane & 15, asel = lane >> 4;
    const int brow = lane & 7,  bsel = (lane >> 3) & 3;
    const int nch = K / 32;

    load_stage(0, 0);  CP_COMMIT();
    load_stage(1, 32); CP_COMMIT();

    for (int c = 0; c < nch; c++) {
        CP_WAIT(1);
        __syncthreads();
        const uint32_t sb = smb + (c & 1) * MG_STAGE;

        uint32_t af[2][2][4];
        uint32_t bq[4][4];

        #pragma unroll
        for (int ma = 0; ma < 2; ma++)
            #pragma unroll
            for (int ks = 0; ks < 2; ks++)
                ldmx4(af[ma][ks], sb + MG_A +
                      (uint32_t)((wm * 32 + ma * 16 + arow) * MG_STRIDE + ks * 32 + asel * 16));
        #pragma unroll
        for (int half = 0; half < 2; half++) {
            #pragma unroll
            for (int q = 0; q < 4; q++)
                ldmx4(bq[q], sb + MG_B +
                      (uint32_t)((wn * 64 + (half * 4 + q) * 8 + brow) * MG_STRIDE + bsel * 16));
            #pragma unroll
            for (int ks = 0; ks < 2; ks++)
                #pragma unroll
                for (int q = 0; q < 4; q++)
                    #pragma unroll
                    for (int ma = 0; ma < 2; ma++)
                        mma_f16(acc[ma][half * 4 + q], af[ma][ks], bq[q][2 * ks], bq[q][2 * ks + 1]);
        }

        __syncthreads();
        if (c + 2 < nch) load_stage(c & 1, (c + 2) * 32);
        CP_COMMIT();
    }

    const int rg = lane >> 2, cg = lane & 3;

    if (MODE == 0) {
        #pragma unroll
        for (int ma = 0; ma < 2; ma++) {
            int row = m0 + wm * 32 + ma * 16 + rg;
            #pragma unroll
            for (int na = 0; na < 8; na++) {
                int col = n0 + wn * 64 + na * 8 + 2 * cg;
                float b0 = bias ? bias[col] : 0.f;
                float b1 = bias ? bias[col + 1] : 0.f;
                *reinterpret_cast<float2*>(Cmat + (size_t)row * ldc + col) =
                    make_float2(acc[ma][na][0] + b0, acc[ma][na][1] + b1);
                *reinterpret_cast<float2*>(Cmat + (size_t)(row + 8) * ldc + col) =
                    make_float2(acc[ma][na][2] + b0, acc[ma][na][3] + b1);
            }
        }
    } else {
        // Fused RoPE epilogue. Whole CTA is k-chunk or v-chunk (n0 aligned to 768).
        const bool isv = (n0 >= 768);
        const float scale = 0.125f;   // D^-0.5, folded into Q
        #pragma unroll
        for (int ma = 0; ma < 2; ma++) {
            int row = m0 + wm * 32 + ma * 16 + rg;   // = b*T + t
            int b  = row >> 11;
            int t0 = row & (Tz - 1);
            int t1 = t0 + 8;
            #pragma unroll
            for (int na = 0; na < 8; na++) {
                int col = n0 + wn * 64 + na * 8 + 2 * cg;
                int ch  = isv ? col - 768 : col;
                int h   = ch >> 6;
                int d   = ch & 63;
                int i   = d >> 1;
                float c0 = cosb[t0 * 32 + i], s0 = sinb[t0 * 32 + i];
                float c1 = cosb[t1 * 32 + i], s1 = sinb[t1 * 32 + i];
                size_t o0 = ((size_t)(b * Hz + h) * Tz + t0) * Dz + d;
                size_t o1 = ((size_t)(b * Hz + h) * Tz + t1) * Dz + d;
                float v0 = acc[ma][na][0], v1 = acc[ma][na][1];
                float v2 = acc[ma][na][2], v3 = acc[ma][na][3];
                if (!isv) {
                    *reinterpret_cast<uint32_t*>(Kf + o0) =
                        packh2(v0 * c0 - v1 * s0, v0 * s0 + v1 * c0);
                    *reinterpret_cast<uint32_t*>(Kf + o1) =
                        packh2(v2 * c1 - v3 * s1, v2 * s1 + v3 * c1);
                } else {
                    *reinterpret_cast<uint32_t*>(Qf + o0) =
                        packh2((v0 * c0 - v1 * s0) * scale, (v0 * s0 + v1 * c0) * scale);
                    *reinterpret_cast<uint32_t*>(Qf + o1) =
                        packh2((v2 * c1 - v3 * s1) * scale, (v2 * s1 + v3 * c1) * scale);
                    *reinterpret_cast<uint32_t*>(Vf + o0) = packh2(v0, v1);
                    *reinterpret_cast<uint32_t*>(Vf + o1) = packh2(v2, v3);
                }
            }
        }
    }
}

// ---------------------------------------------------------------------------
// Flash attention via fp16 mma.sync: S = Qf x Kf (1 pass), PV = P x Vf (1 pass).
// 2-stage cp.async on K/V. 128 q-rows x 128 keys, 8 warps x 16 q-rows.
// Epilogue emits att as fp16 rn (single).
// ---------------------------------------------------------------------------
#define FL_STRIDE 144                // 64 fp16 = 128B + 16B pad
#define FL_TILE   (128 * FL_STRIDE)  // 18432
#define FL_STAGE  (2 * FL_TILE)      // KF,VF = 36864
#define FL_Q      (2 * FL_STAGE)     // 73728
#define FL6_SMEM  (FL_Q + FL_TILE)   // 92160

__global__ __launch_bounds__(256) void flash6_kernel(
    const fp16* __restrict__ Qf, const fp16* __restrict__ Kf,
    const fp16* __restrict__ Vf, fp16* __restrict__ Of)
{
    extern __shared__ __align__(16) char sm6[];
    const uint32_t smb = smem_u32(sm6);
    const int tid  = threadIdx.x;
    const int w    = tid >> 5;
    const int lane = tid & 31;
    const int qt   = (int)gridDim.x - 1 - (int)blockIdx.x;   // heavy tiles first
    const int bh   = blockIdx.y;
    const size_t hb = (size_t)bh * Tz * Dz;

    auto load_kv = [&](int s, int j) {
        uint32_t base = smb + s * FL_STAGE;
        const size_t kb = hb + (size_t)j * 128 * 64;
        #pragma unroll
        for (int it = 0; it < 4; it++) {
            int u = tid + it * 256;
            int row = u >> 3, cc = u & 7;
            uint32_t off = (uint32_t)(row * FL_STRIDE + cc * 16);
            size_t g = kb + row * 64 + cc * 8;
            cpa16(base + 0 * FL_TILE + off, Kf + g);
            cpa16(base + 1 * FL_TILE + off, Vf + g);
        }
    };

    load_kv(0, 0);
    CP_COMMIT();
    {
        const fp16* qsrc = Qf + hb + (size_t)qt * 128 * 64;
        #pragma unroll
        for (int it = 0; it < 4; it++) {
            int u = tid + it * 256;
            int row = u >> 3, cc = u & 7;
            *reinterpret_cast<uint4*>(sm6 + FL_Q + row * FL_STRIDE + cc * 16) =
                *reinterpret_cast<const uint4*>(qsrc + row * 64 + cc * 8);
        }
    }
    __syncthreads();

    uint32_t qf[16];
    {
        int arow = lane & 15, asel = lane >> 4;
        #pragma unroll
        for (int ka = 0; ka < 4; ka++)
            ldmx4(qf + ka * 4, smb + FL_Q +
                  (uint32_t)((16 * w + arow) * FL_STRIDE + ka * 32 + asel * 16));
    }

    float o[8][4];
    #pragma unroll
    for (int nv = 0; nv < 8; nv++)
        #pragma unroll
        for (int c = 0; c < 4; c++) o[nv][c] = 0.f;
    float mA = -1e30f, mB = -1e30f, lA = 0.f, lB = 0.f;

    const int rg = lane >> 2, cg = lane & 3;
    const int brow = lane & 7, bsel = (lane >> 3) & 3;
    const int vkey = lane & 15, vsel = lane >> 4;

    for (int jt = 0; jt <= qt; jt++) {
        if (jt < qt) load_kv((jt + 1) & 1, jt + 1);
        CP_COMMIT();
        CP_WAIT(1);
        __syncthreads();

        const uint32_t sb = smb + (jt & 1) * FL_STAGE;

        // ---- S = Q@K^T, single-pass fp16 ----
        float s[16][4];
        #pragma unroll
        for (int na = 0; na < 16; na++)
            #pragma unroll
            for (int c = 0; c < 4; c++) s[na][c] = 0.f;

        #pragma unroll
        for (int kp = 0; kp < 2; kp++) {
            #pragma unroll
            for (int half = 0; half < 2; half++) {
                uint32_t kf[8][4];
                #pragma unroll
                for (int q = 0; q < 8; q++)
                    ldmx4(kf[q], sb +
                          (uint32_t)(((half * 8 + q) * 8 + brow) * FL_STRIDE + kp * 64 + bsel * 16));
                #pragma unroll
                for (int j = 0; j < 2; j++)
                    #pragma unroll
                    for (int q = 0; q < 8; q++)
                        mma_f16(s[half * 8 + q], qf + (2 * kp + j) * 4, kf[q][2 * j], kf[q][2 * j + 1]);
            }
        }

        // ---- causal mask (diagonal tile) ----
        if (jt == qt) {
            int rA = 16 * w + rg, rB = rA + 8;
            #pragma unroll
            for (int na = 0; na < 16; na++) {
                int c0 = 8 * na + 2 * cg;
                if (c0 > rA)     s[na][0] = -1e30f;
                if (c0 + 1 > rA) s[na][1] = -1e30f;
                if (c0 > rB)     s[na][2] = -1e30f;
                if (c0 + 1 > rB) s[na][3] = -1e30f;
            }
        }

        // ---- online softmax: row maxes + rescale ----
        float xA = -1e30f, xB = -1e30f;
        #pragma unroll
        for (int na = 0; na < 16; na++) {
            xA = fmaxf(xA, fmaxf(s[na][0], s[na][1]));
            xB = fmaxf(xB, fmaxf(s[na][2], s[na][3]));
        }
        xA = fmaxf(xA, __shfl_xor_sync(0xffffffffu, xA, 1));
        xA = fmaxf(xA, __shfl_xor_sync(0xffffffffu, xA, 2));
        xB = fmaxf(xB, __shfl_xor_sync(0xffffffffu, xB, 1));
        xB = fmaxf(xB, __shfl_xor_sync(0xffffffffu, xB, 2));
        float nmA = fmaxf(mA, xA), nmB = fmaxf(mB, xB);
        float cA = __expf(mA - nmA), cB = __expf(mB - nmB);
        mA = nmA; mB = nmB;
        #pragma unroll
        for (int nv = 0; nv < 8; nv++) {
            o[nv][0] *= cA; o[nv][1] *= cA;
            o[nv][2] *= cB; o[nv][3] *= cB;
        }

        // ---- PV: exp -> fp16(rn) P, single-pass V mma ----
        float sA = 0.f, sB = 0.f;
        #pragma unroll
        for (int ka = 0; ka < 8; ka++) {
            float e00 = __expf(s[2 * ka][0] - nmA);
            float e01 = __expf(s[2 * ka][1] - nmA);
            float e02 = __expf(s[2 * ka][2] - nmB);
            float e03 = __expf(s[2 * ka][3] - nmB);
            float e10 = __expf(s[2 * ka + 1][0] - nmA);
            float e11 = __expf(s[2 * ka + 1][1] - nmA);
            float e12 = __expf(s[2 * ka + 1][2] - nmB);
            float e13 = __expf(s[2 * ka + 1][3] - nmB);
            sA += (e00 + e01) + (e10 + e11);
            sB += (e02 + e03) + (e12 + e13);

            uint32_t p4[4];
            p4[0] = packh2(e00, e01);
            p4[1] = packh2(e02, e03);
            p4[2] = packh2(e10, e11);
            p4[3] = packh2(e12, e13);

            uint32_t vf[4][4];
            #pragma unroll
            for (int nv = 0; nv < 4; nv++)
                ldmx4t(vf[nv], sb + 1 * FL_TILE +
                       (uint32_t)((ka * 16 + vkey) * FL_STRIDE + (nv * 16 + vsel * 8) * 2));
            #pragma unroll
            for (int nv = 0; nv < 4; nv++) {
                mma_f16(o[2 * nv],     p4, vf[nv][0], vf[nv][1]);
                mma_f16(o[2 * nv + 1], p4, vf[nv][2], vf[nv][3]);
            }
        }
        sA += __shfl_xor_sync(0xffffffffu, sA, 1);
        sA += __shfl_xor_sync(0xffffffffu, sA, 2);
        sB += __shfl_xor_sync(0xffffffffu, sB, 1);
        sB += __shfl_xor_sync(0xffffffffu, sB, 2);
        lA = lA * cA + sA;
        lB = lB * cB + sB;

        __syncthreads();   // protect stage (jt&1) from next iter's prefetch
    }

    // ---- normalize + write fp16 [B,T,C] ----
    const int b = bh / Hz, h = bh % Hz;
    const float invA = 1.f / lA, invB = 1.f / lB;
    int rA = qt * 128 + 16 * w + rg;
    #pragma unroll
    for (int nv = 0; nv < 8; nv++) {
        int col = h * 64 + nv * 8 + 2 * cg;
        size_t baseA = (size_t)(b * Tz + rA) * Cz + col;
        size_t baseB = (size_t)(b * Tz + rA + 8) * Cz + col;
        *reinterpret_cast<uint32_t*>(Of + baseA) =
            packh2(o[nv][0] * invA, o[nv][1] * invA);
        *reinterpret_cast<uint32_t*>(Of + baseB) =
            packh2(o[nv][2] * invB, o[nv][3] * invB);
    }
}

// ---------------------------------------------------------------------------
// kernel_launch
// ---------------------------------------------------------------------------
extern "C" void kernel_launch(void* const* d_in, const int* in_sizes, int n_in,
                              void* d_out, int out_size)
{
    const float* x      = (const float*)d_in[0];
    const float* cosb   = (const float*)d_in[1];
    const float* sinb   = (const float*)d_in[2];
    const float* W_att  = (const float*)d_in[3];
    const float* W_proj = (const float*)d_in[4];
    const float* b_proj = (const float*)d_in[5];
    float* out = (float*)d_out;

    fp16 *xf, *af, *w1, *w2, *Kfp, *Qfp, *Vfp;
    cudaGetSymbolAddress((void**)&xf,  g_xf);
    cudaGetSymbolAddress((void**)&af,  g_af);
    cudaGetSymbolAddress((void**)&w1,  g_w1);
    cudaGetSymbolAddress((void**)&w2,  g_w2);
    cudaGetSymbolAddress((void**)&Kfp, g_Kf);
    cudaGetSymbolAddress((void**)&Qfp, g_Qf);
    cudaGetSymbolAddress((void**)&Vfp, g_Vf);

    cudaFuncSetAttribute(mm_gemm_kernel<0>,
                         cudaFuncAttributeMaxDynamicSharedMemorySize, MG_SMEM);
    cudaFuncSetAttribute(mm_gemm_kernel<1>,
                         cudaFuncAttributeMaxDynamicSharedMemorySize, MG_SMEM);
    cudaFuncSetAttribute(flash6_kernel,
                         cudaFuncAttributeMaxDynamicSharedMemorySize, FL6_SMEM);

    // prep: x -> fp16 + merged weight transposes
    conv_rows_kernel<<<(Mz * Cz + 255) / 256, 256>>>(x, xf, Mz * Cz);
    transT2_kernel<<<dim3(1536 / 32, Cz / 32, 2), 256>>>(W_att, w1, W_proj, w2);

    // 1) QKV GEMM + fused RoPE epilogue -> Kf / Qf / Vf  [BH,T,D]
    mm_gemm_kernel<1><<<dim3(1536 / 128, Mz / 128), 256, MG_SMEM>>>(
        xf, w1, nullptr, nullptr, cosb, sinb, Kfp, Qfp, Vfp, Cz, 0);

    // 2) Flash attention (fp16 single-pass S and PV) -> af [B,T,C] fp16
    flash6_kernel<<<dim3(Tz / 128, BHz), 256, FL6_SMEM>>>(
        Qfp, Kfp, Vfp, af);

    // 3) proj GEMM + bias -> d_out
    mm_gemm_kernel<0><<<dim3(Cz / 128, Mz / 128), 256, MG_SMEM>>>(
        af, w2, out, b_proj, nullptr, nullptr,
        nullptr, nullptr, nullptr, Cz, Cz);
}

// round 12
// speedup vs baseline: 14.0217x; 1.0253x over previous
#include <cuda_runtime.h>
#include <cuda_fp16.h>
#include <cstdint>

// Problem constants
#define Bz 2
#define Tz 2048
#define Cz 768
#define Hz 12
#define Dz 64
#define BHz (Bz*Hz)        // 24
#define Mz (Bz*Tz)         // 4096

typedef __half fp16;

// ---------------------------------------------------------------------------
// Scratch (static device arrays — no cudaMalloc allowed)
// ---------------------------------------------------------------------------
__device__ fp16 g_xf[(size_t)Mz * Cz];            // x, fp16
__device__ fp16 g_af[(size_t)Mz * Cz];            // attention out, fp16 [B,T,C]
__device__ fp16 g_w1[(size_t)1536 * Cz];          // W_att^T (k|v chunks), fp16
__device__ fp16 g_w2[(size_t)Cz * Cz];            // W_proj^T, fp16

// attention operands, [BH, T, D]
__device__ fp16 g_Kf[(size_t)BHz * Tz * Dz];
__device__ fp16 g_Qf[(size_t)BHz * Tz * Dz];      // rope(v) * 0.125 * log2(e)
__device__ fp16 g_Vf[(size_t)BHz * Tz * Dz];

// ---------------------------------------------------------------------------
// Warp-MMA + async-copy helpers (sm_80-compatible under plain sm_100 target)
// ---------------------------------------------------------------------------
__device__ __forceinline__ uint32_t smem_u32(const void* p) {
    uint32_t a;
    asm("{ .reg .u64 t; cvta.to.shared.u64 t, %1; cvt.u32.u64 %0, t; }"
        : "=r"(a) : "l"(p));
    return a;
}
__device__ __forceinline__ void mma_f16(float* d, const uint32_t* a,
                                        uint32_t b0, uint32_t b1) {
    asm volatile(
        "mma.sync.aligned.m16n8k16.row.col.f32.f16.f16.f32 "
        "{%0,%1,%2,%3}, {%4,%5,%6,%7}, {%8,%9}, {%0,%1,%2,%3};"
        : "+f"(d[0]), "+f"(d[1]), "+f"(d[2]), "+f"(d[3])
        : "r"(a[0]), "r"(a[1]), "r"(a[2]), "r"(a[3]), "r"(b0), "r"(b1));
}
__device__ __forceinline__ void ldmx4(uint32_t* r, uint32_t addr) {
    asm volatile("ldmatrix.sync.aligned.m8n8.x4.shared.b16 {%0,%1,%2,%3}, [%4];"
        : "=r"(r[0]), "=r"(r[1]), "=r"(r[2]), "=r"(r[3]) : "r"(addr));
}
__device__ __forceinline__ void ldmx4t(uint32_t* r, uint32_t addr) {
    asm volatile("ldmatrix.sync.aligned.m8n8.x4.trans.shared.b16 {%0,%1,%2,%3}, [%4];"
        : "=r"(r[0]), "=r"(r[1]), "=r"(r[2]), "=r"(r[3]) : "r"(addr));
}
__device__ __forceinline__ void cpa16(uint32_t d, const void* s) {
    asm volatile("cp.async.cg.shared.global [%0], [%1], 16;" :: "r"(d), "l"(s));
}
#define CP_COMMIT() asm volatile("cp.async.commit_group;" ::: "memory")
#define CP_WAIT(n)  asm volatile("cp.async.wait_group %0;" :: "n"(n) : "memory")

__device__ __forceinline__ uint32_t packh2(float lo, float hi) {
    __half2 h = __floats2half2_rn(lo, hi);
    return *reinterpret_cast<uint32_t*>(&h);
}
// raw ex2.approx (exp2) — single MUFU op
__device__ __forceinline__ float ex2(float x) {
    float y;
    asm("ex2.approx.ftz.f32 %0, %1;" : "=f"(y) : "f"(x));
    return y;
}

// ---------------------------------------------------------------------------
// fp16 prep kernels
// ---------------------------------------------------------------------------
__global__ __launch_bounds__(256) void conv_rows_kernel(
    const float* __restrict__ in, fp16* __restrict__ out, int n)
{
    int i = blockIdx.x * 256 + threadIdx.x;
    if (i >= n) return;
    out[i] = __float2half_rn(in[i]);
}

// Merged tiled transposes: z=0 -> W_att (with k|v col remap), z=1 -> W_proj.
__global__ __launch_bounds__(256) void transT2_kernel(
    const float* __restrict__ W1, fp16* __restrict__ out1,
    const float* __restrict__ W2, fp16* __restrict__ out2)
{
    __shared__ float t[32][33];
    int tx = threadIdx.x & 31, ty = threadIdx.x >> 5;
    int z = blockIdx.z;
    int N = z ? Cz : 1536;
    int ldw = z ? Cz : 3 * Cz;
    if ((int)blockIdx.x * 32 >= N) return;
    const float* W = z ? W2 : W1;
    fp16* out = z ? out2 : out1;

    int n0 = blockIdx.x * 32;
    int k0 = blockIdx.y * 32;
    int col0 = n0 + ((!z && n0 >= 768) ? 768 : 0);   // v-chunk remap for W_att

    #pragma unroll
    for (int i = 0; i < 4; i++) {
        int k = k0 + ty + i * 8;
        t[ty + i * 8][tx] = W[(size_t)k * ldw + col0 + tx];
    }
    __syncthreads();
    #pragma unroll
    for (int i = 0; i < 4; i++) {
        int n = n0 + ty + i * 8;
        out[(size_t)n * Cz + k0 + tx] = __float2half_rn(t[tx][ty + i * 8]);
    }
}

// ---------------------------------------------------------------------------
// Dense GEMM via mma.sync fp16, single-pass, 2-stage cp.async.
// C[M,N] = A[M,K] @ Bt[N,K]^T. 128x128x32 CTA, 8 warps, 2 CTAs/SM.
// MODE 0: epilogue = fp32 C + bias (proj).
// MODE 1: epilogue = fused RoPE + fp16 prep (QKV). Q scale folds log2(e).
// ---------------------------------------------------------------------------
#define MG_STRIDE 80            // 32 fp16 = 64B data + 16B pad
#define MG_A  0
#define MG_B  10240
#define MG_STAGE 20480
#define MG_SMEM (2 * MG_STAGE)  // 40960

template<int MODE>
__global__ __launch_bounds__(256, 2) void mm_gemm_kernel(
    const fp16* __restrict__ Af, const fp16* __restrict__ Bf,
    float* __restrict__ Cmat, const float* __restrict__ bias,
    const float* __restrict__ cosb, const float* __restrict__ sinb,
    fp16* __restrict__ Kf, fp16* __restrict__ Qf, fp16* __restrict__ Vf,
    int K, int ldc)
{
    extern __shared__ __align__(16) char gsm[];
    const uint32_t smb = smem_u32(gsm);
    const int tid  = threadIdx.x;
    const int w    = tid >> 5;
    const int lane = tid & 31;
    const int n0 = blockIdx.x * 128;
    const int m0 = blockIdx.y * 128;
    const int wm = w & 3;
    const int wn = w >> 2;

    auto load_stage = [&](int s, int kc) {
        uint32_t base = smb + s * MG_STAGE;
        #pragma unroll
        for (int it = 0; it < 2; it++) {
            int u   = tid + it * 256;
            int row = u >> 2, cc = u & 3;
            size_t ga = (size_t)(m0 + row) * K + kc + cc * 8;
            size_t gb = (size_t)(n0 + row) * K + kc + cc * 8;
            uint32_t off = (uint32_t)(row * MG_STRIDE + cc * 16);
            cpa16(base + MG_A + off, Af + ga);
            cpa16(base + MG_B + off, Bf + gb);
        }
    };

    float acc[2][8][4];
    #pragma unroll
    for (int a = 0; a < 2; a++)
        #pragma unroll
        for (int b = 0; b < 8; b++)
            #pragma unroll
            for (int c = 0; c < 4; c++) acc[a][b][c] = 0.f;

    const int arow = lane & 15, asel = lane >> 4;
    const int brow = lane & 7,  bsel = (lane >> 3) & 3;
    const int nch = K / 32;

    load_stage(0, 0);  CP_COMMIT();
    load_stage(1, 32); CP_COMMIT();

    for (int c = 0; c < nch; c++) {
        CP_WAIT(1);
        __syncthreads();
        const uint32_t sb = smb + (c & 1) * MG_STAGE;

        uint32_t af[2][2][4];
        uint32_t bq[4][4];

        #pragma unroll
        for (int ma = 0; ma < 2; ma++)
            #pragma unroll
            for (int ks = 0; ks < 2; ks++)
                ldmx4(af[ma][ks], sb + MG_A +
                      (uint32_t)((wm * 32 + ma * 16 + arow) * MG_STRIDE + ks * 32 + asel * 16));
        #pragma unroll
        for (int half = 0; half < 2; half++) {
            #pragma unroll
            for (int q = 0; q < 4; q++)
                ldmx4(bq[q], sb + MG_B +
                      (uint32_t)((wn * 64 + (half * 4 + q) * 8 + brow) * MG_STRIDE + bsel * 16));
            #pragma unroll
            for (int ks = 0; ks < 2; ks++)
                #pragma unroll
                for (int q = 0; q < 4; q++)
                    #pragma unroll
                    for (int ma = 0; ma < 2; ma++)
                        mma_f16(acc[ma][half * 4 + q], af[ma][ks], bq[q][2 * ks], bq[q][2 * ks + 1]);
        }

        __syncthreads();
        if (c + 2 < nch) load_stage(c & 1, (c + 2) * 32);
        CP_COMMIT();
    }

    const int rg = lane >> 2, cg = lane & 3;

    if (MODE == 0) {
        #pragma unroll
        for (int ma = 0; ma < 2; ma++) {
            int row = m0 + wm * 32 + ma * 16 + rg;
            #pragma unroll
            for (int na = 0; na < 8; na++) {
                int col = n0 + wn * 64 + na * 8 + 2 * cg;
                float b0 = bias ? bias[col] : 0.f;
                float b1 = bias ? bias[col + 1] : 0.f;
                *reinterpret_cast<float2*>(Cmat + (size_t)row * ldc + col) =
                    make_float2(acc[ma][na][0] + b0, acc[ma][na][1] + b1);
                *reinterpret_cast<float2*>(Cmat + (size_t)(row + 8) * ldc + col) =
                    make_float2(acc[ma][na][2] + b0, acc[ma][na][3] + b1);
            }
        }
    } else {
        // Fused RoPE epilogue. Whole CTA is k-chunk or v-chunk (n0 aligned to 768).
        const bool isv = (n0 >= 768);
        // Q scale = D^-0.5 * log2(e): softmax runs in exp2 domain.
        const float scale = 0.125f * 1.4426950408889634f;
        #pragma unroll
        for (int ma = 0; ma < 2; ma++) {
            int row = m0 + wm * 32 + ma * 16 + rg;   // = b*T + t
            int b  = row >> 11;
            int t0 = row & (Tz - 1);
            int t1 = t0 + 8;
            #pragma unroll
            for (int na = 0; na < 8; na++) {
                int col = n0 + wn * 64 + na * 8 + 2 * cg;
                int ch  = isv ? col - 768 : col;
                int h   = ch >> 6;
                int d   = ch & 63;
                int i   = d >> 1;
                float c0 = cosb[t0 * 32 + i], s0 = sinb[t0 * 32 + i];
                float c1 = cosb[t1 * 32 + i], s1 = sinb[t1 * 32 + i];
                size_t o0 = ((size_t)(b * Hz + h) * Tz + t0) * Dz + d;
                size_t o1 = ((size_t)(b * Hz + h) * Tz + t1) * Dz + d;
                float v0 = acc[ma][na][0], v1 = acc[ma][na][1];
                float v2 = acc[ma][na][2], v3 = acc[ma][na][3];
                if (!isv) {
                    *reinterpret_cast<uint32_t*>(Kf + o0) =
                        packh2(v0 * c0 - v1 * s0, v0 * s0 + v1 * c0);
                    *reinterpret_cast<uint32_t*>(Kf + o1) =
                        packh2(v2 * c1 - v3 * s1, v2 * s1 + v3 * c1);
                } else {
                    *reinterpret_cast<uint32_t*>(Qf + o0) =
                        packh2((v0 * c0 - v1 * s0) * scale, (v0 * s0 + v1 * c0) * scale);
                    *reinterpret_cast<uint32_t*>(Qf + o1) =
                        packh2((v2 * c1 - v3 * s1) * scale, (v2 * s1 + v3 * c1) * scale);
                    *reinterpret_cast<uint32_t*>(Vf + o0) = packh2(v0, v1);
                    *reinterpret_cast<uint32_t*>(Vf + o1) = packh2(v2, v3);
                }
            }
        }
    }
}

// ---------------------------------------------------------------------------
// Flash attention via fp16 mma.sync, exp2-domain softmax, MMA row-sums.
// S = Qf x Kf (1 pass), PV = P x Vf (1 pass), l = P x ones via MMA.
// 2-stage cp.async on K/V. 128 q-rows x 128 keys, 8 warps x 16 q-rows.
// ---------------------------------------------------------------------------
#define FL_STRIDE 144                // 64 fp16 = 128B + 16B pad
#define FL_TILE   (128 * FL_STRIDE)  // 18432
#define FL_STAGE  (2 * FL_TILE)      // KF,VF = 36864
#define FL_Q      (2 * FL_STAGE)     // 73728
#define FL7_SMEM  (FL_Q + FL_TILE)   // 92160

__global__ __launch_bounds__(256) void flash7_kernel(
    const fp16* __restrict__ Qf, const fp16* __restrict__ Kf,
    const fp16* __restrict__ Vf, fp16* __restrict__ Of)
{
    extern __shared__ __align__(16) char sm7[];
    const uint32_t smb = smem_u32(sm7);
    const int tid  = threadIdx.x;
    const int w    = tid >> 5;
    const int lane = tid & 31;
    const int qt   = (int)gridDim.x - 1 - (int)blockIdx.x;   // heavy tiles first
    const int bh   = blockIdx.y;
    const size_t hb = (size_t)bh * Tz * Dz;
    const uint32_t ONES = 0x3C003C00u;   // fp16 {1,1}

    auto load_kv = [&](int s, int j) {
        uint32_t base = smb + s * FL_STAGE;
        const size_t kb = hb + (size_t)j * 128 * 64;
        #pragma unroll
        for (int it = 0; it < 4; it++) {
            int u = tid + it * 256;
            int row = u >> 3, cc = u & 7;
            uint32_t off = (uint32_t)(row * FL_STRIDE + cc * 16);
            size_t g = kb + row * 64 + cc * 8;
            cpa16(base + 0 * FL_TILE + off, Kf + g);
            cpa16(base + 1 * FL_TILE + off, Vf + g);
        }
    };

    load_kv(0, 0);
    CP_COMMIT();
    {
        const fp16* qsrc = Qf + hb + (size_t)qt * 128 * 64;
        #pragma unroll
        for (int it = 0; it < 4; it++) {
            int u = tid + it * 256;
            int row = u >> 3, cc = u & 7;
            *reinterpret_cast<uint4*>(sm7 + FL_Q + row * FL_STRIDE + cc * 16) =
                *reinterpret_cast<const uint4*>(qsrc + row * 64 + cc * 8);
        }
    }
    __syncthreads();

    uint32_t qf[16];
    {
        int arow = lane & 15, asel = lane >> 4;
        #pragma unroll
        for (int ka = 0; ka < 4; ka++)
            ldmx4(qf + ka * 4, smb + FL_Q +
                  (uint32_t)((16 * w + arow) * FL_STRIDE + ka * 32 + asel * 16));
    }

    float o[8][4];
    #pragma unroll
    for (int nv = 0; nv < 8; nv++)
        #pragma unroll
        for (int c = 0; c < 4; c++) o[nv][c] = 0.f;
    float mA = -1e30f, mB = -1e30f, lA = 0.f, lB = 0.f;

    const int rg = lane >> 2, cg = lane & 3;
    const int brow = lane & 7, bsel = (lane >> 3) & 3;
    const int vkey = lane & 15, vsel = lane >> 4;

    for (int jt = 0; jt <= qt; jt++) {
        if (jt < qt) load_kv((jt + 1) & 1, jt + 1);
        CP_COMMIT();
        CP_WAIT(1);
        __syncthreads();

        const uint32_t sb = smb + (jt & 1) * FL_STAGE;

        // ---- S = Q@K^T (log2 domain), single-pass fp16 ----
        float s[16][4];
        #pragma unroll
        for (int na = 0; na < 16; na++)
            #pragma unroll
            for (int c = 0; c < 4; c++) s[na][c] = 0.f;

        #pragma unroll
        for (int kp = 0; kp < 2; kp++) {
            #pragma unroll
            for (int half = 0; half < 2; half++) {
                uint32_t kf[8][4];
                #pragma unroll
                for (int q = 0; q < 8; q++)
                    ldmx4(kf[q], sb +
                          (uint32_t)(((half * 8 + q) * 8 + brow) * FL_STRIDE + kp * 64 + bsel * 16));
                #pragma unroll
                for (int j = 0; j < 2; j++)
                    #pragma unroll
                    for (int q = 0; q < 8; q++)
                        mma_f16(s[half * 8 + q], qf + (2 * kp + j) * 4, kf[q][2 * j], kf[q][2 * j + 1]);
            }
        }

        // ---- causal mask (diagonal tile) ----
        if (jt == qt) {
            int rA = 16 * w + rg, rB = rA + 8;
            #pragma unroll
            for (int na = 0; na < 16; na++) {
                int c0 = 8 * na + 2 * cg;
                if (c0 > rA)     s[na][0] = -1e30f;
                if (c0 + 1 > rA) s[na][1] = -1e30f;
                if (c0 > rB)     s[na][2] = -1e30f;
                if (c0 + 1 > rB) s[na][3] = -1e30f;
            }
        }

        // ---- online softmax: row maxes + rescale (log2 domain) ----
        float xA = -1e30f, xB = -1e30f;
        #pragma unroll
        for (int na = 0; na < 16; na++) {
            xA = fmaxf(xA, fmaxf(s[na][0], s[na][1]));
            xB = fmaxf(xB, fmaxf(s[na][2], s[na][3]));
        }
        xA = fmaxf(xA, __shfl_xor_sync(0xffffffffu, xA, 1));
        xA = fmaxf(xA, __shfl_xor_sync(0xffffffffu, xA, 2));
        xB = fmaxf(xB, __shfl_xor_sync(0xffffffffu, xB, 1));
        xB = fmaxf(xB, __shfl_xor_sync(0xffffffffu, xB, 2));
        float nmA = fmaxf(mA, xA), nmB = fmaxf(mB, xB);
        float cA = ex2(mA - nmA), cB = ex2(mB - nmB);
        mA = nmA; mB = nmB;
        #pragma unroll
        for (int nv = 0; nv < 8; nv++) {
            o[nv][0] *= cA; o[nv][1] *= cA;
            o[nv][2] *= cB; o[nv][3] *= cB;
        }

        // ---- PV: exp2 -> fp16 P; V mma; row-sums via ones-MMA ----
        float lacc[4] = {0.f, 0.f, 0.f, 0.f};
        #pragma unroll
        for (int ka = 0; ka < 8; ka++) {
            float e00 = ex2(s[2 * ka][0] - nmA);
            float e01 = ex2(s[2 * ka][1] - nmA);
            float e02 = ex2(s[2 * ka][2] - nmB);
            float e03 = ex2(s[2 * ka][3] - nmB);
            float e10 = ex2(s[2 * ka + 1][0] - nmA);
            float e11 = ex2(s[2 * ka + 1][1] - nmA);
            float e12 = ex2(s[2 * ka + 1][2] - nmB);
            float e13 = ex2(s[2 * ka + 1][3] - nmB);

            uint32_t p4[4];
            p4[0] = packh2(e00, e01);
            p4[1] = packh2(e02, e03);
            p4[2] = packh2(e10, e11);
            p4[3] = packh2(e12, e13);

            mma_f16(lacc, p4, ONES, ONES);   // row sums of quantized P

            uint32_t vf[4][4];
            #pragma unroll
            for (int nv = 0; nv < 4; nv++)
                ldmx4t(vf[nv], sb + 1 * FL_TILE +
                       (uint32_t)((ka * 16 + vkey) * FL_STRIDE + (nv * 16 + vsel * 8) * 2));
            #pragma unroll
            for (int nv = 0; nv < 4; nv++) {
                mma_f16(o[2 * nv],     p4, vf[nv][0], vf[nv][1]);
                mma_f16(o[2 * nv + 1], p4, vf[nv][2], vf[nv][3]);
            }
        }
        lA = lA * cA + lacc[0];
        lB = lB * cB + lacc[2];

        __syncthreads();   // protect stage (jt&1) from next iter's prefetch
    }

    // ---- normalize + write fp16 [B,T,C] ----
    const int b = bh / Hz, h = bh % Hz;
    const float invA = 1.f / lA, invB = 1.f / lB;
    int rA = qt * 128 + 16 * w + rg;
    #pragma unroll
    for (int nv = 0; nv < 8; nv++) {
        int col = h * 64 + nv * 8 + 2 * cg;
        size_t baseA = (size_t)(b * Tz + rA) * Cz + col;
        size_t baseB = (size_t)(b * Tz + rA + 8) * Cz + col;
        *reinterpret_cast<uint32_t*>(Of + baseA) =
            packh2(o[nv][0] * invA, o[nv][1] * invA);
        *reinterpret_cast<uint32_t*>(Of + baseB) =
            packh2(o[nv][2] * invB, o[nv][3] * invB);
    }
}

// ---------------------------------------------------------------------------
// kernel_launch
// ---------------------------------------------------------------------------
extern "C" void kernel_launch(void* const* d_in, const int* in_sizes, int n_in,
                              void* d_out, int out_size)
{
    const float* x      = (const float*)d_in[0];
    const float* cosb   = (const float*)d_in[1];
    const float* sinb   = (const float*)d_in[2];
    const float* W_att  = (const float*)d_in[3];
    const float* W_proj = (const float*)d_in[4];
    const float* b_proj = (const float*)d_in[5];
    float* out = (float*)d_out;

    fp16 *xf, *af, *w1, *w2, *Kfp, *Qfp, *Vfp;
    cudaGetSymbolAddress((void**)&xf,  g_xf);
    cudaGetSymbolAddress((void**)&af,  g_af);
    cudaGetSymbolAddress((void**)&w1,  g_w1);
    cudaGetSymbolAddress((void**)&w2,  g_w2);
    cudaGetSymbolAddress((void**)&Kfp, g_Kf);
    cudaGetSymbolAddress((void**)&Qfp, g_Qf);
    cudaGetSymbolAddress((void**)&Vfp, g_Vf);

    cudaFuncSetAttribute(mm_gemm_kernel<0>,
                         cudaFuncAttributeMaxDynamicSharedMemorySize, MG_SMEM);
    cudaFuncSetAttribute(mm_gemm_kernel<1>,
                         cudaFuncAttributeMaxDynamicSharedMemorySize, MG_SMEM);
    cudaFuncSetAttribute(flash7_kernel,
                         cudaFuncAttributeMaxDynamicSharedMemorySize, FL7_SMEM);

    // prep: x -> fp16 + merged weight transposes
    conv_rows_kernel<<<(Mz * Cz + 255) / 256, 256>>>(x, xf, Mz * Cz);
    transT2_kernel<<<dim3(1536 / 32, Cz / 32, 2), 256>>>(W_att, w1, W_proj, w2);

    // 1) QKV GEMM + fused RoPE epilogue -> Kf / Qf / Vf  [BH,T,D]
    mm_gemm_kernel<1><<<dim3(1536 / 128, Mz / 128), 256, MG_SMEM>>>(
        xf, w1, nullptr, nullptr, cosb, sinb, Kfp, Qfp, Vfp, Cz, 0);

    // 2) Flash attention (exp2-domain, MMA row-sums) -> af [B,T,C] fp16
    flash7_kernel<<<dim3(Tz / 128, BHz), 256, FL7_SMEM>>>(
        Qfp, Kfp, Vfp, af);

    // 3) proj GEMM + bias -> d_out
    mm_gemm_kernel<0><<<dim3(Cz / 128, Mz / 128), 256, MG_SMEM>>>(
        af, w2, out, b_proj, nullptr, nullptr,
        nullptr, nullptr, nullptr, Cz, Cz);
}